// round 1
// baseline (speedup 1.0000x reference)
#include <cuda_runtime.h>
#include <math.h>

// ---------------- problem constants ----------------
#define BATCH 32
#define SEQ   577
#define CDIM  768
#define NHEAD 12
#define DHEAD 64
#define DFF   3072
#define MROWS (BATCH*SEQ)          // 18464
#define C3    (3*CDIM)             // 2304

// ---------------- scratch (device globals; no allocation) ----------------
__device__ float g_h   [(size_t)MROWS * CDIM];
__device__ float g_qkv [(size_t)MROWS * C3];
__device__ float g_attn[(size_t)MROWS * CDIM];
__device__ float g_x1  [(size_t)MROWS * CDIM];
__device__ float g_ff  [(size_t)MROWS * DFF];

// ---------------- f32x2 helpers ----------------
__device__ __forceinline__ unsigned long long pack_dup(float a) {
    unsigned long long r;
    asm("mov.b64 %0, {%1, %1};" : "=l"(r) : "f"(a));
    return r;
}
__device__ __forceinline__ void fma2(unsigned long long &c, unsigned long long a, unsigned long long b) {
    asm("fma.rn.f32x2 %0, %1, %2, %0;" : "+l"(c) : "l"(a), "l"(b));
}
__device__ __forceinline__ float2 unpack2(unsigned long long v) {
    float2 f;
    asm("mov.b64 {%0, %1}, %2;" : "=f"(f.x), "=f"(f.y) : "l"(v));
    return f;
}

// ---------------- LayerNorm: one block per row, C=768, 256 threads ----------------
__global__ void __launch_bounds__(256) ln_kernel(
    const float* __restrict__ x, const float* __restrict__ g,
    const float* __restrict__ b, float* __restrict__ out)
{
    __shared__ float red[8];
    const int row = blockIdx.x;
    const int tid = threadIdx.x;
    const float* xr = x + (size_t)row * CDIM;

    float v0 = xr[tid], v1 = xr[tid + 256], v2 = xr[tid + 512];

    // ---- mean ----
    float s = v0 + v1 + v2;
    #pragma unroll
    for (int o = 16; o > 0; o >>= 1) s += __shfl_xor_sync(0xffffffffu, s, o);
    if ((tid & 31) == 0) red[tid >> 5] = s;
    __syncthreads();
    if (tid == 0) {
        float t = 0.f;
        #pragma unroll
        for (int w = 0; w < 8; ++w) t += red[w];
        red[0] = t;
    }
    __syncthreads();
    const float mean = red[0] * (1.0f / CDIM);
    __syncthreads();

    // ---- variance (two-pass, matches reference) ----
    float d0 = v0 - mean, d1 = v1 - mean, d2 = v2 - mean;
    float sq = d0 * d0 + d1 * d1 + d2 * d2;
    #pragma unroll
    for (int o = 16; o > 0; o >>= 1) sq += __shfl_xor_sync(0xffffffffu, sq, o);
    if ((tid & 31) == 0) red[tid >> 5] = sq;
    __syncthreads();
    if (tid == 0) {
        float t = 0.f;
        #pragma unroll
        for (int w = 0; w < 8; ++w) t += red[w];
        red[0] = t;
    }
    __syncthreads();
    const float var = red[0] * (1.0f / CDIM);
    const float rstd = rsqrtf(var + 1e-5f);

    float* outr = out + (size_t)row * CDIM;
    outr[tid]       = d0 * rstd * g[tid]       + b[tid];
    outr[tid + 256] = d1 * rstd * g[tid + 256] + b[tid + 256];
    outr[tid + 512] = d2 * rstd * g[tid + 512] + b[tid + 512];
}

// ---------------- GEMM: out = A[M,K] @ W[K,N] + bias (+epilogue) ----------------
// EPI: 0 = bias only, 1 = bias + residual, 2 = bias + exact GELU
#define BM 128
#define BN 128
#define BKK 16

template <int EPI>
__global__ void __launch_bounds__(256) gemm_kernel(
    const float* __restrict__ A, const float* __restrict__ W,
    const float* __restrict__ bias, const float* __restrict__ res,
    float* __restrict__ out, int M, int K, int N)
{
    __shared__ float As[BKK][BM + 4];   // padded, transposed A tile
    __shared__ float Bs[BKK][BN];

    const int tid = threadIdx.x;
    const int tx = tid & 15;
    const int ty = tid >> 4;
    const int bn = blockIdx.x * BN;
    const int bm = blockIdx.y * BM;

    // A-load mapping: 128x16 tile, 2 float4 per thread
    const int ar = tid >> 2;              // 0..63
    const int ac = (tid & 3) << 2;        // 0,4,8,12
    const bool av0 = (bm + ar)      < M;
    const bool av1 = (bm + ar + 64) < M;
    // B-load mapping: 16x128 tile, 2 float4 per thread
    const int br = tid >> 5;              // 0..7
    const int bc = (tid & 31) << 2;       // 0..124

    const float4 z4 = make_float4(0.f, 0.f, 0.f, 0.f);
    unsigned long long acc[8][4];
    #pragma unroll
    for (int i = 0; i < 8; ++i)
        #pragma unroll
        for (int j = 0; j < 4; ++j) acc[i][j] = 0ull;

    float4 pa0, pa1, pb0, pb1;

    const int KT = K / BKK;

    // prologue: load tile 0
    {
        const float* Ab = A + (size_t)(bm + ar) * K + ac;
        pa0 = av0 ? *(const float4*)Ab : z4;
        pa1 = av1 ? *(const float4*)(Ab + (size_t)64 * K) : z4;
        const float* Bb = W + (size_t)br * N + bn + bc;
        pb0 = *(const float4*)Bb;
        pb1 = *(const float4*)(Bb + (size_t)8 * N);
    }
    // store to smem
    As[ac + 0][ar] = pa0.x; As[ac + 1][ar] = pa0.y; As[ac + 2][ar] = pa0.z; As[ac + 3][ar] = pa0.w;
    As[ac + 0][ar + 64] = pa1.x; As[ac + 1][ar + 64] = pa1.y; As[ac + 2][ar + 64] = pa1.z; As[ac + 3][ar + 64] = pa1.w;
    *(float4*)&Bs[br][bc] = pb0;
    *(float4*)&Bs[br + 8][bc] = pb1;
    __syncthreads();

    for (int t = 0; t < KT; ++t) {
        const bool more = (t + 1 < KT);
        if (more) {
            const float* Ab = A + (size_t)(bm + ar) * K + (t + 1) * BKK + ac;
            pa0 = av0 ? *(const float4*)Ab : z4;
            pa1 = av1 ? *(const float4*)(Ab + (size_t)64 * K) : z4;
            const float* Bb = W + (size_t)((t + 1) * BKK + br) * N + bn + bc;
            pb0 = *(const float4*)Bb;
            pb1 = *(const float4*)(Bb + (size_t)8 * N);
        }
        // compute 16 k-steps
        #pragma unroll
        for (int k = 0; k < BKK; ++k) {
            float4 a0 = *(const float4*)&As[k][ty * 8];
            float4 a1 = *(const float4*)&As[k][ty * 8 + 4];
            ulonglong2 bb0 = *(const ulonglong2*)&Bs[k][tx * 8];
            ulonglong2 bb1 = *(const ulonglong2*)&Bs[k][tx * 8 + 4];
            float af[8] = {a0.x, a0.y, a0.z, a0.w, a1.x, a1.y, a1.z, a1.w};
            #pragma unroll
            for (int i = 0; i < 8; ++i) {
                unsigned long long ad = pack_dup(af[i]);
                fma2(acc[i][0], ad, bb0.x);
                fma2(acc[i][1], ad, bb0.y);
                fma2(acc[i][2], ad, bb1.x);
                fma2(acc[i][3], ad, bb1.y);
            }
        }
        if (more) {
            __syncthreads();
            As[ac + 0][ar] = pa0.x; As[ac + 1][ar] = pa0.y; As[ac + 2][ar] = pa0.z; As[ac + 3][ar] = pa0.w;
            As[ac + 0][ar + 64] = pa1.x; As[ac + 1][ar + 64] = pa1.y; As[ac + 2][ar + 64] = pa1.z; As[ac + 3][ar + 64] = pa1.w;
            *(float4*)&Bs[br][bc] = pb0;
            *(float4*)&Bs[br + 8][bc] = pb1;
            __syncthreads();
        }
    }

    // ---- epilogue ----
    const int col0 = bn + tx * 8;
    const float4 bia0 = *(const float4*)&bias[col0];
    const float4 bia1 = *(const float4*)&bias[col0 + 4];
    const float bf[8] = {bia0.x, bia0.y, bia0.z, bia0.w, bia1.x, bia1.y, bia1.z, bia1.w};

    #pragma unroll
    for (int i = 0; i < 8; ++i) {
        const int row = bm + ty * 8 + i;
        if (row >= M) continue;
        float v[8];
        float2 p;
        p = unpack2(acc[i][0]); v[0] = p.x; v[1] = p.y;
        p = unpack2(acc[i][1]); v[2] = p.x; v[3] = p.y;
        p = unpack2(acc[i][2]); v[4] = p.x; v[5] = p.y;
        p = unpack2(acc[i][3]); v[6] = p.x; v[7] = p.y;
        #pragma unroll
        for (int j = 0; j < 8; ++j) v[j] += bf[j];

        if (EPI == 1) {
            const float* rp = res + (size_t)row * N + col0;
            float4 r0 = *(const float4*)rp;
            float4 r1 = *(const float4*)(rp + 4);
            v[0] += r0.x; v[1] += r0.y; v[2] += r0.z; v[3] += r0.w;
            v[4] += r1.x; v[5] += r1.y; v[6] += r1.z; v[7] += r1.w;
        } else if (EPI == 2) {
            #pragma unroll
            for (int j = 0; j < 8; ++j)
                v[j] = 0.5f * v[j] * (1.0f + erff(v[j] * 0.70710678118654752f));
        }
        float* op = out + (size_t)row * N + col0;
        *(float4*)op       = make_float4(v[0], v[1], v[2], v[3]);
        *(float4*)(op + 4) = make_float4(v[4], v[5], v[6], v[7]);
    }
}

// ---------------- attention: flash-style, 64q x 64k tiles, DH=64 ----------------
__device__ __forceinline__ float rmax16(float v) {
    #pragma unroll
    for (int o = 8; o > 0; o >>= 1) v = fmaxf(v, __shfl_xor_sync(0xffffffffu, v, o));
    return v;
}
__device__ __forceinline__ float rsum16(float v) {
    #pragma unroll
    for (int o = 8; o > 0; o >>= 1) v += __shfl_xor_sync(0xffffffffu, v, o);
    return v;
}

__global__ void __launch_bounds__(256) attn_kernel(
    const float* __restrict__ qkv, float* __restrict__ out)
{
    __shared__ float Qs [64][64];
    __shared__ float KPs[64][64];   // K^T during S; P during PV
    __shared__ float Vs [64][64];

    const int qt = blockIdx.x;      // 0..9
    const int h  = blockIdx.y;      // 0..11
    const int b  = blockIdx.z;      // 0..31
    const int tid = threadIdx.x;
    const int tx = tid & 15;
    const int ty = tid >> 4;
    const int r0 = ty * 4;
    const int c0 = tx * 4;

    const float4 z4 = make_float4(0.f, 0.f, 0.f, 0.f);
    const size_t browbase = (size_t)b * SEQ;

    // load Q tile (row-major [q][d])
    #pragma unroll
    for (int u = 0; u < 4; ++u) {
        int f = u * 256 + tid;
        int row = f >> 4;
        int dd  = (f & 15) << 2;
        int n = qt * 64 + row;
        float4 qv = (n < SEQ)
            ? *(const float4*)&qkv[(browbase + n) * C3 + h * DHEAD + dd] : z4;
        *(float4*)&Qs[row][dd] = qv;
    }

    float oacc[4][4];
    #pragma unroll
    for (int i = 0; i < 4; ++i)
        #pragma unroll
        for (int j = 0; j < 4; ++j) oacc[i][j] = 0.f;
    float mrow[4] = {-INFINITY, -INFINITY, -INFINITY, -INFINITY};
    float lrow[4] = {0.f, 0.f, 0.f, 0.f};

    const int NT = (SEQ + 63) / 64;  // 10
    for (int kt = 0; kt < NT; ++kt) {
        __syncthreads();   // previous iteration done with KPs/Vs (and Qs load visible on kt==0)

        // load K (transposed into KPs[d][k]) and V (row-major Vs[k][d])
        #pragma unroll
        for (int u = 0; u < 4; ++u) {
            int f = u * 256 + tid;
            int row = f >> 4;
            int dd  = (f & 15) << 2;
            int kk = kt * 64 + row;
            float4 kv = z4, vv = z4;
            if (kk < SEQ) {
                const float* base = &qkv[(browbase + kk) * C3 + h * DHEAD + dd];
                kv = *(const float4*)(base + CDIM);
                vv = *(const float4*)(base + 2 * CDIM);
            }
            KPs[dd + 0][row] = kv.x;
            KPs[dd + 1][row] = kv.y;
            KPs[dd + 2][row] = kv.z;
            KPs[dd + 3][row] = kv.w;
            *(float4*)&Vs[row][dd] = vv;
        }
        __syncthreads();

        // S = Q @ K^T
        float s[4][4];
        #pragma unroll
        for (int i = 0; i < 4; ++i)
            #pragma unroll
            for (int j = 0; j < 4; ++j) s[i][j] = 0.f;

        #pragma unroll
        for (int d4 = 0; d4 < 16; ++d4) {
            float4 q4[4];
            #pragma unroll
            for (int i = 0; i < 4; ++i) q4[i] = *(const float4*)&Qs[r0 + i][d4 * 4];
            #pragma unroll
            for (int u = 0; u < 4; ++u) {
                float4 kv = *(const float4*)&KPs[d4 * 4 + u][c0];
                #pragma unroll
                for (int i = 0; i < 4; ++i) {
                    float qv = ((const float*)&q4[i])[u];
                    s[i][0] = fmaf(qv, kv.x, s[i][0]);
                    s[i][1] = fmaf(qv, kv.y, s[i][1]);
                    s[i][2] = fmaf(qv, kv.z, s[i][2]);
                    s[i][3] = fmaf(qv, kv.w, s[i][3]);
                }
            }
        }

        // scale + key mask
        const int kbase = kt * 64;
        #pragma unroll
        for (int i = 0; i < 4; ++i)
            #pragma unroll
            for (int j = 0; j < 4; ++j)
                s[i][j] = (kbase + c0 + j < SEQ) ? s[i][j] * 0.125f : -INFINITY;

        __syncthreads();  // done reading K^T from KPs; about to write P there

        // online softmax + write P
        #pragma unroll
        for (int i = 0; i < 4; ++i) {
            float mt = fmaxf(fmaxf(s[i][0], s[i][1]), fmaxf(s[i][2], s[i][3]));
            mt = rmax16(mt);
            float mnew = fmaxf(mrow[i], mt);
            float corr = expf(mrow[i] - mnew);
            float psum = 0.f;
            #pragma unroll
            for (int j = 0; j < 4; ++j) {
                float p = expf(s[i][j] - mnew);
                s[i][j] = p;
                psum += p;
            }
            psum = rsum16(psum);
            lrow[i] = lrow[i] * corr + psum;
            mrow[i] = mnew;
            #pragma unroll
            for (int j = 0; j < 4; ++j) oacc[i][j] *= corr;
            *(float4*)&KPs[r0 + i][c0] = make_float4(s[i][0], s[i][1], s[i][2], s[i][3]);
        }
        __syncthreads();

        // O += P @ V
        #pragma unroll
        for (int k4 = 0; k4 < 16; ++k4) {
            float4 p4[4];
            #pragma unroll
            for (int i = 0; i < 4; ++i) p4[i] = *(const float4*)&KPs[r0 + i][k4 * 4];
            #pragma unroll
            for (int u = 0; u < 4; ++u) {
                float4 vv = *(const float4*)&Vs[k4 * 4 + u][c0];
                #pragma unroll
                for (int i = 0; i < 4; ++i) {
                    float pv = ((const float*)&p4[i])[u];
                    oacc[i][0] = fmaf(pv, vv.x, oacc[i][0]);
                    oacc[i][1] = fmaf(pv, vv.y, oacc[i][1]);
                    oacc[i][2] = fmaf(pv, vv.z, oacc[i][2]);
                    oacc[i][3] = fmaf(pv, vv.w, oacc[i][3]);
                }
            }
        }
    }

    // write O (transposed directly into [B,N,C] layout)
    #pragma unroll
    for (int i = 0; i < 4; ++i) {
        int n = qt * 64 + r0 + i;
        if (n < SEQ) {
            float inv = 1.0f / lrow[i];
            *(float4*)&out[(browbase + n) * CDIM + h * DHEAD + c0] =
                make_float4(oacc[i][0] * inv, oacc[i][1] * inv,
                            oacc[i][2] * inv, oacc[i][3] * inv);
        }
    }
}

// ---------------- launcher ----------------
extern "C" void kernel_launch(void* const* d_in, const int* in_sizes, int n_in,
                              void* d_out, int out_size)
{
    const float* x      = (const float*)d_in[0];
    const float* ln1_g  = (const float*)d_in[1];
    const float* ln1_b  = (const float*)d_in[2];
    const float* ln2_g  = (const float*)d_in[3];
    const float* ln2_b  = (const float*)d_in[4];
    const float* qkv_w  = (const float*)d_in[5];
    const float* qkv_b  = (const float*)d_in[6];
    const float* proj_w = (const float*)d_in[7];
    const float* proj_b = (const float*)d_in[8];
    const float* fc1_w  = (const float*)d_in[9];
    const float* fc1_b  = (const float*)d_in[10];
    const float* fc2_w  = (const float*)d_in[11];
    const float* fc2_b  = (const float*)d_in[12];
    float* out = (float*)d_out;

    float *h, *qkv, *attn, *x1, *ff;
    cudaGetSymbolAddress((void**)&h,    g_h);
    cudaGetSymbolAddress((void**)&qkv,  g_qkv);
    cudaGetSymbolAddress((void**)&attn, g_attn);
    cudaGetSymbolAddress((void**)&x1,   g_x1);
    cudaGetSymbolAddress((void**)&ff,   g_ff);

    const int M = MROWS;                      // 18464
    const int gy = (M + BM - 1) / BM;         // 145

    // 1. LN1
    ln_kernel<<<M, 256>>>(x, ln1_g, ln1_b, h);
    // 2. QKV = h @ qkv_w + qkv_b
    gemm_kernel<0><<<dim3(C3 / BN, gy), 256>>>(h, qkv_w, qkv_b, nullptr, qkv, M, CDIM, C3);
    // 3. attention
    attn_kernel<<<dim3((SEQ + 63) / 64, NHEAD, BATCH), 256>>>(qkv, attn);
    // 4. x1 = x + attn @ proj_w + proj_b
    gemm_kernel<1><<<dim3(CDIM / BN, gy), 256>>>(attn, proj_w, proj_b, x, x1, M, CDIM, CDIM);
    // 5. LN2
    ln_kernel<<<M, 256>>>(x1, ln2_g, ln2_b, h);
    // 6. ff = gelu(h @ fc1_w + fc1_b)
    gemm_kernel<2><<<dim3(DFF / BN, gy), 256>>>(h, fc1_w, fc1_b, nullptr, ff, M, CDIM, DFF);
    // 7. out = x1 + ff @ fc2_w + fc2_b
    gemm_kernel<1><<<dim3(CDIM / BN, gy), 256>>>(ff, fc2_w, fc2_b, x1, out, M, DFF, CDIM);
}

// round 4
// speedup vs baseline: 2.1840x; 2.1840x over previous
#include <cuda_runtime.h>
#include <cstdint>
#include <math.h>

// ---------------- problem constants ----------------
#define BATCH 32
#define SEQ   577
#define CDIM  768
#define NHEAD 12
#define DHEAD 64
#define DFF   3072
#define MROWS (BATCH*SEQ)          // 18464
#define C3    (3*CDIM)             // 2304

// ---------------- scratch (device globals; no allocation) ----------------
__device__ __align__(256) float g_h   [(size_t)MROWS * CDIM];
__device__ __align__(256) float g_qkv [(size_t)MROWS * C3];
__device__ __align__(256) float g_attn[(size_t)MROWS * CDIM];
__device__ __align__(256) float g_x1  [(size_t)MROWS * CDIM];
__device__ __align__(256) float g_ff  [(size_t)MROWS * DFF];
__device__ __align__(256) float g_wt_qkv [(size_t)C3   * CDIM];
__device__ __align__(256) float g_wt_proj[(size_t)CDIM * CDIM];
__device__ __align__(256) float g_wt_fc1 [(size_t)DFF  * CDIM];
__device__ __align__(256) float g_wt_fc2 [(size_t)CDIM * DFF];

// ---------------- helpers ----------------
static __device__ __forceinline__ uint32_t smem_u32(const void* p) {
    uint32_t a;
    asm("{ .reg .u64 t; cvta.to.shared.u64 t, %1; cvt.u32.u64 %0, t; }" : "=r"(a) : "l"(p));
    return a;
}
static __device__ __forceinline__ float to_tf32(float v) {
    uint32_t r;
    asm("cvt.rna.tf32.f32 %0, %1;" : "=r"(r) : "f"(v));
    return __uint_as_float(r);
}
static __device__ __forceinline__ void cp_async16(uint32_t dst, const void* src) {
    asm volatile("cp.async.cg.shared.global [%0], [%1], 16;" :: "r"(dst), "l"(src));
}
static __device__ __forceinline__ void cp_async16z(uint32_t dst, const void* src, int sz) {
    asm volatile("cp.async.cg.shared.global [%0], [%1], 16, %2;" :: "r"(dst), "l"(src), "r"(sz));
}
static __device__ __forceinline__ void mma_tf32(
    float* d, uint32_t a0, uint32_t a1, uint32_t a2, uint32_t a3,
    uint32_t b0, uint32_t b1)
{
    asm volatile(
        "mma.sync.aligned.m16n8k8.row.col.f32.tf32.tf32.f32 "
        "{%0,%1,%2,%3}, {%4,%5,%6,%7}, {%8,%9}, {%0,%1,%2,%3};"
        : "+f"(d[0]), "+f"(d[1]), "+f"(d[2]), "+f"(d[3])
        : "r"(a0), "r"(a1), "r"(a2), "r"(a3), "r"(b0), "r"(b1));
}

// ---------------- LayerNorm (outputs tf32-rounded — feeds GEMM A) ----------------
__global__ void __launch_bounds__(256) ln_kernel(
    const float* __restrict__ x, const float* __restrict__ g,
    const float* __restrict__ b, float* __restrict__ out)
{
    __shared__ float red[8];
    const int row = blockIdx.x;
    const int tid = threadIdx.x;
    const float* xr = x + (size_t)row * CDIM;

    float v0 = xr[tid], v1 = xr[tid + 256], v2 = xr[tid + 512];

    float s = v0 + v1 + v2;
    #pragma unroll
    for (int o = 16; o > 0; o >>= 1) s += __shfl_xor_sync(0xffffffffu, s, o);
    if ((tid & 31) == 0) red[tid >> 5] = s;
    __syncthreads();
    if (tid == 0) {
        float t = 0.f;
        #pragma unroll
        for (int w = 0; w < 8; ++w) t += red[w];
        red[0] = t;
    }
    __syncthreads();
    const float mean = red[0] * (1.0f / CDIM);
    __syncthreads();

    float d0 = v0 - mean, d1 = v1 - mean, d2 = v2 - mean;
    float sq = d0 * d0 + d1 * d1 + d2 * d2;
    #pragma unroll
    for (int o = 16; o > 0; o >>= 1) sq += __shfl_xor_sync(0xffffffffu, sq, o);
    if ((tid & 31) == 0) red[tid >> 5] = sq;
    __syncthreads();
    if (tid == 0) {
        float t = 0.f;
        #pragma unroll
        for (int w = 0; w < 8; ++w) t += red[w];
        red[0] = t;
    }
    __syncthreads();
    const float var = red[0] * (1.0f / CDIM);
    const float rstd = rsqrtf(var + 1e-5f);

    float* outr = out + (size_t)row * CDIM;
    outr[tid]       = to_tf32(d0 * rstd * g[tid]       + b[tid]);
    outr[tid + 256] = to_tf32(d1 * rstd * g[tid + 256] + b[tid + 256]);
    outr[tid + 512] = to_tf32(d2 * rstd * g[tid + 512] + b[tid + 512]);
}

// ---------------- weight transpose (W[K,N] -> Wt[N,K], tf32-rounded) ----------------
__global__ void __launch_bounds__(256) transpose_w(
    const float* __restrict__ W, float* __restrict__ Wt, int K, int N)
{
    __shared__ float t[32][33];
    const int k0 = blockIdx.x * 32, n0 = blockIdx.y * 32;
    #pragma unroll
    for (int i = threadIdx.y; i < 32; i += 8)
        t[i][threadIdx.x] = W[(size_t)(k0 + i) * N + n0 + threadIdx.x];
    __syncthreads();
    #pragma unroll
    for (int i = threadIdx.y; i < 32; i += 8)
        Wt[(size_t)(n0 + i) * K + k0 + threadIdx.x] = to_tf32(t[threadIdx.x][i]);
}

// ---------------- HMMA-tf32 GEMM: out = A[M,K] @ Wt[N,K]^T + bias (+epilogue) ------
// EPI: 0 = bias, 1 = bias + residual, 2 = bias + exact GELU (tf32-rounded)
#define NSTAGE 3
#define GBM 128
#define GBN 256
#define PITCH 36                          // floats per smem row (32 + 4 pad)
#define A_STG (128 * PITCH)               // floats
#define B_STG (256 * PITCH)
#define STG   (A_STG + B_STG)             // 13824 floats = 55296 B per stage
#define SMEM_DYN (NSTAGE * STG * 4)

__device__ __forceinline__ void load_stage(
    uint32_t sb, const float* __restrict__ A, const float* __restrict__ Wt,
    int bm, int bn, int M, int K, int kc, int tid)
{
    // A tile: 128 rows x 32 floats, one float4 per (row, quad)
    #pragma unroll
    for (int i = 0; i < 4; ++i) {
        int f = i * 256 + tid;
        int r = f >> 3, q = f & 7;
        int rr = bm + r;
        int sz = (rr < M) ? 16 : 0;
        if (rr >= M) rr = M - 1;
        cp_async16z(sb + (uint32_t)((r * PITCH + q * 4) * 4),
                    A + (size_t)rr * K + kc + q * 4, sz);
    }
    // B tile: 256 rows x 32 floats
    const uint32_t bb = sb + A_STG * 4;
    #pragma unroll
    for (int i = 0; i < 8; ++i) {
        int f = i * 256 + tid;
        int r = f >> 3, q = f & 7;
        cp_async16(bb + (uint32_t)((r * PITCH + q * 4) * 4),
                   Wt + (size_t)(bn + r) * K + kc + q * 4);
    }
    asm volatile("cp.async.commit_group;" ::: "memory");
}

template <int EPI>
__global__ void __launch_bounds__(256, 1) gemm_mma(
    const float* __restrict__ A, const float* __restrict__ Wt,
    const float* __restrict__ bias, const float* __restrict__ res,
    float* __restrict__ out, int M, int K, int N)
{
    extern __shared__ float dsm[];
    const uint32_t sbase = smem_u32(dsm);

    const int tid  = threadIdx.x;
    const int wid  = tid >> 5;
    const int lane = tid & 31;
    const int g = lane >> 2, t = lane & 3;
    const int bm = blockIdx.y * GBM;
    const int bn = blockIdx.x * GBN;
    const int wm = (wid >> 2) * 64;       // warp tile 64x64
    const int wn = (wid & 3) * 64;

    float acc[4][8][4];
    #pragma unroll
    for (int mt = 0; mt < 4; ++mt)
        #pragma unroll
        for (int nt = 0; nt < 8; ++nt)
            #pragma unroll
            for (int j = 0; j < 4; ++j) acc[mt][nt][j] = 0.f;

    const int KT = K >> 5;   // 32-wide K chunks

    for (int c = 0; c < NSTAGE - 1; ++c)
        load_stage(sbase + (uint32_t)(c * STG * 4), A, Wt, bm, bn, M, K, c * 32, tid);

    for (int kt = 0; kt < KT; ++kt) {
        asm volatile("cp.async.wait_group %0;" :: "n"(NSTAGE - 2) : "memory");
        __syncthreads();

        const int kn = kt + NSTAGE - 1;
        if (kn < KT)
            load_stage(sbase + (uint32_t)((kn % NSTAGE) * STG * 4), A, Wt, bm, bn, M, K, kn * 32, tid);
        else
            asm volatile("cp.async.commit_group;" ::: "memory");

        const float* sA = dsm + (kt % NSTAGE) * STG;
        const float* sB = sA + A_STG;

        #pragma unroll
        for (int k8 = 0; k8 < 4; ++k8) {
            uint32_t bf[8][2];
            #pragma unroll
            for (int nt = 0; nt < 8; ++nt) {
                const float* bp = sB + (wn + nt * 8 + g) * PITCH + k8 * 8 + t;
                bf[nt][0] = __float_as_uint(bp[0]);
                bf[nt][1] = __float_as_uint(bp[4]);
            }
            #pragma unroll
            for (int mt = 0; mt < 4; ++mt) {
                const float* ap = sA + (wm + mt * 16 + g) * PITCH + k8 * 8 + t;
                uint32_t a0 = __float_as_uint(ap[0]);
                uint32_t a1 = __float_as_uint(ap[8 * PITCH]);
                uint32_t a2 = __float_as_uint(ap[4]);
                uint32_t a3 = __float_as_uint(ap[8 * PITCH + 4]);
                #pragma unroll
                for (int nt = 0; nt < 8; ++nt)
                    mma_tf32(acc[mt][nt], a0, a1, a2, a3, bf[nt][0], bf[nt][1]);
            }
        }
    }

    // ---- epilogue ----
    #pragma unroll
    for (int nt = 0; nt < 8; ++nt) {
        const int c = bn + wn + nt * 8 + 2 * t;
        const float2 bia = *(const float2*)&bias[c];
        #pragma unroll
        for (int mt = 0; mt < 4; ++mt) {
            const int r0 = bm + wm + mt * 16 + g;
            float v0 = acc[mt][nt][0] + bia.x;
            float v1 = acc[mt][nt][1] + bia.y;
            float v2 = acc[mt][nt][2] + bia.x;
            float v3 = acc[mt][nt][3] + bia.y;
            if (EPI == 2) {
                v0 = to_tf32(0.5f * v0 * (1.0f + erff(v0 * 0.70710678118654752f)));
                v1 = to_tf32(0.5f * v1 * (1.0f + erff(v1 * 0.70710678118654752f)));
                v2 = to_tf32(0.5f * v2 * (1.0f + erff(v2 * 0.70710678118654752f)));
                v3 = to_tf32(0.5f * v3 * (1.0f + erff(v3 * 0.70710678118654752f)));
            }
            if (r0 < M) {
                if (EPI == 1) {
                    float2 rv = *(const float2*)&res[(size_t)r0 * N + c];
                    v0 += rv.x; v1 += rv.y;
                }
                *(float2*)&out[(size_t)r0 * N + c] = make_float2(v0, v1);
            }
            if (r0 + 8 < M) {
                if (EPI == 1) {
                    float2 rv = *(const float2*)&res[(size_t)(r0 + 8) * N + c];
                    v2 += rv.x; v3 += rv.y;
                }
                *(float2*)&out[(size_t)(r0 + 8) * N + c] = make_float2(v2, v3);
            }
        }
    }
}

// ---------------- attention: flash-style, 64q x 64k tiles, DH=64 (SIMT fp32) -------
__device__ __forceinline__ float rmax16(float v) {
    #pragma unroll
    for (int o = 8; o > 0; o >>= 1) v = fmaxf(v, __shfl_xor_sync(0xffffffffu, v, o));
    return v;
}
__device__ __forceinline__ float rsum16(float v) {
    #pragma unroll
    for (int o = 8; o > 0; o >>= 1) v += __shfl_xor_sync(0xffffffffu, v, o);
    return v;
}

__global__ void __launch_bounds__(256) attn_kernel(
    const float* __restrict__ qkv, float* __restrict__ out)
{
    __shared__ float Qs [64][64];
    __shared__ float KPs[64][64];   // K^T during S; P during PV
    __shared__ float Vs [64][64];

    const int qt = blockIdx.x;
    const int h  = blockIdx.y;
    const int b  = blockIdx.z;
    const int tid = threadIdx.x;
    const int tx = tid & 15;
    const int ty = tid >> 4;
    const int r0 = ty * 4;
    const int c0 = tx * 4;

    const float4 z4 = make_float4(0.f, 0.f, 0.f, 0.f);
    const size_t browbase = (size_t)b * SEQ;

    #pragma unroll
    for (int u = 0; u < 4; ++u) {
        int f = u * 256 + tid;
        int row = f >> 4;
        int dd  = (f & 15) << 2;
        int n = qt * 64 + row;
        float4 qv = (n < SEQ)
            ? *(const float4*)&qkv[(browbase + n) * C3 + h * DHEAD + dd] : z4;
        *(float4*)&Qs[row][dd] = qv;
    }

    float oacc[4][4];
    #pragma unroll
    for (int i = 0; i < 4; ++i)
        #pragma unroll
        for (int j = 0; j < 4; ++j) oacc[i][j] = 0.f;
    float mrow[4] = {-INFINITY, -INFINITY, -INFINITY, -INFINITY};
    float lrow[4] = {0.f, 0.f, 0.f, 0.f};

    const int NT = (SEQ + 63) / 64;
    for (int kt = 0; kt < NT; ++kt) {
        __syncthreads();

        #pragma unroll
        for (int u = 0; u < 4; ++u) {
            int f = u * 256 + tid;
            int row = f >> 4;
            int dd  = (f & 15) << 2;
            int kk = kt * 64 + row;
            float4 kv = z4, vv = z4;
            if (kk < SEQ) {
                const float* base = &qkv[(browbase + kk) * C3 + h * DHEAD + dd];
                kv = *(const float4*)(base + CDIM);
                vv = *(const float4*)(base + 2 * CDIM);
            }
            KPs[dd + 0][row] = kv.x;
            KPs[dd + 1][row] = kv.y;
            KPs[dd + 2][row] = kv.z;
            KPs[dd + 3][row] = kv.w;
            *(float4*)&Vs[row][dd] = vv;
        }
        __syncthreads();

        float s[4][4];
        #pragma unroll
        for (int i = 0; i < 4; ++i)
            #pragma unroll
            for (int j = 0; j < 4; ++j) s[i][j] = 0.f;

        #pragma unroll
        for (int d4 = 0; d4 < 16; ++d4) {
            float4 q4[4];
            #pragma unroll
            for (int i = 0; i < 4; ++i) q4[i] = *(const float4*)&Qs[r0 + i][d4 * 4];
            #pragma unroll
            for (int u = 0; u < 4; ++u) {
                float4 kv = *(const float4*)&KPs[d4 * 4 + u][c0];
                #pragma unroll
                for (int i = 0; i < 4; ++i) {
                    float qv = ((const float*)&q4[i])[u];
                    s[i][0] = fmaf(qv, kv.x, s[i][0]);
                    s[i][1] = fmaf(qv, kv.y, s[i][1]);
                    s[i][2] = fmaf(qv, kv.z, s[i][2]);
                    s[i][3] = fmaf(qv, kv.w, s[i][3]);
                }
            }
        }

        const int kbase = kt * 64;
        #pragma unroll
        for (int i = 0; i < 4; ++i)
            #pragma unroll
            for (int j = 0; j < 4; ++j)
                s[i][j] = (kbase + c0 + j < SEQ) ? s[i][j] * 0.125f : -INFINITY;

        __syncthreads();

        #pragma unroll
        for (int i = 0; i < 4; ++i) {
            float mt = fmaxf(fmaxf(s[i][0], s[i][1]), fmaxf(s[i][2], s[i][3]));
            mt = rmax16(mt);
            float mnew = fmaxf(mrow[i], mt);
            float corr = expf(mrow[i] - mnew);
            float psum = 0.f;
            #pragma unroll
            for (int j = 0; j < 4; ++j) {
                float p = expf(s[i][j] - mnew);
                s[i][j] = p;
                psum += p;
            }
            psum = rsum16(psum);
            lrow[i] = lrow[i] * corr + psum;
            mrow[i] = mnew;
            #pragma unroll
            for (int j = 0; j < 4; ++j) oacc[i][j] *= corr;
            *(float4*)&KPs[r0 + i][c0] = make_float4(s[i][0], s[i][1], s[i][2], s[i][3]);
        }
        __syncthreads();

        #pragma unroll
        for (int k4 = 0; k4 < 16; ++k4) {
            float4 p4[4];
            #pragma unroll
            for (int i = 0; i < 4; ++i) p4[i] = *(const float4*)&KPs[r0 + i][k4 * 4];
            #pragma unroll
            for (int u = 0; u < 4; ++u) {
                float4 vv = *(const float4*)&Vs[k4 * 4 + u][c0];
                #pragma unroll
                for (int i = 0; i < 4; ++i) {
                    float pv = ((const float*)&p4[i])[u];
                    oacc[i][0] = fmaf(pv, vv.x, oacc[i][0]);
                    oacc[i][1] = fmaf(pv, vv.y, oacc[i][1]);
                    oacc[i][2] = fmaf(pv, vv.z, oacc[i][2]);
                    oacc[i][3] = fmaf(pv, vv.w, oacc[i][3]);
                }
            }
        }
    }

    #pragma unroll
    for (int i = 0; i < 4; ++i) {
        int n = qt * 64 + r0 + i;
        if (n < SEQ) {
            float inv = 1.0f / lrow[i];
            *(float4*)&out[(browbase + n) * CDIM + h * DHEAD + c0] =
                make_float4(to_tf32(oacc[i][0] * inv), to_tf32(oacc[i][1] * inv),
                            to_tf32(oacc[i][2] * inv), to_tf32(oacc[i][3] * inv));
        }
    }
}

// ---------------- launcher ----------------
extern "C" void kernel_launch(void* const* d_in, const int* in_sizes, int n_in,
                              void* d_out, int out_size)
{
    const float* x      = (const float*)d_in[0];
    const float* ln1_g  = (const float*)d_in[1];
    const float* ln1_b  = (const float*)d_in[2];
    const float* ln2_g  = (const float*)d_in[3];
    const float* ln2_b  = (const float*)d_in[4];
    const float* qkv_w  = (const float*)d_in[5];
    const float* qkv_b  = (const float*)d_in[6];
    const float* proj_w = (const float*)d_in[7];
    const float* proj_b = (const float*)d_in[8];
    const float* fc1_w  = (const float*)d_in[9];
    const float* fc1_b  = (const float*)d_in[10];
    const float* fc2_w  = (const float*)d_in[11];
    const float* fc2_b  = (const float*)d_in[12];
    float* out = (float*)d_out;

    float *h, *qkv, *attn, *x1, *ff, *wtq, *wtp, *wt1, *wt2;
    cudaGetSymbolAddress((void**)&h,    g_h);
    cudaGetSymbolAddress((void**)&qkv,  g_qkv);
    cudaGetSymbolAddress((void**)&attn, g_attn);
    cudaGetSymbolAddress((void**)&x1,   g_x1);
    cudaGetSymbolAddress((void**)&ff,   g_ff);
    cudaGetSymbolAddress((void**)&wtq,  g_wt_qkv);
    cudaGetSymbolAddress((void**)&wtp,  g_wt_proj);
    cudaGetSymbolAddress((void**)&wt1,  g_wt_fc1);
    cudaGetSymbolAddress((void**)&wt2,  g_wt_fc2);

    cudaFuncSetAttribute(gemm_mma<0>, cudaFuncAttributeMaxDynamicSharedMemorySize, SMEM_DYN);
    cudaFuncSetAttribute(gemm_mma<1>, cudaFuncAttributeMaxDynamicSharedMemorySize, SMEM_DYN);
    cudaFuncSetAttribute(gemm_mma<2>, cudaFuncAttributeMaxDynamicSharedMemorySize, SMEM_DYN);

    const int M  = MROWS;
    const int gy = (M + GBM - 1) / GBM;     // 145
    dim3 tb(32, 8);

    transpose_w<<<dim3(CDIM / 32, C3 / 32),   tb>>>(qkv_w,  wtq, CDIM, C3);
    transpose_w<<<dim3(CDIM / 32, CDIM / 32), tb>>>(proj_w, wtp, CDIM, CDIM);
    transpose_w<<<dim3(CDIM / 32, DFF / 32),  tb>>>(fc1_w,  wt1, CDIM, DFF);
    transpose_w<<<dim3(DFF / 32, CDIM / 32),  tb>>>(fc2_w,  wt2, DFF, CDIM);

    // 1. LN1
    ln_kernel<<<M, 256>>>(x, ln1_g, ln1_b, h);
    // 2. QKV = h @ qkv_w + qkv_b
    gemm_mma<0><<<dim3(C3 / GBN, gy), 256, SMEM_DYN>>>(h, wtq, qkv_b, nullptr, qkv, M, CDIM, C3);
    // 3. attention
    attn_kernel<<<dim3((SEQ + 63) / 64, NHEAD, BATCH), 256>>>(qkv, attn);
    // 4. x1 = x + attn @ proj_w + proj_b
    gemm_mma<1><<<dim3(CDIM / GBN, gy), 256, SMEM_DYN>>>(attn, wtp, proj_b, x, x1, M, CDIM, CDIM);
    // 5. LN2
    ln_kernel<<<M, 256>>>(x1, ln2_g, ln2_b, h);
    // 6. ff = gelu(h @ fc1_w + fc1_b)
    gemm_mma<2><<<dim3(DFF / GBN, gy), 256, SMEM_DYN>>>(h, wt1, fc1_b, nullptr, ff, M, CDIM, DFF);
    // 7. out = x1 + ff @ fc2_w + fc2_b
    gemm_mma<1><<<dim3(CDIM / GBN, gy), 256, SMEM_DYN>>>(ff, wt2, fc2_b, x1, out, M, DFF, CDIM);
}

// round 5
// speedup vs baseline: 3.0756x; 1.4082x over previous
#include <cuda_runtime.h>
#include <cstdint>
#include <math.h>

// ---------------- problem constants ----------------
#define BATCH 32
#define SEQ   577
#define CDIM  768
#define NHEAD 12
#define DHEAD 64
#define DFF   3072
#define MROWS (BATCH*SEQ)          // 18464
#define C3    (3*CDIM)             // 2304

// ---------------- scratch (device globals; no allocation) ----------------
__device__ __align__(256) float g_h   [(size_t)MROWS * CDIM];
__device__ __align__(256) float g_qkv [(size_t)MROWS * C3];
__device__ __align__(256) float g_attn[(size_t)MROWS * CDIM];
__device__ __align__(256) float g_x1  [(size_t)MROWS * CDIM];
__device__ __align__(256) float g_ff  [(size_t)MROWS * DFF];
__device__ __align__(256) float g_wt_qkv [(size_t)C3   * CDIM];
__device__ __align__(256) float g_wt_proj[(size_t)CDIM * CDIM];
__device__ __align__(256) float g_wt_fc1 [(size_t)DFF  * CDIM];
__device__ __align__(256) float g_wt_fc2 [(size_t)CDIM * DFF];

// ---------------- helpers ----------------
static __device__ __forceinline__ uint32_t smem_u32(const void* p) {
    uint32_t a;
    asm("{ .reg .u64 t; cvta.to.shared.u64 t, %1; cvt.u32.u64 %0, t; }" : "=r"(a) : "l"(p));
    return a;
}
static __device__ __forceinline__ float to_tf32(float v) {
    uint32_t r;
    asm("cvt.rna.tf32.f32 %0, %1;" : "=r"(r) : "f"(v));
    return __uint_as_float(r);
}
static __device__ __forceinline__ void cp_async16(uint32_t dst, const void* src) {
    asm volatile("cp.async.cg.shared.global [%0], [%1], 16;" :: "r"(dst), "l"(src));
}
static __device__ __forceinline__ void cp_async16z(uint32_t dst, const void* src, int sz) {
    asm volatile("cp.async.cg.shared.global [%0], [%1], 16, %2;" :: "r"(dst), "l"(src), "r"(sz));
}
static __device__ __forceinline__ void mma_tf32(
    float* d, uint32_t a0, uint32_t a1, uint32_t a2, uint32_t a3,
    uint32_t b0, uint32_t b1)
{
    asm volatile(
        "mma.sync.aligned.m16n8k8.row.col.f32.tf32.tf32.f32 "
        "{%0,%1,%2,%3}, {%4,%5,%6,%7}, {%8,%9}, {%0,%1,%2,%3};"
        : "+f"(d[0]), "+f"(d[1]), "+f"(d[2]), "+f"(d[3])
        : "r"(a0), "r"(a1), "r"(a2), "r"(a3), "r"(b0), "r"(b1));
}

// ---------------- LayerNorm (outputs tf32-rounded — feeds GEMM A) ----------------
__global__ void __launch_bounds__(256) ln_kernel(
    const float* __restrict__ x, const float* __restrict__ g,
    const float* __restrict__ b, float* __restrict__ out)
{
    __shared__ float red[8];
    const int row = blockIdx.x;
    const int tid = threadIdx.x;
    const float* xr = x + (size_t)row * CDIM;

    float v0 = xr[tid], v1 = xr[tid + 256], v2 = xr[tid + 512];

    float s = v0 + v1 + v2;
    #pragma unroll
    for (int o = 16; o > 0; o >>= 1) s += __shfl_xor_sync(0xffffffffu, s, o);
    if ((tid & 31) == 0) red[tid >> 5] = s;
    __syncthreads();
    if (tid == 0) {
        float t = 0.f;
        #pragma unroll
        for (int w = 0; w < 8; ++w) t += red[w];
        red[0] = t;
    }
    __syncthreads();
    const float mean = red[0] * (1.0f / CDIM);
    __syncthreads();

    float d0 = v0 - mean, d1 = v1 - mean, d2 = v2 - mean;
    float sq = d0 * d0 + d1 * d1 + d2 * d2;
    #pragma unroll
    for (int o = 16; o > 0; o >>= 1) sq += __shfl_xor_sync(0xffffffffu, sq, o);
    if ((tid & 31) == 0) red[tid >> 5] = sq;
    __syncthreads();
    if (tid == 0) {
        float t = 0.f;
        #pragma unroll
        for (int w = 0; w < 8; ++w) t += red[w];
        red[0] = t;
    }
    __syncthreads();
    const float var = red[0] * (1.0f / CDIM);
    const float rstd = rsqrtf(var + 1e-5f);

    float* outr = out + (size_t)row * CDIM;
    outr[tid]       = to_tf32(d0 * rstd * g[tid]       + b[tid]);
    outr[tid + 256] = to_tf32(d1 * rstd * g[tid + 256] + b[tid + 256]);
    outr[tid + 512] = to_tf32(d2 * rstd * g[tid + 512] + b[tid + 512]);
}

// ---------------- weight transpose (W[K,N] -> Wt[N,K], tf32-rounded) ----------------
__global__ void __launch_bounds__(256) transpose_w(
    const float* __restrict__ W, float* __restrict__ Wt, int K, int N)
{
    __shared__ float t[32][33];
    const int k0 = blockIdx.x * 32, n0 = blockIdx.y * 32;
    #pragma unroll
    for (int i = threadIdx.y; i < 32; i += 8)
        t[i][threadIdx.x] = W[(size_t)(k0 + i) * N + n0 + threadIdx.x];
    __syncthreads();
    #pragma unroll
    for (int i = threadIdx.y; i < 32; i += 8)
        Wt[(size_t)(n0 + i) * K + k0 + threadIdx.x] = to_tf32(t[threadIdx.x][i]);
}

// ---------------- HMMA-tf32 GEMM: out = A[M,K] @ Wt[N,K]^T + bias (+epilogue) ------
// EPI: 0 = bias + tf32-round (feeds attention), 1 = bias + residual, 2 = bias + GELU
#define NSTAGE 3
#define GBM 128
#define GBN 256
#define PITCH 36
#define A_STG (128 * PITCH)
#define B_STG (256 * PITCH)
#define STG   (A_STG + B_STG)
#define SMEM_DYN (NSTAGE * STG * 4)

__device__ __forceinline__ void load_stage(
    uint32_t sb, const float* __restrict__ A, const float* __restrict__ Wt,
    int bm, int bn, int M, int K, int kc, int tid)
{
    #pragma unroll
    for (int i = 0; i < 4; ++i) {
        int f = i * 256 + tid;
        int r = f >> 3, q = f & 7;
        int rr = bm + r;
        int sz = (rr < M) ? 16 : 0;
        if (rr >= M) rr = M - 1;
        cp_async16z(sb + (uint32_t)((r * PITCH + q * 4) * 4),
                    A + (size_t)rr * K + kc + q * 4, sz);
    }
    const uint32_t bb = sb + A_STG * 4;
    #pragma unroll
    for (int i = 0; i < 8; ++i) {
        int f = i * 256 + tid;
        int r = f >> 3, q = f & 7;
        cp_async16(bb + (uint32_t)((r * PITCH + q * 4) * 4),
                   Wt + (size_t)(bn + r) * K + kc + q * 4);
    }
    asm volatile("cp.async.commit_group;" ::: "memory");
}

template <int EPI>
__global__ void __launch_bounds__(256, 1) gemm_mma(
    const float* __restrict__ A, const float* __restrict__ Wt,
    const float* __restrict__ bias, const float* __restrict__ res,
    float* __restrict__ out, int M, int K, int N)
{
    extern __shared__ float dsm[];
    const uint32_t sbase = smem_u32(dsm);

    const int tid  = threadIdx.x;
    const int wid  = tid >> 5;
    const int lane = tid & 31;
    const int g = lane >> 2, t = lane & 3;
    const int bm = blockIdx.y * GBM;
    const int bn = blockIdx.x * GBN;
    const int wm = (wid >> 2) * 64;
    const int wn = (wid & 3) * 64;

    float acc[4][8][4];
    #pragma unroll
    for (int mt = 0; mt < 4; ++mt)
        #pragma unroll
        for (int nt = 0; nt < 8; ++nt)
            #pragma unroll
            for (int j = 0; j < 4; ++j) acc[mt][nt][j] = 0.f;

    const int KT = K >> 5;

    for (int c = 0; c < NSTAGE - 1; ++c)
        load_stage(sbase + (uint32_t)(c * STG * 4), A, Wt, bm, bn, M, K, c * 32, tid);

    for (int kt = 0; kt < KT; ++kt) {
        asm volatile("cp.async.wait_group %0;" :: "n"(NSTAGE - 2) : "memory");
        __syncthreads();

        const int kn = kt + NSTAGE - 1;
        if (kn < KT)
            load_stage(sbase + (uint32_t)((kn % NSTAGE) * STG * 4), A, Wt, bm, bn, M, K, kn * 32, tid);
        else
            asm volatile("cp.async.commit_group;" ::: "memory");

        const float* sA = dsm + (kt % NSTAGE) * STG;
        const float* sB = sA + A_STG;

        #pragma unroll
        for (int k8 = 0; k8 < 4; ++k8) {
            uint32_t bf[8][2];
            #pragma unroll
            for (int nt = 0; nt < 8; ++nt) {
                const float* bp = sB + (wn + nt * 8 + g) * PITCH + k8 * 8 + t;
                bf[nt][0] = __float_as_uint(bp[0]);
                bf[nt][1] = __float_as_uint(bp[4]);
            }
            #pragma unroll
            for (int mt = 0; mt < 4; ++mt) {
                const float* ap = sA + (wm + mt * 16 + g) * PITCH + k8 * 8 + t;
                uint32_t a0 = __float_as_uint(ap[0]);
                uint32_t a1 = __float_as_uint(ap[8 * PITCH]);
                uint32_t a2 = __float_as_uint(ap[4]);
                uint32_t a3 = __float_as_uint(ap[8 * PITCH + 4]);
                #pragma unroll
                for (int nt = 0; nt < 8; ++nt)
                    mma_tf32(acc[mt][nt], a0, a1, a2, a3, bf[nt][0], bf[nt][1]);
            }
        }
    }

    #pragma unroll
    for (int nt = 0; nt < 8; ++nt) {
        const int c = bn + wn + nt * 8 + 2 * t;
        const float2 bia = *(const float2*)&bias[c];
        #pragma unroll
        for (int mt = 0; mt < 4; ++mt) {
            const int r0 = bm + wm + mt * 16 + g;
            float v0 = acc[mt][nt][0] + bia.x;
            float v1 = acc[mt][nt][1] + bia.y;
            float v2 = acc[mt][nt][2] + bia.x;
            float v3 = acc[mt][nt][3] + bia.y;
            if (EPI == 0) {
                v0 = to_tf32(v0); v1 = to_tf32(v1); v2 = to_tf32(v2); v3 = to_tf32(v3);
            } else if (EPI == 2) {
                v0 = to_tf32(0.5f * v0 * (1.0f + erff(v0 * 0.70710678118654752f)));
                v1 = to_tf32(0.5f * v1 * (1.0f + erff(v1 * 0.70710678118654752f)));
                v2 = to_tf32(0.5f * v2 * (1.0f + erff(v2 * 0.70710678118654752f)));
                v3 = to_tf32(0.5f * v3 * (1.0f + erff(v3 * 0.70710678118654752f)));
            }
            if (r0 < M) {
                if (EPI == 1) {
                    float2 rv = *(const float2*)&res[(size_t)r0 * N + c];
                    v0 += rv.x; v1 += rv.y;
                }
                *(float2*)&out[(size_t)r0 * N + c] = make_float2(v0, v1);
            }
            if (r0 + 8 < M) {
                if (EPI == 1) {
                    float2 rv = *(const float2*)&res[(size_t)(r0 + 8) * N + c];
                    v2 += rv.x; v3 += rv.y;
                }
                *(float2*)&out[(size_t)(r0 + 8) * N + c] = make_float2(v2, v3);
            }
        }
    }
}

// ---------------- tensor-core flash attention: 128q-CTA, 64-key tiles --------------
// smem layout (floats): Qs[128][68] | Ps[128][68] | Ks[2][64][68] | Vs[2][64][72]
#define QP 68
#define VP 72
#define OFF_Q 0
#define OFF_P (128 * QP)
#define OFF_K (2 * 128 * QP)
#define OFF_V (OFF_K + 2 * 64 * QP)
#define ATT_SMEM ((OFF_V + 2 * 64 * VP) * 4)
#define NKT 10                     // ceil(577/64)

__global__ void __launch_bounds__(256, 1) attn_tc(
    const float* __restrict__ qkv, float* __restrict__ out)
{
    extern __shared__ float sm[];
    const uint32_t sbase = smem_u32(sm);

    const int qt = blockIdx.x;       // 0..4 (128-query tiles)
    const int h  = blockIdx.y;
    const int b  = blockIdx.z;
    const int tid  = threadIdx.x;
    const int wid  = tid >> 5;
    const int lane = tid & 31;
    const int g = lane >> 2, t = lane & 3;
    const int wr = wid * 16;         // warp's q-row base within tile
    const size_t browbase = (size_t)b * SEQ;
    const float* qbase = qkv + browbase * C3 + h * DHEAD;

    // ---- load Q tile (128 x 64) ----
    #pragma unroll
    for (int i = 0; i < 8; ++i) {
        int f = i * 256 + tid;
        int r = f >> 4, q4 = (f & 15) << 2;
        int n = qt * 128 + r;
        int sz = (n < SEQ) ? 16 : 0;
        if (n >= SEQ) n = SEQ - 1;
        cp_async16z(sbase + (uint32_t)((OFF_Q + r * QP + q4) * 4),
                    qbase + (size_t)n * C3 + q4, sz);
    }
    // ---- load K/V tile 0 into buf 0 ----
    #pragma unroll
    for (int i = 0; i < 4; ++i) {
        int f = i * 256 + tid;
        int r = f >> 4, q4 = (f & 15) << 2;
        const float* kb = qbase + (size_t)r * C3 + q4;     // kt=0: kk = r
        cp_async16(sbase + (uint32_t)((OFF_K + r * QP + q4) * 4), kb + CDIM);
        cp_async16(sbase + (uint32_t)((OFF_V + r * VP + q4) * 4), kb + 2 * CDIM);
    }
    asm volatile("cp.async.commit_group;" ::: "memory");

    float oacc[8][4];
    #pragma unroll
    for (int nt = 0; nt < 8; ++nt)
        #pragma unroll
        for (int j = 0; j < 4; ++j) oacc[nt][j] = 0.f;
    float m0 = -INFINITY, m1 = -INFINITY, l0 = 0.f, l1 = 0.f;

    for (int kt = 0; kt < NKT; ++kt) {
        const int buf = kt & 1;
        if (kt > 0) __syncthreads();   // all warps done with buf (kt+1)&1 (from kt-1)
        if (kt + 1 < NKT) {
            const int nbuf = (kt + 1) & 1;
            #pragma unroll
            for (int i = 0; i < 4; ++i) {
                int f = i * 256 + tid;
                int r = f >> 4, q4 = (f & 15) << 2;
                int kk = (kt + 1) * 64 + r;
                int sz = (kk < SEQ) ? 16 : 0;
                if (kk >= SEQ) kk = SEQ - 1;
                const float* kb = qbase + (size_t)kk * C3 + q4;
                cp_async16z(sbase + (uint32_t)((OFF_K + (nbuf * 64 + r) * QP + q4) * 4),
                            kb + CDIM, sz);
                cp_async16z(sbase + (uint32_t)((OFF_V + (nbuf * 64 + r) * VP + q4) * 4),
                            kb + 2 * CDIM, sz);
            }
        }
        asm volatile("cp.async.commit_group;" ::: "memory");
        asm volatile("cp.async.wait_group 1;" ::: "memory");
        __syncthreads();               // tile kt (and Q on kt==0) visible to all

        const float* Qs = sm + OFF_Q;
        const float* Ks = sm + OFF_K + buf * 64 * QP;
        const float* Vs = sm + OFF_V + buf * 64 * VP;
        float* Ps = sm + OFF_P;

        // ---- S = Q @ K^T (16 x 64 per warp) ----
        float sacc[8][4];
        #pragma unroll
        for (int nt = 0; nt < 8; ++nt)
            #pragma unroll
            for (int j = 0; j < 4; ++j) sacc[nt][j] = 0.f;

        #pragma unroll
        for (int k8 = 0; k8 < 8; ++k8) {
            const float* ap = Qs + (wr + g) * QP + k8 * 8 + t;
            uint32_t a0 = __float_as_uint(ap[0]);
            uint32_t a1 = __float_as_uint(ap[8 * QP]);
            uint32_t a2 = __float_as_uint(ap[4]);
            uint32_t a3 = __float_as_uint(ap[8 * QP + 4]);
            #pragma unroll
            for (int nt = 0; nt < 8; ++nt) {
                const float* bp = Ks + (nt * 8 + g) * QP + k8 * 8 + t;
                mma_tf32(sacc[nt], a0, a1, a2, a3,
                         __float_as_uint(bp[0]), __float_as_uint(bp[4]));
            }
        }

        // ---- scale + mask ----
        const int kb0 = kt * 64;
        #pragma unroll
        for (int nt = 0; nt < 8; ++nt) {
            const int c0 = kb0 + nt * 8 + 2 * t;
            sacc[nt][0] = (c0     < SEQ) ? sacc[nt][0] * 0.125f : -INFINITY;
            sacc[nt][1] = (c0 + 1 < SEQ) ? sacc[nt][1] * 0.125f : -INFINITY;
            sacc[nt][2] = (c0     < SEQ) ? sacc[nt][2] * 0.125f : -INFINITY;
            sacc[nt][3] = (c0 + 1 < SEQ) ? sacc[nt][3] * 0.125f : -INFINITY;
        }

        // ---- online softmax (rows g and g+8) ----
        float mt0 = -INFINITY, mt1 = -INFINITY;
        #pragma unroll
        for (int nt = 0; nt < 8; ++nt) {
            mt0 = fmaxf(mt0, fmaxf(sacc[nt][0], sacc[nt][1]));
            mt1 = fmaxf(mt1, fmaxf(sacc[nt][2], sacc[nt][3]));
        }
        mt0 = fmaxf(mt0, __shfl_xor_sync(0xffffffffu, mt0, 1));
        mt0 = fmaxf(mt0, __shfl_xor_sync(0xffffffffu, mt0, 2));
        mt1 = fmaxf(mt1, __shfl_xor_sync(0xffffffffu, mt1, 1));
        mt1 = fmaxf(mt1, __shfl_xor_sync(0xffffffffu, mt1, 2));

        const float mn0 = fmaxf(m0, mt0), mn1 = fmaxf(m1, mt1);
        const float corr0 = expf(m0 - mn0), corr1 = expf(m1 - mn1);
        float ps0 = 0.f, ps1 = 0.f;
        #pragma unroll
        for (int nt = 0; nt < 8; ++nt) {
            float p0 = expf(sacc[nt][0] - mn0);
            float p1 = expf(sacc[nt][1] - mn0);
            float p2 = expf(sacc[nt][2] - mn1);
            float p3 = expf(sacc[nt][3] - mn1);
            ps0 += p0 + p1; ps1 += p2 + p3;
            *(float2*)&Ps[(wr + g) * QP + nt * 8 + 2 * t] =
                make_float2(to_tf32(p0), to_tf32(p1));
            *(float2*)&Ps[(wr + g + 8) * QP + nt * 8 + 2 * t] =
                make_float2(to_tf32(p2), to_tf32(p3));
        }
        ps0 += __shfl_xor_sync(0xffffffffu, ps0, 1);
        ps0 += __shfl_xor_sync(0xffffffffu, ps0, 2);
        ps1 += __shfl_xor_sync(0xffffffffu, ps1, 1);
        ps1 += __shfl_xor_sync(0xffffffffu, ps1, 2);
        l0 = l0 * corr0 + ps0;  m0 = mn0;
        l1 = l1 * corr1 + ps1;  m1 = mn1;
        #pragma unroll
        for (int nt = 0; nt < 8; ++nt) {
            oacc[nt][0] *= corr0; oacc[nt][1] *= corr0;
            oacc[nt][2] *= corr1; oacc[nt][3] *= corr1;
        }
        __syncwarp();   // P stores visible within warp before fragment re-load

        // ---- O += P @ V (16 x 64 per warp) ----
        #pragma unroll
        for (int k8 = 0; k8 < 8; ++k8) {
            const float* ap = Ps + (wr + g) * QP + k8 * 8 + t;
            uint32_t a0 = __float_as_uint(ap[0]);
            uint32_t a1 = __float_as_uint(ap[8 * QP]);
            uint32_t a2 = __float_as_uint(ap[4]);
            uint32_t a3 = __float_as_uint(ap[8 * QP + 4]);
            #pragma unroll
            for (int nt = 0; nt < 8; ++nt) {
                const float* bp = Vs + (k8 * 8 + t) * VP + nt * 8 + g;
                mma_tf32(oacc[nt], a0, a1, a2, a3,
                         __float_as_uint(bp[0]), __float_as_uint(bp[4 * VP]));
            }
        }
    }

    // ---- write O (tf32-rounded; feeds proj GEMM) ----
    const float inv0 = 1.0f / l0, inv1 = 1.0f / l1;
    const int r0 = qt * 128 + wr + g;
    const int r1 = r0 + 8;
    #pragma unroll
    for (int nt = 0; nt < 8; ++nt) {
        const int col = h * DHEAD + nt * 8 + 2 * t;
        if (r0 < SEQ)
            *(float2*)&out[(browbase + r0) * CDIM + col] =
                make_float2(to_tf32(oacc[nt][0] * inv0), to_tf32(oacc[nt][1] * inv0));
        if (r1 < SEQ)
            *(float2*)&out[(browbase + r1) * CDIM + col] =
                make_float2(to_tf32(oacc[nt][2] * inv1), to_tf32(oacc[nt][3] * inv1));
    }
}

// ---------------- launcher ----------------
extern "C" void kernel_launch(void* const* d_in, const int* in_sizes, int n_in,
                              void* d_out, int out_size)
{
    const float* x      = (const float*)d_in[0];
    const float* ln1_g  = (const float*)d_in[1];
    const float* ln1_b  = (const float*)d_in[2];
    const float* ln2_g  = (const float*)d_in[3];
    const float* ln2_b  = (const float*)d_in[4];
    const float* qkv_w  = (const float*)d_in[5];
    const float* qkv_b  = (const float*)d_in[6];
    const float* proj_w = (const float*)d_in[7];
    const float* proj_b = (const float*)d_in[8];
    const float* fc1_w  = (const float*)d_in[9];
    const float* fc1_b  = (const float*)d_in[10];
    const float* fc2_w  = (const float*)d_in[11];
    const float* fc2_b  = (const float*)d_in[12];
    float* out = (float*)d_out;

    float *h, *qkv, *attn, *x1, *ff, *wtq, *wtp, *wt1, *wt2;
    cudaGetSymbolAddress((void**)&h,    g_h);
    cudaGetSymbolAddress((void**)&qkv,  g_qkv);
    cudaGetSymbolAddress((void**)&attn, g_attn);
    cudaGetSymbolAddress((void**)&x1,   g_x1);
    cudaGetSymbolAddress((void**)&ff,   g_ff);
    cudaGetSymbolAddress((void**)&wtq,  g_wt_qkv);
    cudaGetSymbolAddress((void**)&wtp,  g_wt_proj);
    cudaGetSymbolAddress((void**)&wt1,  g_wt_fc1);
    cudaGetSymbolAddress((void**)&wt2,  g_wt_fc2);

    cudaFuncSetAttribute(gemm_mma<0>, cudaFuncAttributeMaxDynamicSharedMemorySize, SMEM_DYN);
    cudaFuncSetAttribute(gemm_mma<1>, cudaFuncAttributeMaxDynamicSharedMemorySize, SMEM_DYN);
    cudaFuncSetAttribute(gemm_mma<2>, cudaFuncAttributeMaxDynamicSharedMemorySize, SMEM_DYN);
    cudaFuncSetAttribute(attn_tc,     cudaFuncAttributeMaxDynamicSharedMemorySize, ATT_SMEM);

    const int M  = MROWS;
    const int gy = (M + GBM - 1) / GBM;     // 145
    dim3 tb(32, 8);

    transpose_w<<<dim3(CDIM / 32, C3 / 32),   tb>>>(qkv_w,  wtq, CDIM, C3);
    transpose_w<<<dim3(CDIM / 32, CDIM / 32), tb>>>(proj_w, wtp, CDIM, CDIM);
    transpose_w<<<dim3(CDIM / 32, DFF / 32),  tb>>>(fc1_w,  wt1, CDIM, DFF);
    transpose_w<<<dim3(DFF / 32, CDIM / 32),  tb>>>(fc2_w,  wt2, DFF, CDIM);

    // 1. LN1
    ln_kernel<<<M, 256>>>(x, ln1_g, ln1_b, h);
    // 2. QKV = h @ qkv_w + qkv_b   (EPI=0: tf32-rounded output)
    gemm_mma<0><<<dim3(C3 / GBN, gy), 256, SMEM_DYN>>>(h, wtq, qkv_b, nullptr, qkv, M, CDIM, C3);
    // 3. attention (tensor-core flash)
    attn_tc<<<dim3((SEQ + 127) / 128, NHEAD, BATCH), 256, ATT_SMEM>>>(qkv, attn);
    // 4. x1 = x + attn @ proj_w + proj_b
    gemm_mma<1><<<dim3(CDIM / GBN, gy), 256, SMEM_DYN>>>(attn, wtp, proj_b, x, x1, M, CDIM, CDIM);
    // 5. LN2
    ln_kernel<<<M, 256>>>(x1, ln2_g, ln2_b, h);
    // 6. ff = gelu(h @ fc1_w + fc1_b)
    gemm_mma<2><<<dim3(DFF / GBN, gy), 256, SMEM_DYN>>>(h, wt1, fc1_b, nullptr, ff, M, CDIM, DFF);
    // 7. out = x1 + ff @ fc2_w + fc2_b
    gemm_mma<1><<<dim3(CDIM / GBN, gy), 256, SMEM_DYN>>>(ff, wt2, fc2_b, x1, out, M, DFF, CDIM);
}

// round 6
// speedup vs baseline: 5.3155x; 1.7283x over previous
#include <cuda_runtime.h>
#include <cuda_fp16.h>
#include <cstdint>
#include <math.h>

// ---------------- problem constants ----------------
#define BATCH 32
#define SEQ   577
#define CDIM  768
#define NHEAD 12
#define DHEAD 64
#define DFF   3072
#define MROWS (BATCH*SEQ)          // 18464
#define C3    2304
#define QKW   1536                 // row width of g_qk (Q|K)
#define SEQP  640                  // padded seq for transposed V

// ---------------- scratch (device globals; no allocation) ----------------
__device__ __align__(256) __half g_h   [(size_t)MROWS * CDIM];
__device__ __align__(256) __half g_qk  [(size_t)MROWS * QKW];
__device__ __align__(256) __half g_vt  [(size_t)BATCH * NHEAD * DHEAD * SEQP];
__device__ __align__(256) __half g_attn[(size_t)MROWS * CDIM];
__device__ __align__(256) float  g_x1  [(size_t)MROWS * CDIM];
__device__ __align__(256) __half g_ff  [(size_t)MROWS * DFF];
__device__ __align__(256) __half g_wt_qkv [(size_t)C3   * CDIM];
__device__ __align__(256) __half g_wt_proj[(size_t)CDIM * CDIM];
__device__ __align__(256) __half g_wt_fc1 [(size_t)DFF  * CDIM];
__device__ __align__(256) __half g_wt_fc2 [(size_t)CDIM * DFF];

// ---------------- helpers ----------------
static __device__ __forceinline__ uint32_t smem_u32(const void* p) {
    uint32_t a;
    asm("{ .reg .u64 t; cvta.to.shared.u64 t, %1; cvt.u32.u64 %0, t; }" : "=r"(a) : "l"(p));
    return a;
}
static __device__ __forceinline__ void cp_async16(uint32_t dst, const void* src) {
    asm volatile("cp.async.cg.shared.global [%0], [%1], 16;" :: "r"(dst), "l"(src));
}
static __device__ __forceinline__ void cp_async16z(uint32_t dst, const void* src, int sz) {
    asm volatile("cp.async.cg.shared.global [%0], [%1], 16, %2;" :: "r"(dst), "l"(src), "r"(sz));
}
static __device__ __forceinline__ void mma_f16(
    float* d, uint32_t a0, uint32_t a1, uint32_t a2, uint32_t a3,
    uint32_t b0, uint32_t b1)
{
    asm volatile(
        "mma.sync.aligned.m16n8k16.row.col.f32.f16.f16.f32 "
        "{%0,%1,%2,%3}, {%4,%5,%6,%7}, {%8,%9}, {%0,%1,%2,%3};"
        : "+f"(d[0]), "+f"(d[1]), "+f"(d[2]), "+f"(d[3])
        : "r"(a0), "r"(a1), "r"(a2), "r"(a3), "r"(b0), "r"(b1));
}

// ---------------- LayerNorm (fp32 in, half out) ----------------
__global__ void __launch_bounds__(256) ln_kernel(
    const float* __restrict__ x, const float* __restrict__ g,
    const float* __restrict__ b, __half* __restrict__ out)
{
    __shared__ float red[8];
    const int row = blockIdx.x;
    const int tid = threadIdx.x;
    const float* xr = x + (size_t)row * CDIM;

    float v0 = xr[tid], v1 = xr[tid + 256], v2 = xr[tid + 512];

    float s = v0 + v1 + v2;
    #pragma unroll
    for (int o = 16; o > 0; o >>= 1) s += __shfl_xor_sync(0xffffffffu, s, o);
    if ((tid & 31) == 0) red[tid >> 5] = s;
    __syncthreads();
    if (tid == 0) {
        float t = 0.f;
        #pragma unroll
        for (int w = 0; w < 8; ++w) t += red[w];
        red[0] = t;
    }
    __syncthreads();
    const float mean = red[0] * (1.0f / CDIM);
    __syncthreads();

    float d0 = v0 - mean, d1 = v1 - mean, d2 = v2 - mean;
    float sq = d0 * d0 + d1 * d1 + d2 * d2;
    #pragma unroll
    for (int o = 16; o > 0; o >>= 1) sq += __shfl_xor_sync(0xffffffffu, sq, o);
    if ((tid & 31) == 0) red[tid >> 5] = sq;
    __syncthreads();
    if (tid == 0) {
        float t = 0.f;
        #pragma unroll
        for (int w = 0; w < 8; ++w) t += red[w];
        red[0] = t;
    }
    __syncthreads();
    const float var = red[0] * (1.0f / CDIM);
    const float rstd = rsqrtf(var + 1e-5f);

    __half* outr = out + (size_t)row * CDIM;
    outr[tid]       = __float2half_rn(d0 * rstd * g[tid]       + b[tid]);
    outr[tid + 256] = __float2half_rn(d1 * rstd * g[tid + 256] + b[tid + 256]);
    outr[tid + 512] = __float2half_rn(d2 * rstd * g[tid + 512] + b[tid + 512]);
}

// ---------------- weight transpose (W[K,N] f32 -> Wt[N,K] half) ----------------
__global__ void __launch_bounds__(256) transpose_w(
    const float* __restrict__ W, __half* __restrict__ Wt, int K, int N)
{
    __shared__ float t[32][33];
    const int k0 = blockIdx.x * 32, n0 = blockIdx.y * 32;
    #pragma unroll
    for (int i = threadIdx.y; i < 32; i += 8)
        t[i][threadIdx.x] = W[(size_t)(k0 + i) * N + n0 + threadIdx.x];
    __syncthreads();
    #pragma unroll
    for (int i = threadIdx.y; i < 32; i += 8)
        Wt[(size_t)(n0 + i) * K + k0 + threadIdx.x] = __float2half_rn(t[threadIdx.x][i]);
}

// ---------------- zero tail of transposed V (n in [512,640)) ----------------
__global__ void __launch_bounds__(256) zero_vt() {
    __half* vt = g_vt + (size_t)blockIdx.x * DHEAD * SEQP;
    const uint4 z = make_uint4(0u, 0u, 0u, 0u);
    #pragma unroll
    for (int i = 0; i < 4; ++i) {
        int f = i * 256 + threadIdx.x;
        int d = f >> 4, u = f & 15;
        *(uint4*)(vt + (size_t)d * SEQP + 512 + u * 8) = z;
    }
}

// ---------------- fp16 HMMA GEMM: out = A[M,K] @ Wt[N,K]^T + bias (+epilogue) ------
// EPI 0: qkv (Q,K -> g_qk half; V -> g_vt transposed half)
// EPI 1: bias + residual(f32) -> f32
// EPI 2: bias + exact GELU -> half
#define NSTAGE 3
#define GBM 128
#define GBN 256
#define PH 72                          // halfs per smem row (64 + 8 pad)
#define STG_BYTES ((128 + 256) * PH * 2)   // 55296
#define SMEM_DYN (NSTAGE * STG_BYTES)

__device__ __forceinline__ void load_stage(
    uint32_t sb, const __half* __restrict__ A, const __half* __restrict__ Wt,
    int bm, int bn, int M, int K, int kc, int tid)
{
    #pragma unroll
    for (int i = 0; i < 4; ++i) {
        int f = i * 256 + tid;
        int r = f >> 3, q = f & 7;
        int rr = bm + r;
        int sz = (rr < M) ? 16 : 0;
        if (rr >= M) rr = M - 1;
        cp_async16z(sb + (uint32_t)(r * (PH * 2) + q * 16),
                    A + (size_t)rr * K + kc + q * 8, sz);
    }
    const uint32_t bb = sb + 128 * (PH * 2);
    #pragma unroll
    for (int i = 0; i < 8; ++i) {
        int f = i * 256 + tid;
        int r = f >> 3, q = f & 7;
        cp_async16(bb + (uint32_t)(r * (PH * 2) + q * 16),
                   Wt + (size_t)(bn + r) * K + kc + q * 8);
    }
    asm volatile("cp.async.commit_group;" ::: "memory");
}

template <int EPI>
__global__ void __launch_bounds__(256, 1) gemm_mma(
    const __half* __restrict__ A, const __half* __restrict__ Wt,
    const float* __restrict__ bias, const float* __restrict__ res,
    void* __restrict__ outp, __half* __restrict__ vt,
    int M, int K, int N)
{
    extern __shared__ __align__(16) char dsm[];
    const uint32_t sbase = smem_u32(dsm);

    const int tid  = threadIdx.x;
    const int wid  = tid >> 5;
    const int lane = tid & 31;
    const int g = lane >> 2, t = lane & 3;
    const int bm = blockIdx.y * GBM;
    const int bn = blockIdx.x * GBN;
    const int wm = (wid >> 2) * 64;
    const int wn = (wid & 3) * 64;

    float acc[4][8][4];
    #pragma unroll
    for (int mt = 0; mt < 4; ++mt)
        #pragma unroll
        for (int nt = 0; nt < 8; ++nt)
            #pragma unroll
            for (int j = 0; j < 4; ++j) acc[mt][nt][j] = 0.f;

    const int KT = K >> 6;   // 64-half K chunks

    for (int c = 0; c < NSTAGE - 1; ++c)
        load_stage(sbase + (uint32_t)(c * STG_BYTES), A, Wt, bm, bn, M, K, c * 64, tid);

    for (int kt = 0; kt < KT; ++kt) {
        asm volatile("cp.async.wait_group %0;" :: "n"(NSTAGE - 2) : "memory");
        __syncthreads();

        const int kn = kt + NSTAGE - 1;
        if (kn < KT)
            load_stage(sbase + (uint32_t)((kn % NSTAGE) * STG_BYTES), A, Wt, bm, bn, M, K, kn * 64, tid);
        else
            asm volatile("cp.async.commit_group;" ::: "memory");

        const uint32_t* sA2 = (const uint32_t*)(dsm + (kt % NSTAGE) * STG_BYTES);
        const uint32_t* sB2 = sA2 + 128 * (PH / 2);

        #pragma unroll
        for (int k16 = 0; k16 < 4; ++k16) {
            uint32_t bf[8][2];
            #pragma unroll
            for (int nt = 0; nt < 8; ++nt) {
                const uint32_t* bp = sB2 + (wn + nt * 8 + g) * (PH / 2) + k16 * 8 + t;
                bf[nt][0] = bp[0];
                bf[nt][1] = bp[4];
            }
            #pragma unroll
            for (int mt = 0; mt < 4; ++mt) {
                const uint32_t* ap = sA2 + (wm + mt * 16 + g) * (PH / 2) + k16 * 8 + t;
                uint32_t a0 = ap[0];
                uint32_t a1 = ap[8 * (PH / 2)];
                uint32_t a2 = ap[4];
                uint32_t a3 = ap[8 * (PH / 2) + 4];
                #pragma unroll
                for (int nt = 0; nt < 8; ++nt)
                    mma_f16(acc[mt][nt], a0, a1, a2, a3, bf[nt][0], bf[nt][1]);
            }
        }
    }

    // ---- epilogue ----
    #pragma unroll
    for (int nt = 0; nt < 8; ++nt) {
        const int c = bn + wn + nt * 8 + 2 * t;
        const float2 bia = *(const float2*)&bias[c];
        #pragma unroll
        for (int mt = 0; mt < 4; ++mt) {
            const int r0 = bm + wm + mt * 16 + g;
            const int r1 = r0 + 8;
            float v0 = acc[mt][nt][0] + bia.x;
            float v1 = acc[mt][nt][1] + bia.y;
            float v2 = acc[mt][nt][2] + bia.x;
            float v3 = acc[mt][nt][3] + bia.y;

            if (EPI == 0) {
                if (c < QKW) {
                    __half* qk = (__half*)outp;
                    if (r0 < M) *(__half2*)&qk[(size_t)r0 * QKW + c] = __floats2half2_rn(v0, v1);
                    if (r1 < M) *(__half2*)&qk[(size_t)r1 * QKW + c] = __floats2half2_rn(v2, v3);
                } else {
                    const int cc = c - QKW;
                    const int hh = cc >> 6, dd = cc & 63;
                    if (r0 < M) {
                        int bb = r0 / SEQ, n = r0 - bb * SEQ;
                        __half* p = vt + ((size_t)(bb * NHEAD + hh) * DHEAD + dd) * SEQP + n;
                        p[0]    = __float2half_rn(v0);
                        p[SEQP] = __float2half_rn(v1);
                    }
                    if (r1 < M) {
                        int bb = r1 / SEQ, n = r1 - bb * SEQ;
                        __half* p = vt + ((size_t)(bb * NHEAD + hh) * DHEAD + dd) * SEQP + n;
                        p[0]    = __float2half_rn(v2);
                        p[SEQP] = __float2half_rn(v3);
                    }
                }
            } else if (EPI == 1) {
                float* out = (float*)outp;
                if (r0 < M) {
                    float2 rv = *(const float2*)&res[(size_t)r0 * N + c];
                    *(float2*)&out[(size_t)r0 * N + c] = make_float2(v0 + rv.x, v1 + rv.y);
                }
                if (r1 < M) {
                    float2 rv = *(const float2*)&res[(size_t)r1 * N + c];
                    *(float2*)&out[(size_t)r1 * N + c] = make_float2(v2 + rv.x, v3 + rv.y);
                }
            } else {
                __half* out = (__half*)outp;
                v0 = 0.5f * v0 * (1.0f + erff(v0 * 0.70710678118654752f));
                v1 = 0.5f * v1 * (1.0f + erff(v1 * 0.70710678118654752f));
                v2 = 0.5f * v2 * (1.0f + erff(v2 * 0.70710678118654752f));
                v3 = 0.5f * v3 * (1.0f + erff(v3 * 0.70710678118654752f));
                if (r0 < M) *(__half2*)&out[(size_t)r0 * N + c] = __floats2half2_rn(v0, v1);
                if (r1 < M) *(__half2*)&out[(size_t)r1 * N + c] = __floats2half2_rn(v2, v3);
            }
        }
    }
}

// ---------------- fp16 flash attention: 128q-CTA, 64-key tiles ---------------------
// smem halfs: Qs[128][72] | Ps[128][72] | Ks[2][64][72] | Vt[2][64][72]
#define OQ 0
#define OP (128 * PH)
#define OK (256 * PH)
#define OV (OK + 2 * 64 * PH)
#define ATT_SMEM ((OV + 2 * 64 * PH) * 2)
#define NKT 10

__global__ void __launch_bounds__(256) attn_tc(
    const __half* __restrict__ qk, const __half* __restrict__ vt,
    __half* __restrict__ outa)
{
    extern __shared__ __align__(16) char sm[];
    const uint32_t sbase = smem_u32(sm);

    const int qt = blockIdx.x;
    const int h  = blockIdx.y;
    const int b  = blockIdx.z;
    const int tid  = threadIdx.x;
    const int wid  = tid >> 5;
    const int lane = tid & 31;
    const int g = lane >> 2, t = lane & 3;
    const int wr = wid * 16;
    const size_t browbase = (size_t)b * SEQ;
    const __half* qbase = qk + browbase * QKW + h * DHEAD;
    const __half* vbase = vt + (size_t)(b * NHEAD + h) * DHEAD * SEQP;

    // ---- Q tile (128 x 64 halfs) ----
    #pragma unroll
    for (int i = 0; i < 4; ++i) {
        int f = i * 256 + tid;
        int r = f >> 3, q = f & 7;
        int n = qt * 128 + r;
        int sz = (n < SEQ) ? 16 : 0;
        if (n >= SEQ) n = SEQ - 1;
        cp_async16z(sbase + (uint32_t)((OQ + r * PH + q * 8) * 2),
                    qbase + (size_t)n * QKW + q * 8, sz);
    }
    // ---- K/V tile 0 into buf 0 ----
    #pragma unroll
    for (int i = 0; i < 2; ++i) {
        int f = i * 256 + tid;
        int r = f >> 3, q = f & 7;
        cp_async16(sbase + (uint32_t)((OK + r * PH + q * 8) * 2),
                   qbase + (size_t)r * QKW + CDIM + q * 8);
        cp_async16(sbase + (uint32_t)((OV + r * PH + q * 8) * 2),
                   vbase + (size_t)r * SEQP + q * 8);
    }
    asm volatile("cp.async.commit_group;" ::: "memory");

    float oacc[8][4];
    #pragma unroll
    for (int nt = 0; nt < 8; ++nt)
        #pragma unroll
        for (int j = 0; j < 4; ++j) oacc[nt][j] = 0.f;
    float m0 = -INFINITY, m1 = -INFINITY, l0 = 0.f, l1 = 0.f;

    for (int kt = 0; kt < NKT; ++kt) {
        const int buf = kt & 1;
        if (kt > 0) __syncthreads();
        if (kt + 1 < NKT) {
            const int nbuf = (kt + 1) & 1;
            #pragma unroll
            for (int i = 0; i < 2; ++i) {
                int f = i * 256 + tid;
                int r = f >> 3, q = f & 7;
                int kk = (kt + 1) * 64 + r;
                int sz = (kk < SEQ) ? 16 : 0;
                if (kk >= SEQ) kk = SEQ - 1;
                cp_async16z(sbase + (uint32_t)((OK + (nbuf * 64 + r) * PH + q * 8) * 2),
                            qbase + (size_t)kk * QKW + CDIM + q * 8, sz);
                cp_async16(sbase + (uint32_t)((OV + (nbuf * 64 + r) * PH + q * 8) * 2),
                           vbase + (size_t)r * SEQP + (kt + 1) * 64 + q * 8);
            }
        }
        asm volatile("cp.async.commit_group;" ::: "memory");
        asm volatile("cp.async.wait_group 1;" ::: "memory");
        __syncthreads();

        const uint32_t* Qs2 = (const uint32_t*)sm + OQ / 2;
        const uint32_t* Ks2 = (const uint32_t*)sm + (OK + buf * 64 * PH) / 2;
        const uint32_t* Vs2 = (const uint32_t*)sm + (OV + buf * 64 * PH) / 2;
        uint32_t* Ps2 = (uint32_t*)sm + OP / 2;

        // ---- S = Q @ K^T ----
        float sacc[8][4];
        #pragma unroll
        for (int nt = 0; nt < 8; ++nt)
            #pragma unroll
            for (int j = 0; j < 4; ++j) sacc[nt][j] = 0.f;

        #pragma unroll
        for (int k16 = 0; k16 < 4; ++k16) {
            const uint32_t* ap = Qs2 + (wr + g) * (PH / 2) + k16 * 8 + t;
            uint32_t a0 = ap[0];
            uint32_t a1 = ap[8 * (PH / 2)];
            uint32_t a2 = ap[4];
            uint32_t a3 = ap[8 * (PH / 2) + 4];
            #pragma unroll
            for (int nt = 0; nt < 8; ++nt) {
                const uint32_t* bp = Ks2 + (nt * 8 + g) * (PH / 2) + k16 * 8 + t;
                mma_f16(sacc[nt], a0, a1, a2, a3, bp[0], bp[4]);
            }
        }

        // ---- scale + mask ----
        const int kb0 = kt * 64;
        #pragma unroll
        for (int nt = 0; nt < 8; ++nt) {
            const int c0 = kb0 + nt * 8 + 2 * t;
            sacc[nt][0] = (c0     < SEQ) ? sacc[nt][0] * 0.125f : -INFINITY;
            sacc[nt][1] = (c0 + 1 < SEQ) ? sacc[nt][1] * 0.125f : -INFINITY;
            sacc[nt][2] = (c0     < SEQ) ? sacc[nt][2] * 0.125f : -INFINITY;
            sacc[nt][3] = (c0 + 1 < SEQ) ? sacc[nt][3] * 0.125f : -INFINITY;
        }

        // ---- online softmax (rows g, g+8) ----
        float mt0 = -INFINITY, mt1 = -INFINITY;
        #pragma unroll
        for (int nt = 0; nt < 8; ++nt) {
            mt0 = fmaxf(mt0, fmaxf(sacc[nt][0], sacc[nt][1]));
            mt1 = fmaxf(mt1, fmaxf(sacc[nt][2], sacc[nt][3]));
        }
        mt0 = fmaxf(mt0, __shfl_xor_sync(0xffffffffu, mt0, 1));
        mt0 = fmaxf(mt0, __shfl_xor_sync(0xffffffffu, mt0, 2));
        mt1 = fmaxf(mt1, __shfl_xor_sync(0xffffffffu, mt1, 1));
        mt1 = fmaxf(mt1, __shfl_xor_sync(0xffffffffu, mt1, 2));

        const float mn0 = fmaxf(m0, mt0), mn1 = fmaxf(m1, mt1);
        const float corr0 = expf(m0 - mn0), corr1 = expf(m1 - mn1);
        float ps0 = 0.f, ps1 = 0.f;
        #pragma unroll
        for (int nt = 0; nt < 8; ++nt) {
            float p0 = expf(sacc[nt][0] - mn0);
            float p1 = expf(sacc[nt][1] - mn0);
            float p2 = expf(sacc[nt][2] - mn1);
            float p3 = expf(sacc[nt][3] - mn1);
            ps0 += p0 + p1; ps1 += p2 + p3;
            __half2 h01 = __floats2half2_rn(p0, p1);
            __half2 h23 = __floats2half2_rn(p2, p3);
            Ps2[(wr + g) * (PH / 2) + nt * 4 + t]     = *(uint32_t*)&h01;
            Ps2[(wr + g + 8) * (PH / 2) + nt * 4 + t] = *(uint32_t*)&h23;
        }
        ps0 += __shfl_xor_sync(0xffffffffu, ps0, 1);
        ps0 += __shfl_xor_sync(0xffffffffu, ps0, 2);
        ps1 += __shfl_xor_sync(0xffffffffu, ps1, 1);
        ps1 += __shfl_xor_sync(0xffffffffu, ps1, 2);
        l0 = l0 * corr0 + ps0;  m0 = mn0;
        l1 = l1 * corr1 + ps1;  m1 = mn1;
        #pragma unroll
        for (int nt = 0; nt < 8; ++nt) {
            oacc[nt][0] *= corr0; oacc[nt][1] *= corr0;
            oacc[nt][2] *= corr1; oacc[nt][3] *= corr1;
        }
        __syncwarp();

        // ---- O += P @ Vt ----
        #pragma unroll
        for (int k16 = 0; k16 < 4; ++k16) {
            const uint32_t* ap = (const uint32_t*)Ps2 + (wr + g) * (PH / 2) + k16 * 8 + t;
            uint32_t a0 = ap[0];
            uint32_t a1 = ap[8 * (PH / 2)];
            uint32_t a2 = ap[4];
            uint32_t a3 = ap[8 * (PH / 2) + 4];
            #pragma unroll
            for (int nt = 0; nt < 8; ++nt) {
                const uint32_t* bp = Vs2 + (nt * 8 + g) * (PH / 2) + k16 * 8 + t;
                mma_f16(oacc[nt], a0, a1, a2, a3, bp[0], bp[4]);
            }
        }
    }

    // ---- write O (half; feeds proj GEMM) ----
    const float inv0 = 1.0f / l0, inv1 = 1.0f / l1;
    const int r0 = qt * 128 + wr + g;
    const int r1 = r0 + 8;
    #pragma unroll
    for (int nt = 0; nt < 8; ++nt) {
        const int col = h * DHEAD + nt * 8 + 2 * t;
        if (r0 < SEQ)
            *(__half2*)&outa[(browbase + r0) * CDIM + col] =
                __floats2half2_rn(oacc[nt][0] * inv0, oacc[nt][1] * inv0);
        if (r1 < SEQ)
            *(__half2*)&outa[(browbase + r1) * CDIM + col] =
                __floats2half2_rn(oacc[nt][2] * inv1, oacc[nt][3] * inv1);
    }
}

// ---------------- launcher ----------------
extern "C" void kernel_launch(void* const* d_in, const int* in_sizes, int n_in,
                              void* d_out, int out_size)
{
    const float* x      = (const float*)d_in[0];
    const float* ln1_g  = (const float*)d_in[1];
    const float* ln1_b  = (const float*)d_in[2];
    const float* ln2_g  = (const float*)d_in[3];
    const float* ln2_b  = (const float*)d_in[4];
    const float* qkv_w  = (const float*)d_in[5];
    const float* qkv_b  = (const float*)d_in[6];
    const float* proj_w = (const float*)d_in[7];
    const float* proj_b = (const float*)d_in[8];
    const float* fc1_w  = (const float*)d_in[9];
    const float* fc1_b  = (const float*)d_in[10];
    const float* fc2_w  = (const float*)d_in[11];
    const float* fc2_b  = (const float*)d_in[12];
    float* out = (float*)d_out;

    __half *h, *qk, *vt, *attn, *ff, *wtq, *wtp, *wt1, *wt2;
    float *x1;
    cudaGetSymbolAddress((void**)&h,    g_h);
    cudaGetSymbolAddress((void**)&qk,   g_qk);
    cudaGetSymbolAddress((void**)&vt,   g_vt);
    cudaGetSymbolAddress((void**)&attn, g_attn);
    cudaGetSymbolAddress((void**)&x1,   g_x1);
    cudaGetSymbolAddress((void**)&ff,   g_ff);
    cudaGetSymbolAddress((void**)&wtq,  g_wt_qkv);
    cudaGetSymbolAddress((void**)&wtp,  g_wt_proj);
    cudaGetSymbolAddress((void**)&wt1,  g_wt_fc1);
    cudaGetSymbolAddress((void**)&wt2,  g_wt_fc2);

    cudaFuncSetAttribute(gemm_mma<0>, cudaFuncAttributeMaxDynamicSharedMemorySize, SMEM_DYN);
    cudaFuncSetAttribute(gemm_mma<1>, cudaFuncAttributeMaxDynamicSharedMemorySize, SMEM_DYN);
    cudaFuncSetAttribute(gemm_mma<2>, cudaFuncAttributeMaxDynamicSharedMemorySize, SMEM_DYN);
    cudaFuncSetAttribute(attn_tc,     cudaFuncAttributeMaxDynamicSharedMemorySize, ATT_SMEM);

    const int M  = MROWS;
    const int gy = (M + GBM - 1) / GBM;     // 145
    dim3 tb(32, 8);

    transpose_w<<<dim3(CDIM / 32, C3 / 32),   tb>>>(qkv_w,  wtq, CDIM, C3);
    transpose_w<<<dim3(CDIM / 32, CDIM / 32), tb>>>(proj_w, wtp, CDIM, CDIM);
    transpose_w<<<dim3(CDIM / 32, DFF / 32),  tb>>>(fc1_w,  wt1, CDIM, DFF);
    transpose_w<<<dim3(DFF / 32, CDIM / 32),  tb>>>(fc2_w,  wt2, DFF, CDIM);
    zero_vt<<<BATCH * NHEAD, 256>>>();

    // 1. LN1
    ln_kernel<<<M, 256>>>(x, ln1_g, ln1_b, h);
    // 2. QKV (Q,K natural; V transposed)
    gemm_mma<0><<<dim3(C3 / GBN, gy), 256, SMEM_DYN>>>(h, wtq, qkv_b, nullptr, qk, vt, M, CDIM, C3);
    // 3. attention
    attn_tc<<<dim3((SEQ + 127) / 128, NHEAD, BATCH), 256, ATT_SMEM>>>(qk, vt, attn);
    // 4. x1 = x + attn @ proj_w + proj_b
    gemm_mma<1><<<dim3(CDIM / GBN, gy), 256, SMEM_DYN>>>(attn, wtp, proj_b, x, x1, nullptr, M, CDIM, CDIM);
    // 5. LN2
    ln_kernel<<<M, 256>>>(x1, ln2_g, ln2_b, h);
    // 6. ff = gelu(h @ fc1_w + fc1_b)
    gemm_mma<2><<<dim3(DFF / GBN, gy), 256, SMEM_DYN>>>(h, wt1, fc1_b, nullptr, ff, nullptr, M, CDIM, DFF);
    // 7. out = x1 + ff @ fc2_w + fc2_b
    gemm_mma<1><<<dim3(CDIM / GBN, gy), 256, SMEM_DYN>>>(ff, wt2, fc2_b, x1, out, nullptr, M, DFF, CDIM);
}

// round 8
// speedup vs baseline: 5.3298x; 1.0027x over previous
#include <cuda_runtime.h>
#include <cuda_fp16.h>
#include <cstdint>
#include <math.h>

// ---------------- problem constants ----------------
#define BATCH 32
#define SEQ   577
#define CDIM  768
#define NHEAD 12
#define DHEAD 64
#define DFF   3072
#define MROWS (BATCH*SEQ)          // 18464
#define C3    2304
#define QKW   1536                 // row width of g_qk (Q|K)
#define SEQP  640                  // padded seq for transposed V

// ---------------- scratch (device globals; no allocation) ----------------
__device__ __align__(256) __half g_h   [(size_t)MROWS * CDIM];
__device__ __align__(256) __half g_qk  [(size_t)MROWS * QKW];
__device__ __align__(256) __half g_vt  [(size_t)BATCH * NHEAD * DHEAD * SEQP];
__device__ __align__(256) __half g_attn[(size_t)MROWS * CDIM];
__device__ __align__(256) float  g_x1  [(size_t)MROWS * CDIM];
__device__ __align__(256) __half g_ff  [(size_t)MROWS * DFF];
__device__ __align__(256) __half g_wt_qkv [(size_t)C3   * CDIM];
__device__ __align__(256) __half g_wt_proj[(size_t)CDIM * CDIM];
__device__ __align__(256) __half g_wt_fc1 [(size_t)DFF  * CDIM];
__device__ __align__(256) __half g_wt_fc2 [(size_t)CDIM * DFF];

// ---------------- helpers ----------------
static __device__ __forceinline__ uint32_t smem_u32(const void* p) {
    uint32_t a;
    asm("{ .reg .u64 t; cvta.to.shared.u64 t, %1; cvt.u32.u64 %0, t; }" : "=r"(a) : "l"(p));
    return a;
}
static __device__ __forceinline__ void cp_async16(uint32_t dst, const void* src) {
    asm volatile("cp.async.cg.shared.global [%0], [%1], 16;" :: "r"(dst), "l"(src));
}
static __device__ __forceinline__ void cp_async16z(uint32_t dst, const void* src, int sz) {
    asm volatile("cp.async.cg.shared.global [%0], [%1], 16, %2;" :: "r"(dst), "l"(src), "r"(sz));
}
static __device__ __forceinline__ void mma_f16(
    float* d, uint32_t a0, uint32_t a1, uint32_t a2, uint32_t a3,
    uint32_t b0, uint32_t b1)
{
    asm volatile(
        "mma.sync.aligned.m16n8k16.row.col.f32.f16.f16.f32 "
        "{%0,%1,%2,%3}, {%4,%5,%6,%7}, {%8,%9}, {%0,%1,%2,%3};"
        : "+f"(d[0]), "+f"(d[1]), "+f"(d[2]), "+f"(d[3])
        : "r"(a0), "r"(a1), "r"(a2), "r"(a3), "r"(b0), "r"(b1));
}
static __device__ __forceinline__ void ldsm_x4(
    uint32_t& r0, uint32_t& r1, uint32_t& r2, uint32_t& r3, uint32_t addr)
{
    asm volatile("ldmatrix.sync.aligned.m8n8.x4.shared.b16 {%0,%1,%2,%3}, [%4];"
                 : "=r"(r0), "=r"(r1), "=r"(r2), "=r"(r3) : "r"(addr));
}

// ---------------- LayerNorm (fp32 in, half out) ----------------
__global__ void __launch_bounds__(256) ln_kernel(
    const float* __restrict__ x, const float* __restrict__ g,
    const float* __restrict__ b, __half* __restrict__ out)
{
    __shared__ float red[8];
    const int row = blockIdx.x;
    const int tid = threadIdx.x;
    const float* xr = x + (size_t)row * CDIM;

    float v0 = xr[tid], v1 = xr[tid + 256], v2 = xr[tid + 512];

    float s = v0 + v1 + v2;
    #pragma unroll
    for (int o = 16; o > 0; o >>= 1) s += __shfl_xor_sync(0xffffffffu, s, o);
    if ((tid & 31) == 0) red[tid >> 5] = s;
    __syncthreads();
    if (tid == 0) {
        float t = 0.f;
        #pragma unroll
        for (int w = 0; w < 8; ++w) t += red[w];
        red[0] = t;
    }
    __syncthreads();
    const float mean = red[0] * (1.0f / CDIM);
    __syncthreads();

    float d0 = v0 - mean, d1 = v1 - mean, d2 = v2 - mean;
    float sq = d0 * d0 + d1 * d1 + d2 * d2;
    #pragma unroll
    for (int o = 16; o > 0; o >>= 1) sq += __shfl_xor_sync(0xffffffffu, sq, o);
    if ((tid & 31) == 0) red[tid >> 5] = sq;
    __syncthreads();
    if (tid == 0) {
        float t = 0.f;
        #pragma unroll
        for (int w = 0; w < 8; ++w) t += red[w];
        red[0] = t;
    }
    __syncthreads();
    const float var = red[0] * (1.0f / CDIM);
    const float rstd = rsqrtf(var + 1e-5f);

    __half* outr = out + (size_t)row * CDIM;
    outr[tid]       = __float2half_rn(d0 * rstd * g[tid]       + b[tid]);
    outr[tid + 256] = __float2half_rn(d1 * rstd * g[tid + 256] + b[tid + 256]);
    outr[tid + 512] = __float2half_rn(d2 * rstd * g[tid + 512] + b[tid + 512]);
}

// ---------------- weight transpose (W[K,N] f32 -> Wt[N,K] half) ----------------
__global__ void __launch_bounds__(256) transpose_w(
    const float* __restrict__ W, __half* __restrict__ Wt, int K, int N)
{
    __shared__ float t[32][33];
    const int k0 = blockIdx.x * 32, n0 = blockIdx.y * 32;
    #pragma unroll
    for (int i = threadIdx.y; i < 32; i += 8)
        t[i][threadIdx.x] = W[(size_t)(k0 + i) * N + n0 + threadIdx.x];
    __syncthreads();
    #pragma unroll
    for (int i = threadIdx.y; i < 32; i += 8)
        Wt[(size_t)(n0 + i) * K + k0 + threadIdx.x] = __float2half_rn(t[threadIdx.x][i]);
}

// ---------------- zero tail of transposed V (n in [512,640)) ----------------
__global__ void __launch_bounds__(256) zero_vt() {
    __half* vt = g_vt + (size_t)blockIdx.x * DHEAD * SEQP;
    const uint4 z = make_uint4(0u, 0u, 0u, 0u);
    #pragma unroll
    for (int i = 0; i < 4; ++i) {
        int f = i * 256 + threadIdx.x;
        int d = f >> 4, u = f & 15;
        *(uint4*)(vt + (size_t)d * SEQP + 512 + u * 8) = z;
    }
}

// ---------------- fp16 HMMA GEMM (ldmatrix fragments) ------------------------------
// EPI 0: qkv (Q,K -> g_qk half; V -> g_vt transposed half)
// EPI 1: bias + residual(f32) -> f32
// EPI 2: bias + exact GELU -> half
#define NSTAGE 4
#define GBM 128
#define GBN 256
#define PH 72                              // halfs per smem row (64 + 8 pad); 144B stride
#define STG_BYTES ((128 + 256) * PH * 2)   // 55296
#define SMEM_DYN (NSTAGE * STG_BYTES)      // 221184

__device__ __forceinline__ void load_stage(
    uint32_t sb, const __half* __restrict__ A, const __half* __restrict__ Wt,
    int bm, int bn, int M, int K, int kc, int tid)
{
    #pragma unroll
    for (int i = 0; i < 4; ++i) {
        int f = i * 256 + tid;
        int r = f >> 3, q = f & 7;
        int rr = bm + r;
        int sz = (rr < M) ? 16 : 0;
        if (rr >= M) rr = M - 1;
        cp_async16z(sb + (uint32_t)(r * (PH * 2) + q * 16),
                    A + (size_t)rr * K + kc + q * 8, sz);
    }
    const uint32_t bb = sb + 128 * (PH * 2);
    #pragma unroll
    for (int i = 0; i < 8; ++i) {
        int f = i * 256 + tid;
        int r = f >> 3, q = f & 7;
        cp_async16(bb + (uint32_t)(r * (PH * 2) + q * 16),
                   Wt + (size_t)(bn + r) * K + kc + q * 8);
    }
    asm volatile("cp.async.commit_group;" ::: "memory");
}

template <int EPI>
__global__ void __launch_bounds__(256, 1) gemm_mma(
    const __half* __restrict__ A, const __half* __restrict__ Wt,
    const float* __restrict__ bias, const float* __restrict__ res,
    void* __restrict__ outp, __half* __restrict__ vt,
    int M, int K, int N)
{
    extern __shared__ __align__(16) char dsm[];
    const uint32_t sbase = smem_u32(dsm);

    const int tid  = threadIdx.x;
    const int wid  = tid >> 5;
    const int lane = tid & 31;
    const int g = lane >> 2, t = lane & 3;
    const int bm = blockIdx.y * GBM;
    const int bn = blockIdx.x * GBN;
    const int wm = (wid >> 2) * 64;
    const int wn = (wid & 3) * 64;

    // ldmatrix per-lane address components
    const int l15 = lane & 15;
    const int lhi = lane >> 4;                 // 0/1 -> k half
    const uint32_t aoff = (uint32_t)(((wm + l15) * PH + lhi * 8) * 2);
    const int l7 = lane & 7;
    const int q2 = lane >> 3;                  // 0..3
    const uint32_t boff = (uint32_t)(((wn + (q2 >> 1) * 8 + l7) * PH + (q2 & 1) * 8) * 2);

    float acc[4][8][4];
    #pragma unroll
    for (int mt = 0; mt < 4; ++mt)
        #pragma unroll
        for (int nt = 0; nt < 8; ++nt)
            #pragma unroll
            for (int j = 0; j < 4; ++j) acc[mt][nt][j] = 0.f;

    const int KT = K >> 6;   // 64-half K chunks

    for (int c = 0; c < NSTAGE - 1; ++c)
        load_stage(sbase + (uint32_t)(c * STG_BYTES), A, Wt, bm, bn, M, K, c * 64, tid);

    for (int kt = 0; kt < KT; ++kt) {
        asm volatile("cp.async.wait_group %0;" :: "n"(NSTAGE - 2) : "memory");
        __syncthreads();

        const int kn = kt + NSTAGE - 1;
        if (kn < KT)
            load_stage(sbase + (uint32_t)((kn % NSTAGE) * STG_BYTES), A, Wt, bm, bn, M, K, kn * 64, tid);
        else
            asm volatile("cp.async.commit_group;" ::: "memory");

        const uint32_t sA_u = sbase + (uint32_t)((kt % NSTAGE) * STG_BYTES);
        const uint32_t sB_u = sA_u + 128 * (PH * 2);

        #pragma unroll
        for (int k16 = 0; k16 < 4; ++k16) {
            uint32_t bf[8][2];
            #pragma unroll
            for (int ntp = 0; ntp < 4; ++ntp) {
                uint32_t r0, r1, r2, r3;
                ldsm_x4(r0, r1, r2, r3,
                        sB_u + boff + (uint32_t)(ntp * 16 * PH * 2 + k16 * 32));
                bf[2 * ntp][0] = r0; bf[2 * ntp][1] = r1;
                bf[2 * ntp + 1][0] = r2; bf[2 * ntp + 1][1] = r3;
            }
            #pragma unroll
            for (int mt = 0; mt < 4; ++mt) {
                uint32_t a0, a1, a2, a3;
                ldsm_x4(a0, a1, a2, a3,
                        sA_u + aoff + (uint32_t)(mt * 16 * PH * 2 + k16 * 32));
                #pragma unroll
                for (int nt = 0; nt < 8; ++nt)
                    mma_f16(acc[mt][nt], a0, a1, a2, a3, bf[nt][0], bf[nt][1]);
            }
        }
    }

    // ---- epilogue ----
    #pragma unroll
    for (int nt = 0; nt < 8; ++nt) {
        const int c = bn + wn + nt * 8 + 2 * t;
        const float2 bia = *(const float2*)&bias[c];
        #pragma unroll
        for (int mt = 0; mt < 4; ++mt) {
            const int r0 = bm + wm + mt * 16 + g;
            const int r1 = r0 + 8;
            float v0 = acc[mt][nt][0] + bia.x;
            float v1 = acc[mt][nt][1] + bia.y;
            float v2 = acc[mt][nt][2] + bia.x;
            float v3 = acc[mt][nt][3] + bia.y;

            if (EPI == 0) {
                if (c < QKW) {
                    __half* qk = (__half*)outp;
                    if (r0 < M) *(__half2*)&qk[(size_t)r0 * QKW + c] = __floats2half2_rn(v0, v1);
                    if (r1 < M) *(__half2*)&qk[(size_t)r1 * QKW + c] = __floats2half2_rn(v2, v3);
                } else {
                    const int cc = c - QKW;
                    const int hh = cc >> 6, dd = cc & 63;
                    if (r0 < M) {
                        int bb = r0 / SEQ, n = r0 - bb * SEQ;
                        __half* p = vt + ((size_t)(bb * NHEAD + hh) * DHEAD + dd) * SEQP + n;
                        p[0]    = __float2half_rn(v0);
                        p[SEQP] = __float2half_rn(v1);
                    }
                    if (r1 < M) {
                        int bb = r1 / SEQ, n = r1 - bb * SEQ;
                        __half* p = vt + ((size_t)(bb * NHEAD + hh) * DHEAD + dd) * SEQP + n;
                        p[0]    = __float2half_rn(v2);
                        p[SEQP] = __float2half_rn(v3);
                    }
                }
            } else if (EPI == 1) {
                float* out = (float*)outp;
                if (r0 < M) {
                    float2 rv = *(const float2*)&res[(size_t)r0 * N + c];
                    *(float2*)&out[(size_t)r0 * N + c] = make_float2(v0 + rv.x, v1 + rv.y);
                }
                if (r1 < M) {
                    float2 rv = *(const float2*)&res[(size_t)r1 * N + c];
                    *(float2*)&out[(size_t)r1 * N + c] = make_float2(v2 + rv.x, v3 + rv.y);
                }
            } else {
                __half* out = (__half*)outp;
                v0 = 0.5f * v0 * (1.0f + erff(v0 * 0.70710678118654752f));
                v1 = 0.5f * v1 * (1.0f + erff(v1 * 0.70710678118654752f));
                v2 = 0.5f * v2 * (1.0f + erff(v2 * 0.70710678118654752f));
                v3 = 0.5f * v3 * (1.0f + erff(v3 * 0.70710678118654752f));
                if (r0 < M) *(__half2*)&out[(size_t)r0 * N + c] = __floats2half2_rn(v0, v1);
                if (r1 < M) *(__half2*)&out[(size_t)r1 * N + c] = __floats2half2_rn(v2, v3);
            }
        }
    }
}

// ---------------- fp16 flash attention (ldmatrix fragments) ------------------------
// smem halfs: Qs[128][72] | Ps[128][72] | Ks[2][64][72] | Vt[2][64][72]
#define OQ 0
#define OP (128 * PH)
#define OK (256 * PH)
#define OV (OK + 2 * 64 * PH)
#define ATT_SMEM ((OV + 2 * 64 * PH) * 2)
#define NKT 10

__global__ void __launch_bounds__(256) attn_tc(
    const __half* __restrict__ qk, const __half* __restrict__ vt,
    __half* __restrict__ outa)
{
    extern __shared__ __align__(16) char sm[];
    const uint32_t sbase = smem_u32(sm);

    const int qt = blockIdx.x;
    const int h  = blockIdx.y;
    const int b  = blockIdx.z;
    const int tid  = threadIdx.x;
    const int wid  = tid >> 5;
    const int lane = tid & 31;
    const int g = lane >> 2, t = lane & 3;
    const int wr = wid * 16;
    const size_t browbase = (size_t)b * SEQ;
    const __half* qbase = qk + browbase * QKW + h * DHEAD;
    const __half* vbase = vt + (size_t)(b * NHEAD + h) * DHEAD * SEQP;

    const int l15 = lane & 15;
    const int lhi = lane >> 4;
    const uint32_t aoff = (uint32_t)(((wr + l15) * PH + lhi * 8) * 2);
    const int l7 = lane & 7;
    const int q2 = lane >> 3;
    const uint32_t boff = (uint32_t)((((q2 >> 1) * 8 + l7) * PH + (q2 & 1) * 8) * 2);

    // ---- Q tile (128 x 64 halfs) ----
    #pragma unroll
    for (int i = 0; i < 4; ++i) {
        int f = i * 256 + tid;
        int r = f >> 3, q = f & 7;
        int n = qt * 128 + r;
        int sz = (n < SEQ) ? 16 : 0;
        if (n >= SEQ) n = SEQ - 1;
        cp_async16z(sbase + (uint32_t)((OQ + r * PH + q * 8) * 2),
                    qbase + (size_t)n * QKW + q * 8, sz);
    }
    // ---- K/V tile 0 into buf 0 ----
    #pragma unroll
    for (int i = 0; i < 2; ++i) {
        int f = i * 256 + tid;
        int r = f >> 3, q = f & 7;
        cp_async16(sbase + (uint32_t)((OK + r * PH + q * 8) * 2),
                   qbase + (size_t)r * QKW + CDIM + q * 8);
        cp_async16(sbase + (uint32_t)((OV + r * PH + q * 8) * 2),
                   vbase + (size_t)r * SEQP + q * 8);
    }
    asm volatile("cp.async.commit_group;" ::: "memory");

    float oacc[8][4];
    #pragma unroll
    for (int nt = 0; nt < 8; ++nt)
        #pragma unroll
        for (int j = 0; j < 4; ++j) oacc[nt][j] = 0.f;
    float m0 = -INFINITY, m1 = -INFINITY, l0 = 0.f, l1 = 0.f;

    for (int kt = 0; kt < NKT; ++kt) {
        const int buf = kt & 1;
        if (kt > 0) __syncthreads();
        if (kt + 1 < NKT) {
            const int nbuf = (kt + 1) & 1;
            #pragma unroll
            for (int i = 0; i < 2; ++i) {
                int f = i * 256 + tid;
                int r = f >> 3, q = f & 7;
                int kk = (kt + 1) * 64 + r;
                int sz = (kk < SEQ) ? 16 : 0;
                if (kk >= SEQ) kk = SEQ - 1;
                cp_async16z(sbase + (uint32_t)((OK + (nbuf * 64 + r) * PH + q * 8) * 2),
                            qbase + (size_t)kk * QKW + CDIM + q * 8, sz);
                cp_async16(sbase + (uint32_t)((OV + (nbuf * 64 + r) * PH + q * 8) * 2),
                           vbase + (size_t)r * SEQP + (kt + 1) * 64 + q * 8);
            }
        }
        asm volatile("cp.async.commit_group;" ::: "memory");
        asm volatile("cp.async.wait_group 1;" ::: "memory");
        __syncthreads();

        const uint32_t Qu = sbase + OQ * 2;
        const uint32_t Ku = sbase + (OK + buf * 64 * PH) * 2;
        const uint32_t Vu = sbase + (OV + buf * 64 * PH) * 2;
        const uint32_t Pu = sbase + OP * 2;
        uint32_t* Ps2 = (uint32_t*)sm + OP / 2;

        // ---- S = Q @ K^T ----
        float sacc[8][4];
        #pragma unroll
        for (int nt = 0; nt < 8; ++nt)
            #pragma unroll
            for (int j = 0; j < 4; ++j) sacc[nt][j] = 0.f;

        #pragma unroll
        for (int k16 = 0; k16 < 4; ++k16) {
            uint32_t a0, a1, a2, a3;
            ldsm_x4(a0, a1, a2, a3, Qu + aoff + (uint32_t)(k16 * 32));
            #pragma unroll
            for (int ntp = 0; ntp < 4; ++ntp) {
                uint32_t b0, b1, b2, b3;
                ldsm_x4(b0, b1, b2, b3,
                        Ku + boff + (uint32_t)(ntp * 16 * PH * 2 + k16 * 32));
                mma_f16(sacc[2 * ntp],     a0, a1, a2, a3, b0, b1);
                mma_f16(sacc[2 * ntp + 1], a0, a1, a2, a3, b2, b3);
            }
        }

        // ---- scale + mask ----
        const int kb0 = kt * 64;
        #pragma unroll
        for (int nt = 0; nt < 8; ++nt) {
            const int c0 = kb0 + nt * 8 + 2 * t;
            sacc[nt][0] = (c0     < SEQ) ? sacc[nt][0] * 0.125f : -INFINITY;
            sacc[nt][1] = (c0 + 1 < SEQ) ? sacc[nt][1] * 0.125f : -INFINITY;
            sacc[nt][2] = (c0     < SEQ) ? sacc[nt][2] * 0.125f : -INFINITY;
            sacc[nt][3] = (c0 + 1 < SEQ) ? sacc[nt][3] * 0.125f : -INFINITY;
        }

        // ---- online softmax (rows g, g+8) ----
        float mt0 = -INFINITY, mt1 = -INFINITY;
        #pragma unroll
        for (int nt = 0; nt < 8; ++nt) {
            mt0 = fmaxf(mt0, fmaxf(sacc[nt][0], sacc[nt][1]));
            mt1 = fmaxf(mt1, fmaxf(sacc[nt][2], sacc[nt][3]));
        }
        mt0 = fmaxf(mt0, __shfl_xor_sync(0xffffffffu, mt0, 1));
        mt0 = fmaxf(mt0, __shfl_xor_sync(0xffffffffu, mt0, 2));
        mt1 = fmaxf(mt1, __shfl_xor_sync(0xffffffffu, mt1, 1));
        mt1 = fmaxf(mt1, __shfl_xor_sync(0xffffffffu, mt1, 2));

        const float mn0 = fmaxf(m0, mt0), mn1 = fmaxf(m1, mt1);
        const float corr0 = expf(m0 - mn0), corr1 = expf(m1 - mn1);
        float ps0 = 0.f, ps1 = 0.f;
        #pragma unroll
        for (int nt = 0; nt < 8; ++nt) {
            float p0 = expf(sacc[nt][0] - mn0);
            float p1 = expf(sacc[nt][1] - mn0);
            float p2 = expf(sacc[nt][2] - mn1);
            float p3 = expf(sacc[nt][3] - mn1);
            ps0 += p0 + p1; ps1 += p2 + p3;
            __half2 h01 = __floats2half2_rn(p0, p1);
            __half2 h23 = __floats2half2_rn(p2, p3);
            Ps2[(wr + g) * (PH / 2) + nt * 4 + t]     = *(uint32_t*)&h01;
            Ps2[(wr + g + 8) * (PH / 2) + nt * 4 + t] = *(uint32_t*)&h23;
        }
        ps0 += __shfl_xor_sync(0xffffffffu, ps0, 1);
        ps0 += __shfl_xor_sync(0xffffffffu, ps0, 2);
        ps1 += __shfl_xor_sync(0xffffffffu, ps1, 1);
        ps1 += __shfl_xor_sync(0xffffffffu, ps1, 2);
        l0 = l0 * corr0 + ps0;  m0 = mn0;
        l1 = l1 * corr1 + ps1;  m1 = mn1;
        #pragma unroll
        for (int nt = 0; nt < 8; ++nt) {
            oacc[nt][0] *= corr0; oacc[nt][1] *= corr0;
            oacc[nt][2] *= corr1; oacc[nt][3] *= corr1;
        }
        __syncwarp();

        // ---- O += P @ Vt ----
        #pragma unroll
        for (int k16 = 0; k16 < 4; ++k16) {
            uint32_t a0, a1, a2, a3;
            ldsm_x4(a0, a1, a2, a3, Pu + aoff + (uint32_t)(k16 * 32));
            #pragma unroll
            for (int ntp = 0; ntp < 4; ++ntp) {
                uint32_t b0, b1, b2, b3;
                ldsm_x4(b0, b1, b2, b3,
                        Vu + boff + (uint32_t)(ntp * 16 * PH * 2 + k16 * 32));
                mma_f16(oacc[2 * ntp],     a0, a1, a2, a3, b0, b1);
                mma_f16(oacc[2 * ntp + 1], a0, a1, a2, a3, b2, b3);
            }
        }
    }

    // ---- write O (half; feeds proj GEMM) ----
    const float inv0 = 1.0f / l0, inv1 = 1.0f / l1;
    const int r0 = qt * 128 + wr + g;
    const int r1 = r0 + 8;
    #pragma unroll
    for (int nt = 0; nt < 8; ++nt) {
        const int col = h * DHEAD + nt * 8 + 2 * t;
        if (r0 < SEQ)
            *(__half2*)&outa[(browbase + r0) * CDIM + col] =
                __floats2half2_rn(oacc[nt][0] * inv0, oacc[nt][1] * inv0);
        if (r1 < SEQ)
            *(__half2*)&outa[(browbase + r1) * CDIM + col] =
                __floats2half2_rn(oacc[nt][2] * inv1, oacc[nt][3] * inv1);
    }
}

// ---------------- launcher ----------------
extern "C" void kernel_launch(void* const* d_in, const int* in_sizes, int n_in,
                              void* d_out, int out_size)
{
    const float* x      = (const float*)d_in[0];
    const float* ln1_g  = (const float*)d_in[1];
    const float* ln1_b  = (const float*)d_in[2];
    const float* ln2_g  = (const float*)d_in[3];
    const float* ln2_b  = (const float*)d_in[4];
    const float* qkv_w  = (const float*)d_in[5];
    const float* qkv_b  = (const float*)d_in[6];
    const float* proj_w = (const float*)d_in[7];
    const float* proj_b = (const float*)d_in[8];
    const float* fc1_w  = (const float*)d_in[9];
    const float* fc1_b  = (const float*)d_in[10];
    const float* fc2_w  = (const float*)d_in[11];
    const float* fc2_b  = (const float*)d_in[12];
    float* out = (float*)d_out;

    __half *h, *qk, *vt, *attn, *ff, *wtq, *wtp, *wt1, *wt2;
    float *x1;
    cudaGetSymbolAddress((void**)&h,    g_h);
    cudaGetSymbolAddress((void**)&qk,   g_qk);
    cudaGetSymbolAddress((void**)&vt,   g_vt);
    cudaGetSymbolAddress((void**)&attn, g_attn);
    cudaGetSymbolAddress((void**)&x1,   g_x1);
    cudaGetSymbolAddress((void**)&ff,   g_ff);
    cudaGetSymbolAddress((void**)&wtq,  g_wt_qkv);
    cudaGetSymbolAddress((void**)&wtp,  g_wt_proj);
    cudaGetSymbolAddress((void**)&wt1,  g_wt_fc1);
    cudaGetSymbolAddress((void**)&wt2,  g_wt_fc2);

    cudaFuncSetAttribute(gemm_mma<0>, cudaFuncAttributeMaxDynamicSharedMemorySize, SMEM_DYN);
    cudaFuncSetAttribute(gemm_mma<1>, cudaFuncAttributeMaxDynamicSharedMemorySize, SMEM_DYN);
    cudaFuncSetAttribute(gemm_mma<2>, cudaFuncAttributeMaxDynamicSharedMemorySize, SMEM_DYN);
    cudaFuncSetAttribute(attn_tc,     cudaFuncAttributeMaxDynamicSharedMemorySize, ATT_SMEM);

    const int M  = MROWS;
    const int gy = (M + GBM - 1) / GBM;     // 145
    dim3 tb(32, 8);

    transpose_w<<<dim3(CDIM / 32, C3 / 32),   tb>>>(qkv_w,  wtq, CDIM, C3);
    transpose_w<<<dim3(CDIM / 32, CDIM / 32), tb>>>(proj_w, wtp, CDIM, CDIM);
    transpose_w<<<dim3(CDIM / 32, DFF / 32),  tb>>>(fc1_w,  wt1, CDIM, DFF);
    transpose_w<<<dim3(DFF / 32, CDIM / 32),  tb>>>(fc2_w,  wt2, DFF, CDIM);
    zero_vt<<<BATCH * NHEAD, 256>>>();

    // 1. LN1
    ln_kernel<<<M, 256>>>(x, ln1_g, ln1_b, h);
    // 2. QKV (Q,K natural; V transposed)
    gemm_mma<0><<<dim3(C3 / GBN, gy), 256, SMEM_DYN>>>(h, wtq, qkv_b, nullptr, qk, vt, M, CDIM, C3);
    // 3. attention
    attn_tc<<<dim3((SEQ + 127) / 128, NHEAD, BATCH), 256, ATT_SMEM>>>(qk, vt, attn);
    // 4. x1 = x + attn @ proj_w + proj_b
    gemm_mma<1><<<dim3(CDIM / GBN, gy), 256, SMEM_DYN>>>(attn, wtp, proj_b, x, x1, nullptr, M, CDIM, CDIM);
    // 5. LN2
    ln_kernel<<<M, 256>>>(x1, ln2_g, ln2_b, h);
    // 6. ff = gelu(h @ fc1_w + fc1_b)
    gemm_mma<2><<<dim3(DFF / GBN, gy), 256, SMEM_DYN>>>(h, wt1, fc1_b, nullptr, ff, nullptr, M, CDIM, DFF);
    // 7. out = x1 + ff @ fc2_w + fc2_b
    gemm_mma<1><<<dim3(CDIM / GBN, gy), 256, SMEM_DYN>>>(ff, wt2, fc2_b, x1, out, nullptr, M, DFF, CDIM);
}

// round 9
// speedup vs baseline: 5.4353x; 1.0198x over previous
#include <cuda_runtime.h>
#include <cuda_fp16.h>
#include <cstdint>
#include <math.h>

// ---------------- problem constants ----------------
#define BATCH 32
#define SEQ   577
#define CDIM  768
#define NHEAD 12
#define DHEAD 64
#define DFF   3072
#define MROWS (BATCH*SEQ)          // 18464
#define C3    2304
#define QKW   1536                 // row width of g_qk (Q|K)
#define SEQP  640                  // padded seq for transposed V

// ---------------- scratch (device globals; no allocation) ----------------
__device__ __align__(256) __half g_h   [(size_t)MROWS * CDIM];
__device__ __align__(256) __half g_qk  [(size_t)MROWS * QKW];
__device__ __align__(256) __half g_vt  [(size_t)BATCH * NHEAD * DHEAD * SEQP];
__device__ __align__(256) __half g_attn[(size_t)MROWS * CDIM];
__device__ __align__(256) float  g_x1  [(size_t)MROWS * CDIM];
__device__ __align__(256) __half g_ff  [(size_t)MROWS * DFF];
__device__ __align__(256) __half g_wt_qkv [(size_t)C3   * CDIM];
__device__ __align__(256) __half g_wt_proj[(size_t)CDIM * CDIM];
__device__ __align__(256) __half g_wt_fc1 [(size_t)DFF  * CDIM];
__device__ __align__(256) __half g_wt_fc2 [(size_t)CDIM * DFF];

// ---------------- helpers ----------------
static __device__ __forceinline__ uint32_t smem_u32(const void* p) {
    uint32_t a;
    asm("{ .reg .u64 t; cvta.to.shared.u64 t, %1; cvt.u32.u64 %0, t; }" : "=r"(a) : "l"(p));
    return a;
}
static __device__ __forceinline__ void cp_async16(uint32_t dst, const void* src) {
    asm volatile("cp.async.cg.shared.global [%0], [%1], 16;" :: "r"(dst), "l"(src));
}
static __device__ __forceinline__ void cp_async16z(uint32_t dst, const void* src, int sz) {
    asm volatile("cp.async.cg.shared.global [%0], [%1], 16, %2;" :: "r"(dst), "l"(src), "r"(sz));
}
static __device__ __forceinline__ void mma_f16(
    float* d, uint32_t a0, uint32_t a1, uint32_t a2, uint32_t a3,
    uint32_t b0, uint32_t b1)
{
    asm volatile(
        "mma.sync.aligned.m16n8k16.row.col.f32.f16.f16.f32 "
        "{%0,%1,%2,%3}, {%4,%5,%6,%7}, {%8,%9}, {%0,%1,%2,%3};"
        : "+f"(d[0]), "+f"(d[1]), "+f"(d[2]), "+f"(d[3])
        : "r"(a0), "r"(a1), "r"(a2), "r"(a3), "r"(b0), "r"(b1));
}
static __device__ __forceinline__ void ldsm_x4(
    uint32_t& r0, uint32_t& r1, uint32_t& r2, uint32_t& r3, uint32_t addr)
{
    asm volatile("ldmatrix.sync.aligned.m8n8.x4.shared.b16 {%0,%1,%2,%3}, [%4];"
                 : "=r"(r0), "=r"(r1), "=r"(r2), "=r"(r3) : "r"(addr));
}

// ---------------- LayerNorm (fp32 in, half out) ----------------
__global__ void __launch_bounds__(256) ln_kernel(
    const float* __restrict__ x, const float* __restrict__ g,
    const float* __restrict__ b, __half* __restrict__ out)
{
    __shared__ float red[8];
    const int row = blockIdx.x;
    const int tid = threadIdx.x;
    const float* xr = x + (size_t)row * CDIM;

    float v0 = xr[tid], v1 = xr[tid + 256], v2 = xr[tid + 512];

    float s = v0 + v1 + v2;
    #pragma unroll
    for (int o = 16; o > 0; o >>= 1) s += __shfl_xor_sync(0xffffffffu, s, o);
    if ((tid & 31) == 0) red[tid >> 5] = s;
    __syncthreads();
    if (tid == 0) {
        float t = 0.f;
        #pragma unroll
        for (int w = 0; w < 8; ++w) t += red[w];
        red[0] = t;
    }
    __syncthreads();
    const float mean = red[0] * (1.0f / CDIM);
    __syncthreads();

    float d0 = v0 - mean, d1 = v1 - mean, d2 = v2 - mean;
    float sq = d0 * d0 + d1 * d1 + d2 * d2;
    #pragma unroll
    for (int o = 16; o > 0; o >>= 1) sq += __shfl_xor_sync(0xffffffffu, sq, o);
    if ((tid & 31) == 0) red[tid >> 5] = sq;
    __syncthreads();
    if (tid == 0) {
        float t = 0.f;
        #pragma unroll
        for (int w = 0; w < 8; ++w) t += red[w];
        red[0] = t;
    }
    __syncthreads();
    const float var = red[0] * (1.0f / CDIM);
    const float rstd = rsqrtf(var + 1e-5f);

    __half* outr = out + (size_t)row * CDIM;
    outr[tid]       = __float2half_rn(d0 * rstd * g[tid]       + b[tid]);
    outr[tid + 256] = __float2half_rn(d1 * rstd * g[tid + 256] + b[tid + 256]);
    outr[tid + 512] = __float2half_rn(d2 * rstd * g[tid + 512] + b[tid + 512]);
}

// ---------------- merged prep: 4 weight transposes + V-tail zero (one launch) ------
// block layout: [0,1728) qkv | [1728,2304) proj | [2304,4608) fc1 | [4608,6912) fc2
//               [6912,7296) zero g_vt tail
__global__ void __launch_bounds__(256) prep_kernel(
    const float* __restrict__ qkv_w, const float* __restrict__ proj_w,
    const float* __restrict__ fc1_w, const float* __restrict__ fc2_w)
{
    __shared__ float tb[32][33];
    int bid = blockIdx.x;
    const float* W; __half* Wt; int K, N;

    if (bid >= 6912) {
        // zero tail of transposed V (n in [512,640))
        __half* vt = g_vt + (size_t)(bid - 6912) * DHEAD * SEQP;
        const uint4 z = make_uint4(0u, 0u, 0u, 0u);
        int tid = threadIdx.y * 32 + threadIdx.x;
        #pragma unroll
        for (int i = 0; i < 4; ++i) {
            int f = i * 256 + tid;
            int d = f >> 4, u = f & 15;
            *(uint4*)(vt + (size_t)d * SEQP + 512 + u * 8) = z;
        }
        return;
    }
    if (bid < 1728)      { W = qkv_w;  Wt = g_wt_qkv;  K = CDIM; N = C3;  }
    else if (bid < 2304) { W = proj_w; Wt = g_wt_proj; K = CDIM; N = CDIM; bid -= 1728; }
    else if (bid < 4608) { W = fc1_w;  Wt = g_wt_fc1;  K = CDIM; N = DFF;  bid -= 2304; }
    else                 { W = fc2_w;  Wt = g_wt_fc2;  K = DFF;  N = CDIM; bid -= 4608; }

    const int nbx = K >> 5;
    const int k0 = (bid % nbx) * 32, n0 = (bid / nbx) * 32;
    #pragma unroll
    for (int i = threadIdx.y; i < 32; i += 8)
        tb[i][threadIdx.x] = W[(size_t)(k0 + i) * N + n0 + threadIdx.x];
    __syncthreads();
    #pragma unroll
    for (int i = threadIdx.y; i < 32; i += 8)
        Wt[(size_t)(n0 + i) * K + k0 + threadIdx.x] = __float2half_rn(tb[threadIdx.x][i]);
}

// ---------------- fp16 HMMA GEMM (ldmatrix fragments) ------------------------------
// EPI 0: qkv (Q,K -> g_qk half; V -> g_vt transposed half)
// EPI 1: bias + residual(f32) -> f32
// EPI 2: bias + exact GELU -> half
#define NSTAGE 4
#define GBM 128
#define GBN 256
#define PH 72                              // halfs per smem row (64 + 8 pad); 144B stride
#define STG_BYTES ((128 + 256) * PH * 2)   // 55296
#define SMEM_DYN (NSTAGE * STG_BYTES)      // 221184

__device__ __forceinline__ void load_stage(
    uint32_t sb, const __half* __restrict__ A, const __half* __restrict__ Wt,
    int bm, int bn, int M, int K, int kc, int tid)
{
    #pragma unroll
    for (int i = 0; i < 4; ++i) {
        int f = i * 256 + tid;
        int r = f >> 3, q = f & 7;
        int rr = bm + r;
        int sz = (rr < M) ? 16 : 0;
        if (rr >= M) rr = M - 1;
        cp_async16z(sb + (uint32_t)(r * (PH * 2) + q * 16),
                    A + (size_t)rr * K + kc + q * 8, sz);
    }
    const uint32_t bb = sb + 128 * (PH * 2);
    #pragma unroll
    for (int i = 0; i < 8; ++i) {
        int f = i * 256 + tid;
        int r = f >> 3, q = f & 7;
        cp_async16(bb + (uint32_t)(r * (PH * 2) + q * 16),
                   Wt + (size_t)(bn + r) * K + kc + q * 8);
    }
    asm volatile("cp.async.commit_group;" ::: "memory");
}

template <int EPI>
__global__ void __launch_bounds__(256, 1) gemm_mma(
    const __half* __restrict__ A, const __half* __restrict__ Wt,
    const float* __restrict__ bias, const float* __restrict__ res,
    void* __restrict__ outp, __half* __restrict__ vt,
    int M, int K, int N)
{
    extern __shared__ __align__(16) char dsm[];
    const uint32_t sbase = smem_u32(dsm);

    const int tid  = threadIdx.x;
    const int wid  = tid >> 5;
    const int lane = tid & 31;
    const int g = lane >> 2, t = lane & 3;
    const int bm = blockIdx.y * GBM;
    const int bn = blockIdx.x * GBN;
    const int wm = (wid >> 2) * 64;
    const int wn = (wid & 3) * 64;

    // ldmatrix per-lane address components
    const int l15 = lane & 15;
    const int lhi = lane >> 4;                 // 0/1 -> k half
    const uint32_t aoff = (uint32_t)(((wm + l15) * PH + lhi * 8) * 2);
    const int l7 = lane & 7;
    const int q2 = lane >> 3;                  // 0..3
    const uint32_t boff = (uint32_t)(((wn + (q2 >> 1) * 8 + l7) * PH + (q2 & 1) * 8) * 2);

    float acc[4][8][4];
    #pragma unroll
    for (int mt = 0; mt < 4; ++mt)
        #pragma unroll
        for (int nt = 0; nt < 8; ++nt)
            #pragma unroll
            for (int j = 0; j < 4; ++j) acc[mt][nt][j] = 0.f;

    const int KT = K >> 6;   // 64-half K chunks

    for (int c = 0; c < NSTAGE - 1; ++c)
        load_stage(sbase + (uint32_t)(c * STG_BYTES), A, Wt, bm, bn, M, K, c * 64, tid);

    for (int kt = 0; kt < KT; ++kt) {
        asm volatile("cp.async.wait_group %0;" :: "n"(NSTAGE - 2) : "memory");
        __syncthreads();

        const int kn = kt + NSTAGE - 1;
        if (kn < KT)
            load_stage(sbase + (uint32_t)((kn % NSTAGE) * STG_BYTES), A, Wt, bm, bn, M, K, kn * 64, tid);
        else
            asm volatile("cp.async.commit_group;" ::: "memory");

        const uint32_t sA_u = sbase + (uint32_t)((kt % NSTAGE) * STG_BYTES);
        const uint32_t sB_u = sA_u + 128 * (PH * 2);

        #pragma unroll
        for (int k16 = 0; k16 < 4; ++k16) {
            uint32_t bf[8][2];
            #pragma unroll
            for (int ntp = 0; ntp < 4; ++ntp) {
                uint32_t r0, r1, r2, r3;
                ldsm_x4(r0, r1, r2, r3,
                        sB_u + boff + (uint32_t)(ntp * 16 * PH * 2 + k16 * 32));
                bf[2 * ntp][0] = r0; bf[2 * ntp][1] = r1;
                bf[2 * ntp + 1][0] = r2; bf[2 * ntp + 1][1] = r3;
            }
            #pragma unroll
            for (int mt = 0; mt < 4; ++mt) {
                uint32_t a0, a1, a2, a3;
                ldsm_x4(a0, a1, a2, a3,
                        sA_u + aoff + (uint32_t)(mt * 16 * PH * 2 + k16 * 32));
                #pragma unroll
                for (int nt = 0; nt < 8; ++nt)
                    mma_f16(acc[mt][nt], a0, a1, a2, a3, bf[nt][0], bf[nt][1]);
            }
        }
    }

    // ---- epilogue ----
    #pragma unroll
    for (int nt = 0; nt < 8; ++nt) {
        const int c = bn + wn + nt * 8 + 2 * t;
        const float2 bia = *(const float2*)&bias[c];
        #pragma unroll
        for (int mt = 0; mt < 4; ++mt) {
            const int r0 = bm + wm + mt * 16 + g;
            const int r1 = r0 + 8;
            float v0 = acc[mt][nt][0] + bia.x;
            float v1 = acc[mt][nt][1] + bia.y;
            float v2 = acc[mt][nt][2] + bia.x;
            float v3 = acc[mt][nt][3] + bia.y;

            if (EPI == 0) {
                if (c < QKW) {
                    __half* qk = (__half*)outp;
                    if (r0 < M) *(__half2*)&qk[(size_t)r0 * QKW + c] = __floats2half2_rn(v0, v1);
                    if (r1 < M) *(__half2*)&qk[(size_t)r1 * QKW + c] = __floats2half2_rn(v2, v3);
                } else {
                    const int cc = c - QKW;
                    const int hh = cc >> 6, dd = cc & 63;
                    if (r0 < M) {
                        int bb = r0 / SEQ, n = r0 - bb * SEQ;
                        __half* p = vt + ((size_t)(bb * NHEAD + hh) * DHEAD + dd) * SEQP + n;
                        p[0]    = __float2half_rn(v0);
                        p[SEQP] = __float2half_rn(v1);
                    }
                    if (r1 < M) {
                        int bb = r1 / SEQ, n = r1 - bb * SEQ;
                        __half* p = vt + ((size_t)(bb * NHEAD + hh) * DHEAD + dd) * SEQP + n;
                        p[0]    = __float2half_rn(v2);
                        p[SEQP] = __float2half_rn(v3);
                    }
                }
            } else if (EPI == 1) {
                float* out = (float*)outp;
                if (r0 < M) {
                    float2 rv = *(const float2*)&res[(size_t)r0 * N + c];
                    *(float2*)&out[(size_t)r0 * N + c] = make_float2(v0 + rv.x, v1 + rv.y);
                }
                if (r1 < M) {
                    float2 rv = *(const float2*)&res[(size_t)r1 * N + c];
                    *(float2*)&out[(size_t)r1 * N + c] = make_float2(v2 + rv.x, v3 + rv.y);
                }
            } else {
                __half* out = (__half*)outp;
                v0 = 0.5f * v0 * (1.0f + erff(v0 * 0.70710678118654752f));
                v1 = 0.5f * v1 * (1.0f + erff(v1 * 0.70710678118654752f));
                v2 = 0.5f * v2 * (1.0f + erff(v2 * 0.70710678118654752f));
                v3 = 0.5f * v3 * (1.0f + erff(v3 * 0.70710678118654752f));
                if (r0 < M) *(__half2*)&out[(size_t)r0 * N + c] = __floats2half2_rn(v0, v1);
                if (r1 < M) *(__half2*)&out[(size_t)r1 * N + c] = __floats2half2_rn(v2, v3);
            }
        }
    }
}

// ---------------- fp16 flash attention (ldmatrix fragments, __expf softmax) --------
// smem halfs: Qs[128][72] | Ps[128][72] | Ks[2][64][72] | Vt[2][64][72]
#define OQ 0
#define OP (128 * PH)
#define OK (256 * PH)
#define OV (OK + 2 * 64 * PH)
#define ATT_SMEM ((OV + 2 * 64 * PH) * 2)
#define NKT 10

__global__ void __launch_bounds__(256) attn_tc(
    const __half* __restrict__ qk, const __half* __restrict__ vt,
    __half* __restrict__ outa)
{
    extern __shared__ __align__(16) char sm[];
    const uint32_t sbase = smem_u32(sm);

    const int qt = blockIdx.x;
    const int h  = blockIdx.y;
    const int b  = blockIdx.z;
    const int tid  = threadIdx.x;
    const int wid  = tid >> 5;
    const int lane = tid & 31;
    const int g = lane >> 2, t = lane & 3;
    const int wr = wid * 16;
    const size_t browbase = (size_t)b * SEQ;
    const __half* qbase = qk + browbase * QKW + h * DHEAD;
    const __half* vbase = vt + (size_t)(b * NHEAD + h) * DHEAD * SEQP;

    const int l15 = lane & 15;
    const int lhi = lane >> 4;
    const uint32_t aoff = (uint32_t)(((wr + l15) * PH + lhi * 8) * 2);
    const int l7 = lane & 7;
    const int q2 = lane >> 3;
    const uint32_t boff = (uint32_t)((((q2 >> 1) * 8 + l7) * PH + (q2 & 1) * 8) * 2);

    // ---- Q tile (128 x 64 halfs) ----
    #pragma unroll
    for (int i = 0; i < 4; ++i) {
        int f = i * 256 + tid;
        int r = f >> 3, q = f & 7;
        int n = qt * 128 + r;
        int sz = (n < SEQ) ? 16 : 0;
        if (n >= SEQ) n = SEQ - 1;
        cp_async16z(sbase + (uint32_t)((OQ + r * PH + q * 8) * 2),
                    qbase + (size_t)n * QKW + q * 8, sz);
    }
    // ---- K/V tile 0 into buf 0 ----
    #pragma unroll
    for (int i = 0; i < 2; ++i) {
        int f = i * 256 + tid;
        int r = f >> 3, q = f & 7;
        cp_async16(sbase + (uint32_t)((OK + r * PH + q * 8) * 2),
                   qbase + (size_t)r * QKW + CDIM + q * 8);
        cp_async16(sbase + (uint32_t)((OV + r * PH + q * 8) * 2),
                   vbase + (size_t)r * SEQP + q * 8);
    }
    asm volatile("cp.async.commit_group;" ::: "memory");

    float oacc[8][4];
    #pragma unroll
    for (int nt = 0; nt < 8; ++nt)
        #pragma unroll
        for (int j = 0; j < 4; ++j) oacc[nt][j] = 0.f;
    float m0 = -INFINITY, m1 = -INFINITY, l0 = 0.f, l1 = 0.f;

    for (int kt = 0; kt < NKT; ++kt) {
        const int buf = kt & 1;
        if (kt > 0) __syncthreads();
        if (kt + 1 < NKT) {
            const int nbuf = (kt + 1) & 1;
            #pragma unroll
            for (int i = 0; i < 2; ++i) {
                int f = i * 256 + tid;
                int r = f >> 3, q = f & 7;
                int kk = (kt + 1) * 64 + r;
                int sz = (kk < SEQ) ? 16 : 0;
                if (kk >= SEQ) kk = SEQ - 1;
                cp_async16z(sbase + (uint32_t)((OK + (nbuf * 64 + r) * PH + q * 8) * 2),
                            qbase + (size_t)kk * QKW + CDIM + q * 8, sz);
                cp_async16(sbase + (uint32_t)((OV + (nbuf * 64 + r) * PH + q * 8) * 2),
                           vbase + (size_t)r * SEQP + (kt + 1) * 64 + q * 8);
            }
        }
        asm volatile("cp.async.commit_group;" ::: "memory");
        asm volatile("cp.async.wait_group 1;" ::: "memory");
        __syncthreads();

        const uint32_t Qu = sbase + OQ * 2;
        const uint32_t Ku = sbase + (OK + buf * 64 * PH) * 2;
        const uint32_t Vu = sbase + (OV + buf * 64 * PH) * 2;
        const uint32_t Pu = sbase + OP * 2;
        uint32_t* Ps2 = (uint32_t*)sm + OP / 2;

        // ---- S = Q @ K^T ----
        float sacc[8][4];
        #pragma unroll
        for (int nt = 0; nt < 8; ++nt)
            #pragma unroll
            for (int j = 0; j < 4; ++j) sacc[nt][j] = 0.f;

        #pragma unroll
        for (int k16 = 0; k16 < 4; ++k16) {
            uint32_t a0, a1, a2, a3;
            ldsm_x4(a0, a1, a2, a3, Qu + aoff + (uint32_t)(k16 * 32));
            #pragma unroll
            for (int ntp = 0; ntp < 4; ++ntp) {
                uint32_t b0, b1, b2, b3;
                ldsm_x4(b0, b1, b2, b3,
                        Ku + boff + (uint32_t)(ntp * 16 * PH * 2 + k16 * 32));
                mma_f16(sacc[2 * ntp],     a0, a1, a2, a3, b0, b1);
                mma_f16(sacc[2 * ntp + 1], a0, a1, a2, a3, b2, b3);
            }
        }

        // ---- scale + mask ----
        const int kb0 = kt * 64;
        #pragma unroll
        for (int nt = 0; nt < 8; ++nt) {
            const int c0 = kb0 + nt * 8 + 2 * t;
            sacc[nt][0] = (c0     < SEQ) ? sacc[nt][0] * 0.125f : -INFINITY;
            sacc[nt][1] = (c0 + 1 < SEQ) ? sacc[nt][1] * 0.125f : -INFINITY;
            sacc[nt][2] = (c0     < SEQ) ? sacc[nt][2] * 0.125f : -INFINITY;
            sacc[nt][3] = (c0 + 1 < SEQ) ? sacc[nt][3] * 0.125f : -INFINITY;
        }

        // ---- online softmax (rows g, g+8), __expf fast path ----
        float mt0 = -INFINITY, mt1 = -INFINITY;
        #pragma unroll
        for (int nt = 0; nt < 8; ++nt) {
            mt0 = fmaxf(mt0, fmaxf(sacc[nt][0], sacc[nt][1]));
            mt1 = fmaxf(mt1, fmaxf(sacc[nt][2], sacc[nt][3]));
        }
        mt0 = fmaxf(mt0, __shfl_xor_sync(0xffffffffu, mt0, 1));
        mt0 = fmaxf(mt0, __shfl_xor_sync(0xffffffffu, mt0, 2));
        mt1 = fmaxf(mt1, __shfl_xor_sync(0xffffffffu, mt1, 1));
        mt1 = fmaxf(mt1, __shfl_xor_sync(0xffffffffu, mt1, 2));

        const float mn0 = fmaxf(m0, mt0), mn1 = fmaxf(m1, mt1);
        const float corr0 = __expf(m0 - mn0), corr1 = __expf(m1 - mn1);
        float ps0 = 0.f, ps1 = 0.f;
        #pragma unroll
        for (int nt = 0; nt < 8; ++nt) {
            float p0 = __expf(sacc[nt][0] - mn0);
            float p1 = __expf(sacc[nt][1] - mn0);
            float p2 = __expf(sacc[nt][2] - mn1);
            float p3 = __expf(sacc[nt][3] - mn1);
            ps0 += p0 + p1; ps1 += p2 + p3;
            __half2 h01 = __floats2half2_rn(p0, p1);
            __half2 h23 = __floats2half2_rn(p2, p3);
            Ps2[(wr + g) * (PH / 2) + nt * 4 + t]     = *(uint32_t*)&h01;
            Ps2[(wr + g + 8) * (PH / 2) + nt * 4 + t] = *(uint32_t*)&h23;
        }
        ps0 += __shfl_xor_sync(0xffffffffu, ps0, 1);
        ps0 += __shfl_xor_sync(0xffffffffu, ps0, 2);
        ps1 += __shfl_xor_sync(0xffffffffu, ps1, 1);
        ps1 += __shfl_xor_sync(0xffffffffu, ps1, 2);
        l0 = l0 * corr0 + ps0;  m0 = mn0;
        l1 = l1 * corr1 + ps1;  m1 = mn1;
        #pragma unroll
        for (int nt = 0; nt < 8; ++nt) {
            oacc[nt][0] *= corr0; oacc[nt][1] *= corr0;
            oacc[nt][2] *= corr1; oacc[nt][3] *= corr1;
        }
        __syncwarp();

        // ---- O += P @ Vt ----
        #pragma unroll
        for (int k16 = 0; k16 < 4; ++k16) {
            uint32_t a0, a1, a2, a3;
            ldsm_x4(a0, a1, a2, a3, Pu + aoff + (uint32_t)(k16 * 32));
            #pragma unroll
            for (int ntp = 0; ntp < 4; ++ntp) {
                uint32_t b0, b1, b2, b3;
                ldsm_x4(b0, b1, b2, b3,
                        Vu + boff + (uint32_t)(ntp * 16 * PH * 2 + k16 * 32));
                mma_f16(oacc[2 * ntp],     a0, a1, a2, a3, b0, b1);
                mma_f16(oacc[2 * ntp + 1], a0, a1, a2, a3, b2, b3);
            }
        }
    }

    // ---- write O (half; feeds proj GEMM) ----
    const float inv0 = 1.0f / l0, inv1 = 1.0f / l1;
    const int r0 = qt * 128 + wr + g;
    const int r1 = r0 + 8;
    #pragma unroll
    for (int nt = 0; nt < 8; ++nt) {
        const int col = h * DHEAD + nt * 8 + 2 * t;
        if (r0 < SEQ)
            *(__half2*)&outa[(browbase + r0) * CDIM + col] =
                __floats2half2_rn(oacc[nt][0] * inv0, oacc[nt][1] * inv0);
        if (r1 < SEQ)
            *(__half2*)&outa[(browbase + r1) * CDIM + col] =
                __floats2half2_rn(oacc[nt][2] * inv1, oacc[nt][3] * inv1);
    }
}

// ---------------- launcher ----------------
extern "C" void kernel_launch(void* const* d_in, const int* in_sizes, int n_in,
                              void* d_out, int out_size)
{
    const float* x      = (const float*)d_in[0];
    const float* ln1_g  = (const float*)d_in[1];
    const float* ln1_b  = (const float*)d_in[2];
    const float* ln2_g  = (const float*)d_in[3];
    const float* ln2_b  = (const float*)d_in[4];
    const float* qkv_w  = (const float*)d_in[5];
    const float* qkv_b  = (const float*)d_in[6];
    const float* proj_w = (const float*)d_in[7];
    const float* proj_b = (const float*)d_in[8];
    const float* fc1_w  = (const float*)d_in[9];
    const float* fc1_b  = (const float*)d_in[10];
    const float* fc2_w  = (const float*)d_in[11];
    const float* fc2_b  = (const float*)d_in[12];
    float* out = (float*)d_out;

    __half *h, *qk, *vt, *attn, *ff, *wtq, *wtp, *wt1, *wt2;
    float *x1;
    cudaGetSymbolAddress((void**)&h,    g_h);
    cudaGetSymbolAddress((void**)&qk,   g_qk);
    cudaGetSymbolAddress((void**)&vt,   g_vt);
    cudaGetSymbolAddress((void**)&attn, g_attn);
    cudaGetSymbolAddress((void**)&x1,   g_x1);
    cudaGetSymbolAddress((void**)&ff,   g_ff);
    cudaGetSymbolAddress((void**)&wtq,  g_wt_qkv);
    cudaGetSymbolAddress((void**)&wtp,  g_wt_proj);
    cudaGetSymbolAddress((void**)&wt1,  g_wt_fc1);
    cudaGetSymbolAddress((void**)&wt2,  g_wt_fc2);

    cudaFuncSetAttribute(gemm_mma<0>, cudaFuncAttributeMaxDynamicSharedMemorySize, SMEM_DYN);
    cudaFuncSetAttribute(gemm_mma<1>, cudaFuncAttributeMaxDynamicSharedMemorySize, SMEM_DYN);
    cudaFuncSetAttribute(gemm_mma<2>, cudaFuncAttributeMaxDynamicSharedMemorySize, SMEM_DYN);
    cudaFuncSetAttribute(attn_tc,     cudaFuncAttributeMaxDynamicSharedMemorySize, ATT_SMEM);

    const int M  = MROWS;
    const int gy = (M + GBM - 1) / GBM;     // 145

    // merged weight transposes + V-tail zero (one launch)
    prep_kernel<<<7296, dim3(32, 8)>>>(qkv_w, proj_w, fc1_w, fc2_w);

    // 1. LN1
    ln_kernel<<<M, 256>>>(x, ln1_g, ln1_b, h);
    // 2. QKV (Q,K natural; V transposed)
    gemm_mma<0><<<dim3(C3 / GBN, gy), 256, SMEM_DYN>>>(h, wtq, qkv_b, nullptr, qk, vt, M, CDIM, C3);
    // 3. attention
    attn_tc<<<dim3((SEQ + 127) / 128, NHEAD, BATCH), 256, ATT_SMEM>>>(qk, vt, attn);
    // 4. x1 = x + attn @ proj_w + proj_b
    gemm_mma<1><<<dim3(CDIM / GBN, gy), 256, SMEM_DYN>>>(attn, wtp, proj_b, x, x1, nullptr, M, CDIM, CDIM);
    // 5. LN2
    ln_kernel<<<M, 256>>>(x1, ln2_g, ln2_b, h);
    // 6. ff = gelu(h @ fc1_w + fc1_b)
    gemm_mma<2><<<dim3(DFF / GBN, gy), 256, SMEM_DYN>>>(h, wt1, fc1_b, nullptr, ff, nullptr, M, CDIM, DFF);
    // 7. out = x1 + ff @ fc2_w + fc2_b
    gemm_mma<1><<<dim3(CDIM / GBN, gy), 256, SMEM_DYN>>>(ff, wt2, fc2_b, x1, out, nullptr, M, DFF, CDIM);
}

// round 10
// speedup vs baseline: 5.4708x; 1.0065x over previous
#include <cuda_runtime.h>
#include <cuda_fp16.h>
#include <cstdint>
#include <math.h>

// ---------------- problem constants ----------------
#define BATCH 32
#define SEQ   577
#define CDIM  768
#define NHEAD 12
#define DHEAD 64
#define DFF   3072
#define MROWS (BATCH*SEQ)          // 18464
#define C3    2304
#define QKW   1536                 // row width of g_qk (Q|K)
#define SEQP  640                  // padded seq for transposed V

// ---------------- scratch (device globals; no allocation) ----------------
__device__ __align__(256) __half g_h   [(size_t)MROWS * CDIM];
__device__ __align__(256) __half g_qk  [(size_t)MROWS * QKW];
__device__ __align__(256) __half g_vt  [(size_t)BATCH * NHEAD * DHEAD * SEQP];
__device__ __align__(256) __half g_attn[(size_t)MROWS * CDIM];
__device__ __align__(256) float  g_x1  [(size_t)MROWS * CDIM];
__device__ __align__(256) __half g_ff  [(size_t)MROWS * DFF];
__device__ __align__(256) __half g_wt_qkv [(size_t)C3   * CDIM];
__device__ __align__(256) __half g_wt_proj[(size_t)CDIM * CDIM];
__device__ __align__(256) __half g_wt_fc1 [(size_t)DFF  * CDIM];
__device__ __align__(256) __half g_wt_fc2 [(size_t)CDIM * DFF];

// ---------------- helpers ----------------
static __device__ __forceinline__ uint32_t smem_u32(const void* p) {
    uint32_t a;
    asm("{ .reg .u64 t; cvta.to.shared.u64 t, %1; cvt.u32.u64 %0, t; }" : "=r"(a) : "l"(p));
    return a;
}
static __device__ __forceinline__ void cp_async16(uint32_t dst, const void* src) {
    asm volatile("cp.async.cg.shared.global [%0], [%1], 16;" :: "r"(dst), "l"(src));
}
static __device__ __forceinline__ void cp_async16z(uint32_t dst, const void* src, int sz) {
    asm volatile("cp.async.cg.shared.global [%0], [%1], 16, %2;" :: "r"(dst), "l"(src), "r"(sz));
}
static __device__ __forceinline__ void mma_f16(
    float* d, uint32_t a0, uint32_t a1, uint32_t a2, uint32_t a3,
    uint32_t b0, uint32_t b1)
{
    asm volatile(
        "mma.sync.aligned.m16n8k16.row.col.f32.f16.f16.f32 "
        "{%0,%1,%2,%3}, {%4,%5,%6,%7}, {%8,%9}, {%0,%1,%2,%3};"
        : "+f"(d[0]), "+f"(d[1]), "+f"(d[2]), "+f"(d[3])
        : "r"(a0), "r"(a1), "r"(a2), "r"(a3), "r"(b0), "r"(b1));
}
static __device__ __forceinline__ void ldsm_x4(
    uint32_t& r0, uint32_t& r1, uint32_t& r2, uint32_t& r3, uint32_t addr)
{
    asm volatile("ldmatrix.sync.aligned.m8n8.x4.shared.b16 {%0,%1,%2,%3}, [%4];"
                 : "=r"(r0), "=r"(r1), "=r"(r2), "=r"(r3) : "r"(addr));
}

// ---------------- LayerNorm (fp32 in, half out) ----------------
__global__ void __launch_bounds__(256) ln_kernel(
    const float* __restrict__ x, const float* __restrict__ g,
    const float* __restrict__ b, __half* __restrict__ out)
{
    __shared__ float red[8];
    const int row = blockIdx.x;
    const int tid = threadIdx.x;
    const float* xr = x + (size_t)row * CDIM;

    float v0 = xr[tid], v1 = xr[tid + 256], v2 = xr[tid + 512];

    float s = v0 + v1 + v2;
    #pragma unroll
    for (int o = 16; o > 0; o >>= 1) s += __shfl_xor_sync(0xffffffffu, s, o);
    if ((tid & 31) == 0) red[tid >> 5] = s;
    __syncthreads();
    if (tid == 0) {
        float t = 0.f;
        #pragma unroll
        for (int w = 0; w < 8; ++w) t += red[w];
        red[0] = t;
    }
    __syncthreads();
    const float mean = red[0] * (1.0f / CDIM);
    __syncthreads();

    float d0 = v0 - mean, d1 = v1 - mean, d2 = v2 - mean;
    float sq = d0 * d0 + d1 * d1 + d2 * d2;
    #pragma unroll
    for (int o = 16; o > 0; o >>= 1) sq += __shfl_xor_sync(0xffffffffu, sq, o);
    if ((tid & 31) == 0) red[tid >> 5] = sq;
    __syncthreads();
    if (tid == 0) {
        float t = 0.f;
        #pragma unroll
        for (int w = 0; w < 8; ++w) t += red[w];
        red[0] = t;
    }
    __syncthreads();
    const float var = red[0] * (1.0f / CDIM);
    const float rstd = rsqrtf(var + 1e-5f);

    __half* outr = out + (size_t)row * CDIM;
    outr[tid]       = __float2half_rn(d0 * rstd * g[tid]       + b[tid]);
    outr[tid + 256] = __float2half_rn(d1 * rstd * g[tid + 256] + b[tid + 256]);
    outr[tid + 512] = __float2half_rn(d2 * rstd * g[tid + 512] + b[tid + 512]);
}

// ---------------- merged prep: 4 weight transposes + V-tail zero (one launch) ------
__global__ void __launch_bounds__(256) prep_kernel(
    const float* __restrict__ qkv_w, const float* __restrict__ proj_w,
    const float* __restrict__ fc1_w, const float* __restrict__ fc2_w)
{
    __shared__ float tb[32][33];
    int bid = blockIdx.x;
    const float* W; __half* Wt; int K, N;

    if (bid >= 6912) {
        __half* vt = g_vt + (size_t)(bid - 6912) * DHEAD * SEQP;
        const uint4 z = make_uint4(0u, 0u, 0u, 0u);
        int tid = threadIdx.y * 32 + threadIdx.x;
        #pragma unroll
        for (int i = 0; i < 4; ++i) {
            int f = i * 256 + tid;
            int d = f >> 4, u = f & 15;
            *(uint4*)(vt + (size_t)d * SEQP + 512 + u * 8) = z;
        }
        return;
    }
    if (bid < 1728)      { W = qkv_w;  Wt = g_wt_qkv;  K = CDIM; N = C3;  }
    else if (bid < 2304) { W = proj_w; Wt = g_wt_proj; K = CDIM; N = CDIM; bid -= 1728; }
    else if (bid < 4608) { W = fc1_w;  Wt = g_wt_fc1;  K = CDIM; N = DFF;  bid -= 2304; }
    else                 { W = fc2_w;  Wt = g_wt_fc2;  K = DFF;  N = CDIM; bid -= 4608; }

    const int nbx = K >> 5;
    const int k0 = (bid % nbx) * 32, n0 = (bid / nbx) * 32;
    #pragma unroll
    for (int i = threadIdx.y; i < 32; i += 8)
        tb[i][threadIdx.x] = W[(size_t)(k0 + i) * N + n0 + threadIdx.x];
    __syncthreads();
    #pragma unroll
    for (int i = threadIdx.y; i < 32; i += 8)
        Wt[(size_t)(n0 + i) * K + k0 + threadIdx.x] = __float2half_rn(tb[threadIdx.x][i]);
}

// ---------------- fp16 HMMA GEMM (ldmatrix fragments) ------------------------------
#define NSTAGE 4
#define GBM 128
#define GBN 256
#define PH 72                              // halfs per smem row (64 + 8 pad); 144B stride
#define STG_BYTES ((128 + 256) * PH * 2)   // 55296
#define SMEM_DYN (NSTAGE * STG_BYTES)      // 221184

__device__ __forceinline__ void load_stage(
    uint32_t sb, const __half* __restrict__ A, const __half* __restrict__ Wt,
    int bm, int bn, int M, int K, int kc, int tid)
{
    #pragma unroll
    for (int i = 0; i < 4; ++i) {
        int f = i * 256 + tid;
        int r = f >> 3, q = f & 7;
        int rr = bm + r;
        int sz = (rr < M) ? 16 : 0;
        if (rr >= M) rr = M - 1;
        cp_async16z(sb + (uint32_t)(r * (PH * 2) + q * 16),
                    A + (size_t)rr * K + kc + q * 8, sz);
    }
    const uint32_t bb = sb + 128 * (PH * 2);
    #pragma unroll
    for (int i = 0; i < 8; ++i) {
        int f = i * 256 + tid;
        int r = f >> 3, q = f & 7;
        cp_async16(bb + (uint32_t)(r * (PH * 2) + q * 16),
                   Wt + (size_t)(bn + r) * K + kc + q * 8);
    }
    asm volatile("cp.async.commit_group;" ::: "memory");
}

template <int EPI>
__global__ void __launch_bounds__(256, 1) gemm_mma(
    const __half* __restrict__ A, const __half* __restrict__ Wt,
    const float* __restrict__ bias, const float* __restrict__ res,
    void* __restrict__ outp, __half* __restrict__ vt,
    int M, int K, int N)
{
    extern __shared__ __align__(16) char dsm[];
    const uint32_t sbase = smem_u32(dsm);

    const int tid  = threadIdx.x;
    const int wid  = tid >> 5;
    const int lane = tid & 31;
    const int g = lane >> 2, t = lane & 3;
    const int bm = blockIdx.y * GBM;
    const int bn = blockIdx.x * GBN;
    const int wm = (wid >> 2) * 64;
    const int wn = (wid & 3) * 64;

    const int l15 = lane & 15;
    const int lhi = lane >> 4;
    const uint32_t aoff = (uint32_t)(((wm + l15) * PH + lhi * 8) * 2);
    const int l7 = lane & 7;
    const int q2 = lane >> 3;
    const uint32_t boff = (uint32_t)(((wn + (q2 >> 1) * 8 + l7) * PH + (q2 & 1) * 8) * 2);

    float acc[4][8][4];
    #pragma unroll
    for (int mt = 0; mt < 4; ++mt)
        #pragma unroll
        for (int nt = 0; nt < 8; ++nt)
            #pragma unroll
            for (int j = 0; j < 4; ++j) acc[mt][nt][j] = 0.f;

    const int KT = K >> 6;

    for (int c = 0; c < NSTAGE - 1; ++c)
        load_stage(sbase + (uint32_t)(c * STG_BYTES), A, Wt, bm, bn, M, K, c * 64, tid);

    for (int kt = 0; kt < KT; ++kt) {
        asm volatile("cp.async.wait_group %0;" :: "n"(NSTAGE - 2) : "memory");
        __syncthreads();

        const int kn = kt + NSTAGE - 1;
        if (kn < KT)
            load_stage(sbase + (uint32_t)((kn % NSTAGE) * STG_BYTES), A, Wt, bm, bn, M, K, kn * 64, tid);
        else
            asm volatile("cp.async.commit_group;" ::: "memory");

        const uint32_t sA_u = sbase + (uint32_t)((kt % NSTAGE) * STG_BYTES);
        const uint32_t sB_u = sA_u + 128 * (PH * 2);

        #pragma unroll
        for (int k16 = 0; k16 < 4; ++k16) {
            uint32_t bf[8][2];
            #pragma unroll
            for (int ntp = 0; ntp < 4; ++ntp) {
                uint32_t r0, r1, r2, r3;
                ldsm_x4(r0, r1, r2, r3,
                        sB_u + boff + (uint32_t)(ntp * 16 * PH * 2 + k16 * 32));
                bf[2 * ntp][0] = r0; bf[2 * ntp][1] = r1;
                bf[2 * ntp + 1][0] = r2; bf[2 * ntp + 1][1] = r3;
            }
            #pragma unroll
            for (int mt = 0; mt < 4; ++mt) {
                uint32_t a0, a1, a2, a3;
                ldsm_x4(a0, a1, a2, a3,
                        sA_u + aoff + (uint32_t)(mt * 16 * PH * 2 + k16 * 32));
                #pragma unroll
                for (int nt = 0; nt < 8; ++nt)
                    mma_f16(acc[mt][nt], a0, a1, a2, a3, bf[nt][0], bf[nt][1]);
            }
        }
    }

    // ---- epilogue ----
    #pragma unroll
    for (int nt = 0; nt < 8; ++nt) {
        const int c = bn + wn + nt * 8 + 2 * t;
        const float2 bia = *(const float2*)&bias[c];
        #pragma unroll
        for (int mt = 0; mt < 4; ++mt) {
            const int r0 = bm + wm + mt * 16 + g;
            const int r1 = r0 + 8;
            float v0 = acc[mt][nt][0] + bia.x;
            float v1 = acc[mt][nt][1] + bia.y;
            float v2 = acc[mt][nt][2] + bia.x;
            float v3 = acc[mt][nt][3] + bia.y;

            if (EPI == 0) {
                if (c < QKW) {
                    __half* qk = (__half*)outp;
                    if (r0 < M) *(__half2*)&qk[(size_t)r0 * QKW + c] = __floats2half2_rn(v0, v1);
                    if (r1 < M) *(__half2*)&qk[(size_t)r1 * QKW + c] = __floats2half2_rn(v2, v3);
                } else {
                    const int cc = c - QKW;
                    const int hh = cc >> 6, dd = cc & 63;
                    if (r0 < M) {
                        int bb = r0 / SEQ, n = r0 - bb * SEQ;
                        __half* p = vt + ((size_t)(bb * NHEAD + hh) * DHEAD + dd) * SEQP + n;
                        p[0]    = __float2half_rn(v0);
                        p[SEQP] = __float2half_rn(v1);
                    }
                    if (r1 < M) {
                        int bb = r1 / SEQ, n = r1 - bb * SEQ;
                        __half* p = vt + ((size_t)(bb * NHEAD + hh) * DHEAD + dd) * SEQP + n;
                        p[0]    = __float2half_rn(v2);
                        p[SEQP] = __float2half_rn(v3);
                    }
                }
            } else if (EPI == 1) {
                float* out = (float*)outp;
                if (r0 < M) {
                    float2 rv = *(const float2*)&res[(size_t)r0 * N + c];
                    *(float2*)&out[(size_t)r0 * N + c] = make_float2(v0 + rv.x, v1 + rv.y);
                }
                if (r1 < M) {
                    float2 rv = *(const float2*)&res[(size_t)r1 * N + c];
                    *(float2*)&out[(size_t)r1 * N + c] = make_float2(v2 + rv.x, v3 + rv.y);
                }
            } else {
                __half* out = (__half*)outp;
                v0 = 0.5f * v0 * (1.0f + erff(v0 * 0.70710678118654752f));
                v1 = 0.5f * v1 * (1.0f + erff(v1 * 0.70710678118654752f));
                v2 = 0.5f * v2 * (1.0f + erff(v2 * 0.70710678118654752f));
                v3 = 0.5f * v3 * (1.0f + erff(v3 * 0.70710678118654752f));
                if (r0 < M) *(__half2*)&out[(size_t)r0 * N + c] = __floats2half2_rn(v0, v1);
                if (r1 < M) *(__half2*)&out[(size_t)r1 * N + c] = __floats2half2_rn(v2, v3);
            }
        }
    }
}

// ---------------- fp16 flash attention: register-direct P fragments ----------------
// smem halfs: Qs[128][72] | Ks[2][64][72] | Vt[2][64][72]   (no P buffer)
#define OQ 0
#define OK (128 * PH)
#define OV (OK + 2 * 64 * PH)
#define ATT_SMEM ((OV + 2 * 64 * PH) * 2)
#define NKT 10

__global__ void __launch_bounds__(256) attn_tc(
    const __half* __restrict__ qk, const __half* __restrict__ vt,
    __half* __restrict__ outa)
{
    extern __shared__ __align__(16) char sm[];
    const uint32_t sbase = smem_u32(sm);

    const int qt = blockIdx.x;
    const int h  = blockIdx.y;
    const int b  = blockIdx.z;
    const int tid  = threadIdx.x;
    const int wid  = tid >> 5;
    const int lane = tid & 31;
    const int g = lane >> 2, t = lane & 3;
    const int wr = wid * 16;
    const size_t browbase = (size_t)b * SEQ;
    const __half* qbase = qk + browbase * QKW + h * DHEAD;
    const __half* vbase = vt + (size_t)(b * NHEAD + h) * DHEAD * SEQP;

    const int l15 = lane & 15;
    const int lhi = lane >> 4;
    const uint32_t aoff = (uint32_t)(((wr + l15) * PH + lhi * 8) * 2);
    const int l7 = lane & 7;
    const int q2 = lane >> 3;
    const uint32_t boff = (uint32_t)((((q2 >> 1) * 8 + l7) * PH + (q2 & 1) * 8) * 2);

    // ---- Q tile (128 x 64 halfs) ----
    #pragma unroll
    for (int i = 0; i < 4; ++i) {
        int f = i * 256 + tid;
        int r = f >> 3, q = f & 7;
        int n = qt * 128 + r;
        int sz = (n < SEQ) ? 16 : 0;
        if (n >= SEQ) n = SEQ - 1;
        cp_async16z(sbase + (uint32_t)((OQ + r * PH + q * 8) * 2),
                    qbase + (size_t)n * QKW + q * 8, sz);
    }
    // ---- K/V tile 0 into buf 0 ----
    #pragma unroll
    for (int i = 0; i < 2; ++i) {
        int f = i * 256 + tid;
        int r = f >> 3, q = f & 7;
        cp_async16(sbase + (uint32_t)((OK + r * PH + q * 8) * 2),
                   qbase + (size_t)r * QKW + CDIM + q * 8);
        cp_async16(sbase + (uint32_t)((OV + r * PH + q * 8) * 2),
                   vbase + (size_t)r * SEQP + q * 8);
    }
    asm volatile("cp.async.commit_group;" ::: "memory");

    float oacc[8][4];
    #pragma unroll
    for (int nt = 0; nt < 8; ++nt)
        #pragma unroll
        for (int j = 0; j < 4; ++j) oacc[nt][j] = 0.f;
    float m0 = -INFINITY, m1 = -INFINITY, l0 = 0.f, l1 = 0.f;

    for (int kt = 0; kt < NKT; ++kt) {
        const int buf = kt & 1;
        if (kt > 0) __syncthreads();
        if (kt + 1 < NKT) {
            const int nbuf = (kt + 1) & 1;
            #pragma unroll
            for (int i = 0; i < 2; ++i) {
                int f = i * 256 + tid;
                int r = f >> 3, q = f & 7;
                int kk = (kt + 1) * 64 + r;
                int sz = (kk < SEQ) ? 16 : 0;
                if (kk >= SEQ) kk = SEQ - 1;
                cp_async16z(sbase + (uint32_t)((OK + (nbuf * 64 + r) * PH + q * 8) * 2),
                            qbase + (size_t)kk * QKW + CDIM + q * 8, sz);
                cp_async16(sbase + (uint32_t)((OV + (nbuf * 64 + r) * PH + q * 8) * 2),
                           vbase + (size_t)r * SEQP + (kt + 1) * 64 + q * 8);
            }
        }
        asm volatile("cp.async.commit_group;" ::: "memory");
        asm volatile("cp.async.wait_group 1;" ::: "memory");
        __syncthreads();

        const uint32_t Qu = sbase + OQ * 2;
        const uint32_t Ku = sbase + (OK + buf * 64 * PH) * 2;
        const uint32_t Vu = sbase + (OV + buf * 64 * PH) * 2;

        // ---- S = Q @ K^T ----
        float sacc[8][4];
        #pragma unroll
        for (int nt = 0; nt < 8; ++nt)
            #pragma unroll
            for (int j = 0; j < 4; ++j) sacc[nt][j] = 0.f;

        #pragma unroll
        for (int k16 = 0; k16 < 4; ++k16) {
            uint32_t a0, a1, a2, a3;
            ldsm_x4(a0, a1, a2, a3, Qu + aoff + (uint32_t)(k16 * 32));
            #pragma unroll
            for (int ntp = 0; ntp < 4; ++ntp) {
                uint32_t b0, b1, b2, b3;
                ldsm_x4(b0, b1, b2, b3,
                        Ku + boff + (uint32_t)(ntp * 16 * PH * 2 + k16 * 32));
                mma_f16(sacc[2 * ntp],     a0, a1, a2, a3, b0, b1);
                mma_f16(sacc[2 * ntp + 1], a0, a1, a2, a3, b2, b3);
            }
        }

        // ---- scale + mask ----
        const int kb0 = kt * 64;
        #pragma unroll
        for (int nt = 0; nt < 8; ++nt) {
            const int c0 = kb0 + nt * 8 + 2 * t;
            sacc[nt][0] = (c0     < SEQ) ? sacc[nt][0] * 0.125f : -INFINITY;
            sacc[nt][1] = (c0 + 1 < SEQ) ? sacc[nt][1] * 0.125f : -INFINITY;
            sacc[nt][2] = (c0     < SEQ) ? sacc[nt][2] * 0.125f : -INFINITY;
            sacc[nt][3] = (c0 + 1 < SEQ) ? sacc[nt][3] * 0.125f : -INFINITY;
        }

        // ---- online softmax (rows g, g+8); pack P directly into A-fragments ----
        float mt0 = -INFINITY, mt1 = -INFINITY;
        #pragma unroll
        for (int nt = 0; nt < 8; ++nt) {
            mt0 = fmaxf(mt0, fmaxf(sacc[nt][0], sacc[nt][1]));
            mt1 = fmaxf(mt1, fmaxf(sacc[nt][2], sacc[nt][3]));
        }
        mt0 = fmaxf(mt0, __shfl_xor_sync(0xffffffffu, mt0, 1));
        mt0 = fmaxf(mt0, __shfl_xor_sync(0xffffffffu, mt0, 2));
        mt1 = fmaxf(mt1, __shfl_xor_sync(0xffffffffu, mt1, 1));
        mt1 = fmaxf(mt1, __shfl_xor_sync(0xffffffffu, mt1, 2));

        const float mn0 = fmaxf(m0, mt0), mn1 = fmaxf(m1, mt1);
        const float corr0 = __expf(m0 - mn0), corr1 = __expf(m1 - mn1);
        float ps0 = 0.f, ps1 = 0.f;
        uint32_t pfrag[4][4];   // [k16][a-reg]
        #pragma unroll
        for (int nt = 0; nt < 8; ++nt) {
            float p0 = __expf(sacc[nt][0] - mn0);
            float p1 = __expf(sacc[nt][1] - mn0);
            float p2 = __expf(sacc[nt][2] - mn1);
            float p3 = __expf(sacc[nt][3] - mn1);
            ps0 += p0 + p1; ps1 += p2 + p3;
            __half2 h01 = __floats2half2_rn(p0, p1);   // row g
            __half2 h23 = __floats2half2_rn(p2, p3);   // row g+8
            const int k16i = nt >> 1, hi = nt & 1;     // hi=0 -> a0/a1, hi=1 -> a2/a3
            pfrag[k16i][2 * hi]     = *(uint32_t*)&h01;
            pfrag[k16i][2 * hi + 1] = *(uint32_t*)&h23;
        }
        ps0 += __shfl_xor_sync(0xffffffffu, ps0, 1);
        ps0 += __shfl_xor_sync(0xffffffffu, ps0, 2);
        ps1 += __shfl_xor_sync(0xffffffffu, ps1, 1);
        ps1 += __shfl_xor_sync(0xffffffffu, ps1, 2);
        l0 = l0 * corr0 + ps0;  m0 = mn0;
        l1 = l1 * corr1 + ps1;  m1 = mn1;
        #pragma unroll
        for (int nt = 0; nt < 8; ++nt) {
            oacc[nt][0] *= corr0; oacc[nt][1] *= corr0;
            oacc[nt][2] *= corr1; oacc[nt][3] *= corr1;
        }

        // ---- O += P @ Vt (P from registers) ----
        #pragma unroll
        for (int k16 = 0; k16 < 4; ++k16) {
            #pragma unroll
            for (int ntp = 0; ntp < 4; ++ntp) {
                uint32_t b0, b1, b2, b3;
                ldsm_x4(b0, b1, b2, b3,
                        Vu + boff + (uint32_t)(ntp * 16 * PH * 2 + k16 * 32));
                mma_f16(oacc[2 * ntp],     pfrag[k16][0], pfrag[k16][1],
                        pfrag[k16][2], pfrag[k16][3], b0, b1);
                mma_f16(oacc[2 * ntp + 1], pfrag[k16][0], pfrag[k16][1],
                        pfrag[k16][2], pfrag[k16][3], b2, b3);
            }
        }
    }

    // ---- write O (half; feeds proj GEMM) ----
    const float inv0 = 1.0f / l0, inv1 = 1.0f / l1;
    const int r0 = qt * 128 + wr + g;
    const int r1 = r0 + 8;
    #pragma unroll
    for (int nt = 0; nt < 8; ++nt) {
        const int col = h * DHEAD + nt * 8 + 2 * t;
        if (r0 < SEQ)
            *(__half2*)&outa[(browbase + r0) * CDIM + col] =
                __floats2half2_rn(oacc[nt][0] * inv0, oacc[nt][1] * inv0);
        if (r1 < SEQ)
            *(__half2*)&outa[(browbase + r1) * CDIM + col] =
                __floats2half2_rn(oacc[nt][2] * inv1, oacc[nt][3] * inv1);
    }
}

// ---------------- launcher ----------------
extern "C" void kernel_launch(void* const* d_in, const int* in_sizes, int n_in,
                              void* d_out, int out_size)
{
    const float* x      = (const float*)d_in[0];
    const float* ln1_g  = (const float*)d_in[1];
    const float* ln1_b  = (const float*)d_in[2];
    const float* ln2_g  = (const float*)d_in[3];
    const float* ln2_b  = (const float*)d_in[4];
    const float* qkv_w  = (const float*)d_in[5];
    const float* qkv_b  = (const float*)d_in[6];
    const float* proj_w = (const float*)d_in[7];
    const float* proj_b = (const float*)d_in[8];
    const float* fc1_w  = (const float*)d_in[9];
    const float* fc1_b  = (const float*)d_in[10];
    const float* fc2_w  = (const float*)d_in[11];
    const float* fc2_b  = (const float*)d_in[12];
    float* out = (float*)d_out;

    __half *h, *qk, *vt, *attn, *ff, *wtq, *wtp, *wt1, *wt2;
    float *x1;
    cudaGetSymbolAddress((void**)&h,    g_h);
    cudaGetSymbolAddress((void**)&qk,   g_qk);
    cudaGetSymbolAddress((void**)&vt,   g_vt);
    cudaGetSymbolAddress((void**)&attn, g_attn);
    cudaGetSymbolAddress((void**)&x1,   g_x1);
    cudaGetSymbolAddress((void**)&ff,   g_ff);
    cudaGetSymbolAddress((void**)&wtq,  g_wt_qkv);
    cudaGetSymbolAddress((void**)&wtp,  g_wt_proj);
    cudaGetSymbolAddress((void**)&wt1,  g_wt_fc1);
    cudaGetSymbolAddress((void**)&wt2,  g_wt_fc2);

    cudaFuncSetAttribute(gemm_mma<0>, cudaFuncAttributeMaxDynamicSharedMemorySize, SMEM_DYN);
    cudaFuncSetAttribute(gemm_mma<1>, cudaFuncAttributeMaxDynamicSharedMemorySize, SMEM_DYN);
    cudaFuncSetAttribute(gemm_mma<2>, cudaFuncAttributeMaxDynamicSharedMemorySize, SMEM_DYN);
    cudaFuncSetAttribute(attn_tc,     cudaFuncAttributeMaxDynamicSharedMemorySize, ATT_SMEM);

    const int M  = MROWS;
    const int gy = (M + GBM - 1) / GBM;     // 145

    prep_kernel<<<7296, dim3(32, 8)>>>(qkv_w, proj_w, fc1_w, fc2_w);

    // 1. LN1
    ln_kernel<<<M, 256>>>(x, ln1_g, ln1_b, h);
    // 2. QKV (Q,K natural; V transposed)
    gemm_mma<0><<<dim3(C3 / GBN, gy), 256, SMEM_DYN>>>(h, wtq, qkv_b, nullptr, qk, vt, M, CDIM, C3);
    // 3. attention
    attn_tc<<<dim3((SEQ + 127) / 128, NHEAD, BATCH), 256, ATT_SMEM>>>(qk, vt, attn);
    // 4. x1 = x + attn @ proj_w + proj_b
    gemm_mma<1><<<dim3(CDIM / GBN, gy), 256, SMEM_DYN>>>(attn, wtp, proj_b, x, x1, nullptr, M, CDIM, CDIM);
    // 5. LN2
    ln_kernel<<<M, 256>>>(x1, ln2_g, ln2_b, h);
    // 6. ff = gelu(h @ fc1_w + fc1_b)
    gemm_mma<2><<<dim3(DFF / GBN, gy), 256, SMEM_DYN>>>(h, wt1, fc1_b, nullptr, ff, nullptr, M, CDIM, DFF);
    // 7. out = x1 + ff @ fc2_w + fc2_b
    gemm_mma<1><<<dim3(CDIM / GBN, gy), 256, SMEM_DYN>>>(ff, wt2, fc2_b, x1, out, nullptr, M, DFF, CDIM);
}

// round 11
// speedup vs baseline: 5.5430x; 1.0132x over previous
#include <cuda_runtime.h>
#include <cuda_fp16.h>
#include <cstdint>
#include <math.h>

// ---------------- problem constants ----------------
#define BATCH 32
#define SEQ   577
#define CDIM  768
#define NHEAD 12
#define DHEAD 64
#define DFF   3072
#define MROWS (BATCH*SEQ)          // 18464
#define C3    2304
#define QKW   1536                 // row width of g_qk (Q|K)
#define SEQP  640                  // padded seq for transposed V

// ---------------- scratch (device globals; no allocation) ----------------
__device__ __align__(256) __half g_h   [(size_t)MROWS * CDIM];
__device__ __align__(256) __half g_qk  [(size_t)MROWS * QKW];
__device__ __align__(256) __half g_vt  [(size_t)BATCH * NHEAD * DHEAD * SEQP];
__device__ __align__(256) __half g_attn[(size_t)MROWS * CDIM];
__device__ __align__(256) float  g_x1  [(size_t)MROWS * CDIM];
__device__ __align__(256) __half g_ff  [(size_t)MROWS * DFF];
__device__ __align__(256) __half g_wt_qkv [(size_t)C3   * CDIM];
__device__ __align__(256) __half g_wt_proj[(size_t)CDIM * CDIM];
__device__ __align__(256) __half g_wt_fc1 [(size_t)DFF  * CDIM];
__device__ __align__(256) __half g_wt_fc2 [(size_t)CDIM * DFF];

// ---------------- helpers ----------------
static __device__ __forceinline__ uint32_t smem_u32(const void* p) {
    uint32_t a;
    asm("{ .reg .u64 t; cvta.to.shared.u64 t, %1; cvt.u32.u64 %0, t; }" : "=r"(a) : "l"(p));
    return a;
}
static __device__ __forceinline__ void cp_async16(uint32_t dst, const void* src) {
    asm volatile("cp.async.cg.shared.global [%0], [%1], 16;" :: "r"(dst), "l"(src));
}
static __device__ __forceinline__ void cp_async16z(uint32_t dst, const void* src, int sz) {
    asm volatile("cp.async.cg.shared.global [%0], [%1], 16, %2;" :: "r"(dst), "l"(src), "r"(sz));
}
static __device__ __forceinline__ void mma_f16(
    float* d, uint32_t a0, uint32_t a1, uint32_t a2, uint32_t a3,
    uint32_t b0, uint32_t b1)
{
    asm volatile(
        "mma.sync.aligned.m16n8k16.row.col.f32.f16.f16.f32 "
        "{%0,%1,%2,%3}, {%4,%5,%6,%7}, {%8,%9}, {%0,%1,%2,%3};"
        : "+f"(d[0]), "+f"(d[1]), "+f"(d[2]), "+f"(d[3])
        : "r"(a0), "r"(a1), "r"(a2), "r"(a3), "r"(b0), "r"(b1));
}
static __device__ __forceinline__ void ldsm_x4(
    uint32_t& r0, uint32_t& r1, uint32_t& r2, uint32_t& r3, uint32_t addr)
{
    asm volatile("ldmatrix.sync.aligned.m8n8.x4.shared.b16 {%0,%1,%2,%3}, [%4];"
                 : "=r"(r0), "=r"(r1), "=r"(r2), "=r"(r3) : "r"(addr));
}

// ---------------- LayerNorm body (shared by prep + standalone) ----------------
static __device__ __forceinline__ void ln_body(
    const float* __restrict__ x, const float* __restrict__ g,
    const float* __restrict__ b, __half* __restrict__ out,
    int row, int tid, float* red)
{
    const float* xr = x + (size_t)row * CDIM;
    float v0 = xr[tid], v1 = xr[tid + 256], v2 = xr[tid + 512];

    float s = v0 + v1 + v2;
    #pragma unroll
    for (int o = 16; o > 0; o >>= 1) s += __shfl_xor_sync(0xffffffffu, s, o);
    if ((tid & 31) == 0) red[tid >> 5] = s;
    __syncthreads();
    if (tid == 0) {
        float t = 0.f;
        #pragma unroll
        for (int w = 0; w < 8; ++w) t += red[w];
        red[0] = t;
    }
    __syncthreads();
    const float mean = red[0] * (1.0f / CDIM);
    __syncthreads();

    float d0 = v0 - mean, d1 = v1 - mean, d2 = v2 - mean;
    float sq = d0 * d0 + d1 * d1 + d2 * d2;
    #pragma unroll
    for (int o = 16; o > 0; o >>= 1) sq += __shfl_xor_sync(0xffffffffu, sq, o);
    if ((tid & 31) == 0) red[tid >> 5] = sq;
    __syncthreads();
    if (tid == 0) {
        float t = 0.f;
        #pragma unroll
        for (int w = 0; w < 8; ++w) t += red[w];
        red[0] = t;
    }
    __syncthreads();
    const float var = red[0] * (1.0f / CDIM);
    const float rstd = rsqrtf(var + 1e-5f);

    __half* outr = out + (size_t)row * CDIM;
    outr[tid]       = __float2half_rn(d0 * rstd * g[tid]       + b[tid]);
    outr[tid + 256] = __float2half_rn(d1 * rstd * g[tid + 256] + b[tid + 256]);
    outr[tid + 512] = __float2half_rn(d2 * rstd * g[tid + 512] + b[tid + 512]);
}

__global__ void __launch_bounds__(256) ln_kernel(
    const float* __restrict__ x, const float* __restrict__ g,
    const float* __restrict__ b, __half* __restrict__ out)
{
    __shared__ float red[8];
    ln_body(x, g, b, out, blockIdx.x, threadIdx.x, red);
}

// ---------------- merged prep: LN1 + 4 weight transposes + V-tail zero -------------
// blocks: [0,18464) LN1 | [18464,25376) transposes | [25376,25760) zero g_vt tail
__global__ void __launch_bounds__(256) prep_kernel(
    const float* __restrict__ x, const float* __restrict__ ln1_g,
    const float* __restrict__ ln1_b,
    const float* __restrict__ qkv_w, const float* __restrict__ proj_w,
    const float* __restrict__ fc1_w, const float* __restrict__ fc2_w)
{
    __shared__ float tb[32][33];
    __shared__ float red[8];
    int bid = blockIdx.x;
    const int tid = threadIdx.y * 32 + threadIdx.x;

    if (bid < MROWS) {
        ln_body(x, ln1_g, ln1_b, g_h, bid, tid, red);
        return;
    }
    bid -= MROWS;

    if (bid >= 6912) {
        __half* vt = g_vt + (size_t)(bid - 6912) * DHEAD * SEQP;
        const uint4 z = make_uint4(0u, 0u, 0u, 0u);
        #pragma unroll
        for (int i = 0; i < 4; ++i) {
            int f = i * 256 + tid;
            int d = f >> 4, u = f & 15;
            *(uint4*)(vt + (size_t)d * SEQP + 512 + u * 8) = z;
        }
        return;
    }
    const float* W; __half* Wt; int K, N;
    if (bid < 1728)      { W = qkv_w;  Wt = g_wt_qkv;  K = CDIM; N = C3;  }
    else if (bid < 2304) { W = proj_w; Wt = g_wt_proj; K = CDIM; N = CDIM; bid -= 1728; }
    else if (bid < 4608) { W = fc1_w;  Wt = g_wt_fc1;  K = CDIM; N = DFF;  bid -= 2304; }
    else                 { W = fc2_w;  Wt = g_wt_fc2;  K = DFF;  N = CDIM; bid -= 4608; }

    const int nbx = K >> 5;
    const int k0 = (bid % nbx) * 32, n0 = (bid / nbx) * 32;
    #pragma unroll
    for (int i = threadIdx.y; i < 32; i += 8)
        tb[i][threadIdx.x] = W[(size_t)(k0 + i) * N + n0 + threadIdx.x];
    __syncthreads();
    #pragma unroll
    for (int i = threadIdx.y; i < 32; i += 8)
        Wt[(size_t)(n0 + i) * K + k0 + threadIdx.x] = __float2half_rn(tb[threadIdx.x][i]);
}

// ---------------- fp16 HMMA GEMM (ldmatrix fragments) ------------------------------
#define NSTAGE 4
#define GBM 128
#define GBN 256
#define PH 72                              // halfs per smem row (64 + 8 pad); 144B stride
#define STG_BYTES ((128 + 256) * PH * 2)   // 55296
#define SMEM_DYN (NSTAGE * STG_BYTES)      // 221184

__device__ __forceinline__ void load_stage(
    uint32_t sb, const __half* __restrict__ A, const __half* __restrict__ Wt,
    int bm, int bn, int M, int K, int kc, int tid)
{
    #pragma unroll
    for (int i = 0; i < 4; ++i) {
        int f = i * 256 + tid;
        int r = f >> 3, q = f & 7;
        int rr = bm + r;
        int sz = (rr < M) ? 16 : 0;
        if (rr >= M) rr = M - 1;
        cp_async16z(sb + (uint32_t)(r * (PH * 2) + q * 16),
                    A + (size_t)rr * K + kc + q * 8, sz);
    }
    const uint32_t bb = sb + 128 * (PH * 2);
    #pragma unroll
    for (int i = 0; i < 8; ++i) {
        int f = i * 256 + tid;
        int r = f >> 3, q = f & 7;
        cp_async16(bb + (uint32_t)(r * (PH * 2) + q * 16),
                   Wt + (size_t)(bn + r) * K + kc + q * 8);
    }
    asm volatile("cp.async.commit_group;" ::: "memory");
}

template <int EPI>
__global__ void __launch_bounds__(256, 1) gemm_mma(
    const __half* __restrict__ A, const __half* __restrict__ Wt,
    const float* __restrict__ bias, const float* __restrict__ res,
    void* __restrict__ outp, __half* __restrict__ vt,
    int M, int K, int N)
{
    extern __shared__ __align__(16) char dsm[];
    const uint32_t sbase = smem_u32(dsm);

    const int tid  = threadIdx.x;
    const int wid  = tid >> 5;
    const int lane = tid & 31;
    const int g = lane >> 2, t = lane & 3;
    const int bm = blockIdx.y * GBM;
    const int bn = blockIdx.x * GBN;
    const int wm = (wid >> 2) * 64;
    const int wn = (wid & 3) * 64;

    const int l15 = lane & 15;
    const int lhi = lane >> 4;
    const uint32_t aoff = (uint32_t)(((wm + l15) * PH + lhi * 8) * 2);
    const int l7 = lane & 7;
    const int q2 = lane >> 3;
    const uint32_t boff = (uint32_t)(((wn + (q2 >> 1) * 8 + l7) * PH + (q2 & 1) * 8) * 2);

    float acc[4][8][4];
    #pragma unroll
    for (int mt = 0; mt < 4; ++mt)
        #pragma unroll
        for (int nt = 0; nt < 8; ++nt)
            #pragma unroll
            for (int j = 0; j < 4; ++j) acc[mt][nt][j] = 0.f;

    const int KT = K >> 6;

    for (int c = 0; c < NSTAGE - 1; ++c)
        load_stage(sbase + (uint32_t)(c * STG_BYTES), A, Wt, bm, bn, M, K, c * 64, tid);

    for (int kt = 0; kt < KT; ++kt) {
        asm volatile("cp.async.wait_group %0;" :: "n"(NSTAGE - 2) : "memory");
        __syncthreads();

        const int kn = kt + NSTAGE - 1;
        if (kn < KT)
            load_stage(sbase + (uint32_t)((kn % NSTAGE) * STG_BYTES), A, Wt, bm, bn, M, K, kn * 64, tid);
        else
            asm volatile("cp.async.commit_group;" ::: "memory");

        const uint32_t sA_u = sbase + (uint32_t)((kt % NSTAGE) * STG_BYTES);
        const uint32_t sB_u = sA_u + 128 * (PH * 2);

        #pragma unroll
        for (int k16 = 0; k16 < 4; ++k16) {
            uint32_t bf[8][2];
            #pragma unroll
            for (int ntp = 0; ntp < 4; ++ntp) {
                uint32_t r0, r1, r2, r3;
                ldsm_x4(r0, r1, r2, r3,
                        sB_u + boff + (uint32_t)(ntp * 16 * PH * 2 + k16 * 32));
                bf[2 * ntp][0] = r0; bf[2 * ntp][1] = r1;
                bf[2 * ntp + 1][0] = r2; bf[2 * ntp + 1][1] = r3;
            }
            #pragma unroll
            for (int mt = 0; mt < 4; ++mt) {
                uint32_t a0, a1, a2, a3;
                ldsm_x4(a0, a1, a2, a3,
                        sA_u + aoff + (uint32_t)(mt * 16 * PH * 2 + k16 * 32));
                #pragma unroll
                for (int nt = 0; nt < 8; ++nt)
                    mma_f16(acc[mt][nt], a0, a1, a2, a3, bf[nt][0], bf[nt][1]);
            }
        }
    }

    // ---- epilogue ----
    #pragma unroll
    for (int nt = 0; nt < 8; ++nt) {
        const int c = bn + wn + nt * 8 + 2 * t;
        const float2 bia = *(const float2*)&bias[c];
        #pragma unroll
        for (int mt = 0; mt < 4; ++mt) {
            const int r0 = bm + wm + mt * 16 + g;
            const int r1 = r0 + 8;
            float v0 = acc[mt][nt][0] + bia.x;
            float v1 = acc[mt][nt][1] + bia.y;
            float v2 = acc[mt][nt][2] + bia.x;
            float v3 = acc[mt][nt][3] + bia.y;

            if (EPI == 0) {
                if (c < QKW) {
                    __half* qk = (__half*)outp;
                    if (r0 < M) *(__half2*)&qk[(size_t)r0 * QKW + c] = __floats2half2_rn(v0, v1);
                    if (r1 < M) *(__half2*)&qk[(size_t)r1 * QKW + c] = __floats2half2_rn(v2, v3);
                } else {
                    const int cc = c - QKW;
                    const int hh = cc >> 6, dd = cc & 63;
                    if (r0 < M) {
                        int bb = r0 / SEQ, n = r0 - bb * SEQ;
                        __half* p = vt + ((size_t)(bb * NHEAD + hh) * DHEAD + dd) * SEQP + n;
                        p[0]    = __float2half_rn(v0);
                        p[SEQP] = __float2half_rn(v1);
                    }
                    if (r1 < M) {
                        int bb = r1 / SEQ, n = r1 - bb * SEQ;
                        __half* p = vt + ((size_t)(bb * NHEAD + hh) * DHEAD + dd) * SEQP + n;
                        p[0]    = __float2half_rn(v2);
                        p[SEQP] = __float2half_rn(v3);
                    }
                }
            } else if (EPI == 1) {
                float* out = (float*)outp;
                if (r0 < M) {
                    float2 rv = *(const float2*)&res[(size_t)r0 * N + c];
                    *(float2*)&out[(size_t)r0 * N + c] = make_float2(v0 + rv.x, v1 + rv.y);
                }
                if (r1 < M) {
                    float2 rv = *(const float2*)&res[(size_t)r1 * N + c];
                    *(float2*)&out[(size_t)r1 * N + c] = make_float2(v2 + rv.x, v3 + rv.y);
                }
            } else {
                __half* out = (__half*)outp;
                v0 = 0.5f * v0 * (1.0f + erff(v0 * 0.70710678118654752f));
                v1 = 0.5f * v1 * (1.0f + erff(v1 * 0.70710678118654752f));
                v2 = 0.5f * v2 * (1.0f + erff(v2 * 0.70710678118654752f));
                v3 = 0.5f * v3 * (1.0f + erff(v3 * 0.70710678118654752f));
                if (r0 < M) *(__half2*)&out[(size_t)r0 * N + c] = __floats2half2_rn(v0, v1);
                if (r1 < M) *(__half2*)&out[(size_t)r1 * N + c] = __floats2half2_rn(v2, v3);
            }
        }
    }
}

// ---------------- fp16 flash attention: no-max softmax, register P -----------------
// smem halfs: Qs[128][72] | Ks[2][64][72] | Vt[2][64][72]
#define OQ 0
#define OK (128 * PH)
#define OV (OK + 2 * 64 * PH)
#define ATT_SMEM ((OV + 2 * 64 * PH) * 2)
#define NKT 10

__global__ void __launch_bounds__(256) attn_tc(
    const __half* __restrict__ qk, const __half* __restrict__ vt,
    __half* __restrict__ outa)
{
    extern __shared__ __align__(16) char sm[];
    const uint32_t sbase = smem_u32(sm);

    const int qt = blockIdx.x;
    const int h  = blockIdx.y;
    const int b  = blockIdx.z;
    const int tid  = threadIdx.x;
    const int wid  = tid >> 5;
    const int lane = tid & 31;
    const int g = lane >> 2, t = lane & 3;
    const int wr = wid * 16;
    const size_t browbase = (size_t)b * SEQ;
    const __half* qbase = qk + browbase * QKW + h * DHEAD;
    const __half* vbase = vt + (size_t)(b * NHEAD + h) * DHEAD * SEQP;

    const int l15 = lane & 15;
    const int lhi = lane >> 4;
    const uint32_t aoff = (uint32_t)(((wr + l15) * PH + lhi * 8) * 2);
    const int l7 = lane & 7;
    const int q2 = lane >> 3;
    const uint32_t boff = (uint32_t)((((q2 >> 1) * 8 + l7) * PH + (q2 & 1) * 8) * 2);

    // ---- Q tile (128 x 64 halfs) ----
    #pragma unroll
    for (int i = 0; i < 4; ++i) {
        int f = i * 256 + tid;
        int r = f >> 3, q = f & 7;
        int n = qt * 128 + r;
        int sz = (n < SEQ) ? 16 : 0;
        if (n >= SEQ) n = SEQ - 1;
        cp_async16z(sbase + (uint32_t)((OQ + r * PH + q * 8) * 2),
                    qbase + (size_t)n * QKW + q * 8, sz);
    }
    // ---- K/V tile 0 into buf 0 ----
    #pragma unroll
    for (int i = 0; i < 2; ++i) {
        int f = i * 256 + tid;
        int r = f >> 3, q = f & 7;
        cp_async16(sbase + (uint32_t)((OK + r * PH + q * 8) * 2),
                   qbase + (size_t)r * QKW + CDIM + q * 8);
        cp_async16(sbase + (uint32_t)((OV + r * PH + q * 8) * 2),
                   vbase + (size_t)r * SEQP + q * 8);
    }
    asm volatile("cp.async.commit_group;" ::: "memory");

    float oacc[8][4];
    #pragma unroll
    for (int nt = 0; nt < 8; ++nt)
        #pragma unroll
        for (int j = 0; j < 4; ++j) oacc[nt][j] = 0.f;
    float l0 = 0.f, l1 = 0.f;

    for (int kt = 0; kt < NKT; ++kt) {
        const int buf = kt & 1;
        if (kt > 0) __syncthreads();
        if (kt + 1 < NKT) {
            const int nbuf = (kt + 1) & 1;
            #pragma unroll
            for (int i = 0; i < 2; ++i) {
                int f = i * 256 + tid;
                int r = f >> 3, q = f & 7;
                int kk = (kt + 1) * 64 + r;
                int sz = (kk < SEQ) ? 16 : 0;
                if (kk >= SEQ) kk = SEQ - 1;
                cp_async16z(sbase + (uint32_t)((OK + (nbuf * 64 + r) * PH + q * 8) * 2),
                            qbase + (size_t)kk * QKW + CDIM + q * 8, sz);
                cp_async16(sbase + (uint32_t)((OV + (nbuf * 64 + r) * PH + q * 8) * 2),
                           vbase + (size_t)r * SEQP + (kt + 1) * 64 + q * 8);
            }
        }
        asm volatile("cp.async.commit_group;" ::: "memory");
        asm volatile("cp.async.wait_group 1;" ::: "memory");
        __syncthreads();

        const uint32_t Qu = sbase + OQ * 2;
        const uint32_t Ku = sbase + (OK + buf * 64 * PH) * 2;
        const uint32_t Vu = sbase + (OV + buf * 64 * PH) * 2;

        // ---- S = Q @ K^T ----
        float sacc[8][4];
        #pragma unroll
        for (int nt = 0; nt < 8; ++nt)
            #pragma unroll
            for (int j = 0; j < 4; ++j) sacc[nt][j] = 0.f;

        #pragma unroll
        for (int k16 = 0; k16 < 4; ++k16) {
            uint32_t a0, a1, a2, a3;
            ldsm_x4(a0, a1, a2, a3, Qu + aoff + (uint32_t)(k16 * 32));
            #pragma unroll
            for (int ntp = 0; ntp < 4; ++ntp) {
                uint32_t b0, b1, b2, b3;
                ldsm_x4(b0, b1, b2, b3,
                        Ku + boff + (uint32_t)(ntp * 16 * PH * 2 + k16 * 32));
                mma_f16(sacc[2 * ntp],     a0, a1, a2, a3, b0, b1);
                mma_f16(sacc[2 * ntp + 1], a0, a1, a2, a3, b2, b3);
            }
        }

        // ---- no-max softmax: P = exp(S/8), mask -> 0; pack into A-fragments ----
        const int kb0 = kt * 64;
        uint32_t pfrag[4][4];
        #pragma unroll
        for (int nt = 0; nt < 8; ++nt) {
            const int c0 = kb0 + nt * 8 + 2 * t;
            float p0 = (c0     < SEQ) ? __expf(sacc[nt][0] * 0.125f) : 0.f;
            float p1 = (c0 + 1 < SEQ) ? __expf(sacc[nt][1] * 0.125f) : 0.f;
            float p2 = (c0     < SEQ) ? __expf(sacc[nt][2] * 0.125f) : 0.f;
            float p3 = (c0 + 1 < SEQ) ? __expf(sacc[nt][3] * 0.125f) : 0.f;
            l0 += p0 + p1; l1 += p2 + p3;
            __half2 h01 = __floats2half2_rn(p0, p1);   // row g
            __half2 h23 = __floats2half2_rn(p2, p3);   // row g+8
            const int k16i = nt >> 1, hi = nt & 1;
            pfrag[k16i][2 * hi]     = *(uint32_t*)&h01;
            pfrag[k16i][2 * hi + 1] = *(uint32_t*)&h23;
        }

        // ---- O += P @ Vt (P from registers) ----
        #pragma unroll
        for (int k16 = 0; k16 < 4; ++k16) {
            #pragma unroll
            for (int ntp = 0; ntp < 4; ++ntp) {
                uint32_t b0, b1, b2, b3;
                ldsm_x4(b0, b1, b2, b3,
                        Vu + boff + (uint32_t)(ntp * 16 * PH * 2 + k16 * 32));
                mma_f16(oacc[2 * ntp],     pfrag[k16][0], pfrag[k16][1],
                        pfrag[k16][2], pfrag[k16][3], b0, b1);
                mma_f16(oacc[2 * ntp + 1], pfrag[k16][0], pfrag[k16][1],
                        pfrag[k16][2], pfrag[k16][3], b2, b3);
            }
        }
    }

    // ---- single row-sum reduction after the loop ----
    l0 += __shfl_xor_sync(0xffffffffu, l0, 1);
    l0 += __shfl_xor_sync(0xffffffffu, l0, 2);
    l1 += __shfl_xor_sync(0xffffffffu, l1, 1);
    l1 += __shfl_xor_sync(0xffffffffu, l1, 2);

    // ---- write O (half; feeds proj GEMM) ----
    const float inv0 = 1.0f / l0, inv1 = 1.0f / l1;
    const int r0 = qt * 128 + wr + g;
    const int r1 = r0 + 8;
    #pragma unroll
    for (int nt = 0; nt < 8; ++nt) {
        const int col = h * DHEAD + nt * 8 + 2 * t;
        if (r0 < SEQ)
            *(__half2*)&outa[(browbase + r0) * CDIM + col] =
                __floats2half2_rn(oacc[nt][0] * inv0, oacc[nt][1] * inv0);
        if (r1 < SEQ)
            *(__half2*)&outa[(browbase + r1) * CDIM + col] =
                __floats2half2_rn(oacc[nt][2] * inv1, oacc[nt][3] * inv1);
    }
}

// ---------------- launcher ----------------
extern "C" void kernel_launch(void* const* d_in, const int* in_sizes, int n_in,
                              void* d_out, int out_size)
{
    const float* x      = (const float*)d_in[0];
    const float* ln1_g  = (const float*)d_in[1];
    const float* ln1_b  = (const float*)d_in[2];
    const float* ln2_g  = (const float*)d_in[3];
    const float* ln2_b  = (const float*)d_in[4];
    const float* qkv_w  = (const float*)d_in[5];
    const float* qkv_b  = (const float*)d_in[6];
    const float* proj_w = (const float*)d_in[7];
    const float* proj_b = (const float*)d_in[8];
    const float* fc1_w  = (const float*)d_in[9];
    const float* fc1_b  = (const float*)d_in[10];
    const float* fc2_w  = (const float*)d_in[11];
    const float* fc2_b  = (const float*)d_in[12];
    float* out = (float*)d_out;

    __half *h, *qk, *vt, *attn, *ff, *wtq, *wtp, *wt1, *wt2;
    float *x1;
    cudaGetSymbolAddress((void**)&h,    g_h);
    cudaGetSymbolAddress((void**)&qk,   g_qk);
    cudaGetSymbolAddress((void**)&vt,   g_vt);
    cudaGetSymbolAddress((void**)&attn, g_attn);
    cudaGetSymbolAddress((void**)&x1,   g_x1);
    cudaGetSymbolAddress((void**)&ff,   g_ff);
    cudaGetSymbolAddress((void**)&wtq,  g_wt_qkv);
    cudaGetSymbolAddress((void**)&wtp,  g_wt_proj);
    cudaGetSymbolAddress((void**)&wt1,  g_wt_fc1);
    cudaGetSymbolAddress((void**)&wt2,  g_wt_fc2);

    cudaFuncSetAttribute(gemm_mma<0>, cudaFuncAttributeMaxDynamicSharedMemorySize, SMEM_DYN);
    cudaFuncSetAttribute(gemm_mma<1>, cudaFuncAttributeMaxDynamicSharedMemorySize, SMEM_DYN);
    cudaFuncSetAttribute(gemm_mma<2>, cudaFuncAttributeMaxDynamicSharedMemorySize, SMEM_DYN);
    cudaFuncSetAttribute(attn_tc,     cudaFuncAttributeMaxDynamicSharedMemorySize, ATT_SMEM);

    const int M  = MROWS;
    const int gy = (M + GBM - 1) / GBM;     // 145

    // merged LN1 + weight transposes + V-tail zero (one launch)
    prep_kernel<<<MROWS + 7296, dim3(32, 8)>>>(x, ln1_g, ln1_b, qkv_w, proj_w, fc1_w, fc2_w);

    // 2. QKV (Q,K natural; V transposed)
    gemm_mma<0><<<dim3(C3 / GBN, gy), 256, SMEM_DYN>>>(h, wtq, qkv_b, nullptr, qk, vt, M, CDIM, C3);
    // 3. attention
    attn_tc<<<dim3((SEQ + 127) / 128, NHEAD, BATCH), 256, ATT_SMEM>>>(qk, vt, attn);
    // 4. x1 = x + attn @ proj_w + proj_b
    gemm_mma<1><<<dim3(CDIM / GBN, gy), 256, SMEM_DYN>>>(attn, wtp, proj_b, x, x1, nullptr, M, CDIM, CDIM);
    // 5. LN2
    ln_kernel<<<M, 256>>>(x1, ln2_g, ln2_b, h);
    // 6. ff = gelu(h @ fc1_w + fc1_b)
    gemm_mma<2><<<dim3(DFF / GBN, gy), 256, SMEM_DYN>>>(h, wt1, fc1_b, nullptr, ff, nullptr, M, CDIM, DFF);
    // 7. out = x1 + ff @ fc2_w + fc2_b
    gemm_mma<1><<<dim3(CDIM / GBN, gy), 256, SMEM_DYN>>>(ff, wt2, fc2_b, x1, out, nullptr, M, DFF, CDIM);
}

// round 12
// speedup vs baseline: 5.6642x; 1.0218x over previous
#include <cuda_runtime.h>
#include <cuda_fp16.h>
#include <cstdint>
#include <math.h>

// ---------------- problem constants ----------------
#define BATCH 32
#define SEQ   577
#define CDIM  768
#define NHEAD 12
#define DHEAD 64
#define DFF   3072
#define MROWS (BATCH*SEQ)          // 18464
#define C3    2304
#define QKW   1536                 // row width of g_qk (Q|K)
#define SEQP  640                  // padded seq for transposed V

// ---------------- scratch (device globals; no allocation) ----------------
__device__ __align__(256) __half g_h   [(size_t)MROWS * CDIM];
__device__ __align__(256) __half g_qk  [(size_t)MROWS * QKW];
__device__ __align__(256) __half g_vt  [(size_t)BATCH * NHEAD * DHEAD * SEQP];
__device__ __align__(256) __half g_attn[(size_t)MROWS * CDIM];
__device__ __align__(256) float  g_x1  [(size_t)MROWS * CDIM];
__device__ __align__(256) __half g_ff  [(size_t)MROWS * DFF];
__device__ __align__(256) __half g_wt_qkv [(size_t)C3   * CDIM];
__device__ __align__(256) __half g_wt_proj[(size_t)CDIM * CDIM];
__device__ __align__(256) __half g_wt_fc1 [(size_t)DFF  * CDIM];
__device__ __align__(256) __half g_wt_fc2 [(size_t)CDIM * DFF];

// ---------------- helpers ----------------
static __device__ __forceinline__ uint32_t smem_u32(const void* p) {
    uint32_t a;
    asm("{ .reg .u64 t; cvta.to.shared.u64 t, %1; cvt.u32.u64 %0, t; }" : "=r"(a) : "l"(p));
    return a;
}
static __device__ __forceinline__ void cp_async16(uint32_t dst, const void* src) {
    asm volatile("cp.async.cg.shared.global [%0], [%1], 16;" :: "r"(dst), "l"(src));
}
static __device__ __forceinline__ void cp_async16z(uint32_t dst, const void* src, int sz) {
    asm volatile("cp.async.cg.shared.global [%0], [%1], 16, %2;" :: "r"(dst), "l"(src), "r"(sz));
}
static __device__ __forceinline__ void mma_f16(
    float* d, uint32_t a0, uint32_t a1, uint32_t a2, uint32_t a3,
    uint32_t b0, uint32_t b1)
{
    asm volatile(
        "mma.sync.aligned.m16n8k16.row.col.f32.f16.f16.f32 "
        "{%0,%1,%2,%3}, {%4,%5,%6,%7}, {%8,%9}, {%0,%1,%2,%3};"
        : "+f"(d[0]), "+f"(d[1]), "+f"(d[2]), "+f"(d[3])
        : "r"(a0), "r"(a1), "r"(a2), "r"(a3), "r"(b0), "r"(b1));
}
static __device__ __forceinline__ void ldsm_x4(
    uint32_t& r0, uint32_t& r1, uint32_t& r2, uint32_t& r3, uint32_t addr)
{
    asm volatile("ldmatrix.sync.aligned.m8n8.x4.shared.b16 {%0,%1,%2,%3}, [%4];"
                 : "=r"(r0), "=r"(r1), "=r"(r2), "=r"(r3) : "r"(addr));
}

// ---------------- LayerNorm body (shared by prep + standalone) ----------------
static __device__ __forceinline__ void ln_body(
    const float* __restrict__ x, const float* __restrict__ g,
    const float* __restrict__ b, __half* __restrict__ out,
    int row, int tid, float* red)
{
    const float* xr = x + (size_t)row * CDIM;
    float v0 = xr[tid], v1 = xr[tid + 256], v2 = xr[tid + 512];

    float s = v0 + v1 + v2;
    #pragma unroll
    for (int o = 16; o > 0; o >>= 1) s += __shfl_xor_sync(0xffffffffu, s, o);
    if ((tid & 31) == 0) red[tid >> 5] = s;
    __syncthreads();
    if (tid == 0) {
        float t = 0.f;
        #pragma unroll
        for (int w = 0; w < 8; ++w) t += red[w];
        red[0] = t;
    }
    __syncthreads();
    const float mean = red[0] * (1.0f / CDIM);
    __syncthreads();

    float d0 = v0 - mean, d1 = v1 - mean, d2 = v2 - mean;
    float sq = d0 * d0 + d1 * d1 + d2 * d2;
    #pragma unroll
    for (int o = 16; o > 0; o >>= 1) sq += __shfl_xor_sync(0xffffffffu, sq, o);
    if ((tid & 31) == 0) red[tid >> 5] = sq;
    __syncthreads();
    if (tid == 0) {
        float t = 0.f;
        #pragma unroll
        for (int w = 0; w < 8; ++w) t += red[w];
        red[0] = t;
    }
    __syncthreads();
    const float var = red[0] * (1.0f / CDIM);
    const float rstd = rsqrtf(var + 1e-5f);

    __half* outr = out + (size_t)row * CDIM;
    outr[tid]       = __float2half_rn(d0 * rstd * g[tid]       + b[tid]);
    outr[tid + 256] = __float2half_rn(d1 * rstd * g[tid + 256] + b[tid + 256]);
    outr[tid + 512] = __float2half_rn(d2 * rstd * g[tid + 512] + b[tid + 512]);
}

__global__ void __launch_bounds__(256) ln_kernel(
    const float* __restrict__ x, const float* __restrict__ g,
    const float* __restrict__ b, __half* __restrict__ out)
{
    __shared__ float red[8];
    ln_body(x, g, b, out, blockIdx.x, threadIdx.x, red);
}

// ---------------- merged prep: LN1 + 4 weight transposes + V-tail zero -------------
__global__ void __launch_bounds__(256) prep_kernel(
    const float* __restrict__ x, const float* __restrict__ ln1_g,
    const float* __restrict__ ln1_b,
    const float* __restrict__ qkv_w, const float* __restrict__ proj_w,
    const float* __restrict__ fc1_w, const float* __restrict__ fc2_w)
{
    __shared__ float tb[32][33];
    __shared__ float red[8];
    int bid = blockIdx.x;
    const int tid = threadIdx.y * 32 + threadIdx.x;

    if (bid < MROWS) {
        ln_body(x, ln1_g, ln1_b, g_h, bid, tid, red);
        return;
    }
    bid -= MROWS;

    if (bid >= 6912) {
        __half* vt = g_vt + (size_t)(bid - 6912) * DHEAD * SEQP;
        const uint4 z = make_uint4(0u, 0u, 0u, 0u);
        #pragma unroll
        for (int i = 0; i < 4; ++i) {
            int f = i * 256 + tid;
            int d = f >> 4, u = f & 15;
            *(uint4*)(vt + (size_t)d * SEQP + 512 + u * 8) = z;
        }
        return;
    }
    const float* W; __half* Wt; int K, N;
    if (bid < 1728)      { W = qkv_w;  Wt = g_wt_qkv;  K = CDIM; N = C3;  }
    else if (bid < 2304) { W = proj_w; Wt = g_wt_proj; K = CDIM; N = CDIM; bid -= 1728; }
    else if (bid < 4608) { W = fc1_w;  Wt = g_wt_fc1;  K = CDIM; N = DFF;  bid -= 2304; }
    else                 { W = fc2_w;  Wt = g_wt_fc2;  K = DFF;  N = CDIM; bid -= 4608; }

    const int nbx = K >> 5;
    const int k0 = (bid % nbx) * 32, n0 = (bid / nbx) * 32;
    #pragma unroll
    for (int i = threadIdx.y; i < 32; i += 8)
        tb[i][threadIdx.x] = W[(size_t)(k0 + i) * N + n0 + threadIdx.x];
    __syncthreads();
    #pragma unroll
    for (int i = threadIdx.y; i < 32; i += 8)
        Wt[(size_t)(n0 + i) * K + k0 + threadIdx.x] = __float2half_rn(tb[threadIdx.x][i]);
}

// ---------------- fp16 HMMA GEMM: 512 threads, 16 warps of 32x64 -------------------
#define NSTAGE 4
#define GBM 128
#define GBN 256
#define PH 72                              // halfs per smem row (64 + 8 pad); 144B stride
#define STG_BYTES ((128 + 256) * PH * 2)   // 55296
#define SMEM_DYN (NSTAGE * STG_BYTES)      // 221184
#define GTHREADS 512

__device__ __forceinline__ void load_stage(
    uint32_t sb, const __half* __restrict__ A, const __half* __restrict__ Wt,
    int bm, int bn, int M, int K, int kc, int tid)
{
    #pragma unroll
    for (int i = 0; i < 2; ++i) {
        int f = i * GTHREADS + tid;
        int r = f >> 3, q = f & 7;
        int rr = bm + r;
        int sz = (rr < M) ? 16 : 0;
        if (rr >= M) rr = M - 1;
        cp_async16z(sb + (uint32_t)(r * (PH * 2) + q * 16),
                    A + (size_t)rr * K + kc + q * 8, sz);
    }
    const uint32_t bb = sb + 128 * (PH * 2);
    #pragma unroll
    for (int i = 0; i < 4; ++i) {
        int f = i * GTHREADS + tid;
        int r = f >> 3, q = f & 7;
        cp_async16(bb + (uint32_t)(r * (PH * 2) + q * 16),
                   Wt + (size_t)(bn + r) * K + kc + q * 8);
    }
    asm volatile("cp.async.commit_group;" ::: "memory");
}

template <int EPI>
__global__ void __launch_bounds__(GTHREADS, 1) gemm_mma(
    const __half* __restrict__ A, const __half* __restrict__ Wt,
    const float* __restrict__ bias, const float* __restrict__ res,
    void* __restrict__ outp, __half* __restrict__ vt,
    int M, int K, int N)
{
    extern __shared__ __align__(16) char dsm[];
    const uint32_t sbase = smem_u32(dsm);

    const int tid  = threadIdx.x;
    const int wid  = tid >> 5;
    const int lane = tid & 31;
    const int g = lane >> 2, t = lane & 3;
    const int bm = blockIdx.y * GBM;
    const int bn = blockIdx.x * GBN;
    const int wm = (wid >> 2) * 32;       // 4 warp-rows of 32
    const int wn = (wid & 3) * 64;        // 4 warp-cols of 64

    const int l15 = lane & 15;
    const int lhi = lane >> 4;
    const uint32_t aoff = (uint32_t)(((wm + l15) * PH + lhi * 8) * 2);
    const int l7 = lane & 7;
    const int q2 = lane >> 3;
    const uint32_t boff = (uint32_t)(((wn + (q2 >> 1) * 8 + l7) * PH + (q2 & 1) * 8) * 2);

    float acc[2][8][4];
    #pragma unroll
    for (int mt = 0; mt < 2; ++mt)
        #pragma unroll
        for (int nt = 0; nt < 8; ++nt)
            #pragma unroll
            for (int j = 0; j < 4; ++j) acc[mt][nt][j] = 0.f;

    const int KT = K >> 6;

    for (int c = 0; c < NSTAGE - 1; ++c)
        load_stage(sbase + (uint32_t)(c * STG_BYTES), A, Wt, bm, bn, M, K, c * 64, tid);

    for (int kt = 0; kt < KT; ++kt) {
        asm volatile("cp.async.wait_group %0;" :: "n"(NSTAGE - 2) : "memory");
        __syncthreads();

        const int kn = kt + NSTAGE - 1;
        if (kn < KT)
            load_stage(sbase + (uint32_t)((kn % NSTAGE) * STG_BYTES), A, Wt, bm, bn, M, K, kn * 64, tid);
        else
            asm volatile("cp.async.commit_group;" ::: "memory");

        const uint32_t sA_u = sbase + (uint32_t)((kt % NSTAGE) * STG_BYTES);
        const uint32_t sB_u = sA_u + 128 * (PH * 2);

        #pragma unroll
        for (int k16 = 0; k16 < 4; ++k16) {
            uint32_t bf[8][2];
            #pragma unroll
            for (int ntp = 0; ntp < 4; ++ntp) {
                uint32_t r0, r1, r2, r3;
                ldsm_x4(r0, r1, r2, r3,
                        sB_u + boff + (uint32_t)(ntp * 16 * PH * 2 + k16 * 32));
                bf[2 * ntp][0] = r0; bf[2 * ntp][1] = r1;
                bf[2 * ntp + 1][0] = r2; bf[2 * ntp + 1][1] = r3;
            }
            #pragma unroll
            for (int mt = 0; mt < 2; ++mt) {
                uint32_t a0, a1, a2, a3;
                ldsm_x4(a0, a1, a2, a3,
                        sA_u + aoff + (uint32_t)(mt * 16 * PH * 2 + k16 * 32));
                #pragma unroll
                for (int nt = 0; nt < 8; ++nt)
                    mma_f16(acc[mt][nt], a0, a1, a2, a3, bf[nt][0], bf[nt][1]);
            }
        }
    }

    // ---- epilogue ----
    #pragma unroll
    for (int nt = 0; nt < 8; ++nt) {
        const int c = bn + wn + nt * 8 + 2 * t;
        const float2 bia = *(const float2*)&bias[c];
        #pragma unroll
        for (int mt = 0; mt < 2; ++mt) {
            const int r0 = bm + wm + mt * 16 + g;
            const int r1 = r0 + 8;
            float v0 = acc[mt][nt][0] + bia.x;
            float v1 = acc[mt][nt][1] + bia.y;
            float v2 = acc[mt][nt][2] + bia.x;
            float v3 = acc[mt][nt][3] + bia.y;

            if (EPI == 0) {
                if (c < QKW) {
                    __half* qk = (__half*)outp;
                    if (r0 < M) *(__half2*)&qk[(size_t)r0 * QKW + c] = __floats2half2_rn(v0, v1);
                    if (r1 < M) *(__half2*)&qk[(size_t)r1 * QKW + c] = __floats2half2_rn(v2, v3);
                } else {
                    const int cc = c - QKW;
                    const int hh = cc >> 6, dd = cc & 63;
                    if (r0 < M) {
                        int bb = r0 / SEQ, n = r0 - bb * SEQ;
                        __half* p = vt + ((size_t)(bb * NHEAD + hh) * DHEAD + dd) * SEQP + n;
                        p[0]    = __float2half_rn(v0);
                        p[SEQP] = __float2half_rn(v1);
                    }
                    if (r1 < M) {
                        int bb = r1 / SEQ, n = r1 - bb * SEQ;
                        __half* p = vt + ((size_t)(bb * NHEAD + hh) * DHEAD + dd) * SEQP + n;
                        p[0]    = __float2half_rn(v2);
                        p[SEQP] = __float2half_rn(v3);
                    }
                }
            } else if (EPI == 1) {
                float* out = (float*)outp;
                if (r0 < M) {
                    float2 rv = *(const float2*)&res[(size_t)r0 * N + c];
                    *(float2*)&out[(size_t)r0 * N + c] = make_float2(v0 + rv.x, v1 + rv.y);
                }
                if (r1 < M) {
                    float2 rv = *(const float2*)&res[(size_t)r1 * N + c];
                    *(float2*)&out[(size_t)r1 * N + c] = make_float2(v2 + rv.x, v3 + rv.y);
                }
            } else {
                __half* out = (__half*)outp;
                v0 = 0.5f * v0 * (1.0f + erff(v0 * 0.70710678118654752f));
                v1 = 0.5f * v1 * (1.0f + erff(v1 * 0.70710678118654752f));
                v2 = 0.5f * v2 * (1.0f + erff(v2 * 0.70710678118654752f));
                v3 = 0.5f * v3 * (1.0f + erff(v3 * 0.70710678118654752f));
                if (r0 < M) *(__half2*)&out[(size_t)r0 * N + c] = __floats2half2_rn(v0, v1);
                if (r1 < M) *(__half2*)&out[(size_t)r1 * N + c] = __floats2half2_rn(v2, v3);
            }
        }
    }
}

// ---------------- fp16 flash attention: no-max softmax, register P -----------------
#define OQ 0
#define OK (128 * PH)
#define OV (OK + 2 * 64 * PH)
#define ATT_SMEM ((OV + 2 * 64 * PH) * 2)
#define NKT 10

__global__ void __launch_bounds__(256) attn_tc(
    const __half* __restrict__ qk, const __half* __restrict__ vt,
    __half* __restrict__ outa)
{
    extern __shared__ __align__(16) char sm[];
    const uint32_t sbase = smem_u32(sm);

    const int qt = blockIdx.x;
    const int h  = blockIdx.y;
    const int b  = blockIdx.z;
    const int tid  = threadIdx.x;
    const int wid  = tid >> 5;
    const int lane = tid & 31;
    const int g = lane >> 2, t = lane & 3;
    const int wr = wid * 16;
    const size_t browbase = (size_t)b * SEQ;
    const __half* qbase = qk + browbase * QKW + h * DHEAD;
    const __half* vbase = vt + (size_t)(b * NHEAD + h) * DHEAD * SEQP;

    const int l15 = lane & 15;
    const int lhi = lane >> 4;
    const uint32_t aoff = (uint32_t)(((wr + l15) * PH + lhi * 8) * 2);
    const int l7 = lane & 7;
    const int q2 = lane >> 3;
    const uint32_t boff = (uint32_t)((((q2 >> 1) * 8 + l7) * PH + (q2 & 1) * 8) * 2);

    #pragma unroll
    for (int i = 0; i < 4; ++i) {
        int f = i * 256 + tid;
        int r = f >> 3, q = f & 7;
        int n = qt * 128 + r;
        int sz = (n < SEQ) ? 16 : 0;
        if (n >= SEQ) n = SEQ - 1;
        cp_async16z(sbase + (uint32_t)((OQ + r * PH + q * 8) * 2),
                    qbase + (size_t)n * QKW + q * 8, sz);
    }
    #pragma unroll
    for (int i = 0; i < 2; ++i) {
        int f = i * 256 + tid;
        int r = f >> 3, q = f & 7;
        cp_async16(sbase + (uint32_t)((OK + r * PH + q * 8) * 2),
                   qbase + (size_t)r * QKW + CDIM + q * 8);
        cp_async16(sbase + (uint32_t)((OV + r * PH + q * 8) * 2),
                   vbase + (size_t)r * SEQP + q * 8);
    }
    asm volatile("cp.async.commit_group;" ::: "memory");

    float oacc[8][4];
    #pragma unroll
    for (int nt = 0; nt < 8; ++nt)
        #pragma unroll
        for (int j = 0; j < 4; ++j) oacc[nt][j] = 0.f;
    float l0 = 0.f, l1 = 0.f;

    for (int kt = 0; kt < NKT; ++kt) {
        const int buf = kt & 1;
        if (kt > 0) __syncthreads();
        if (kt + 1 < NKT) {
            const int nbuf = (kt + 1) & 1;
            #pragma unroll
            for (int i = 0; i < 2; ++i) {
                int f = i * 256 + tid;
                int r = f >> 3, q = f & 7;
                int kk = (kt + 1) * 64 + r;
                int sz = (kk < SEQ) ? 16 : 0;
                if (kk >= SEQ) kk = SEQ - 1;
                cp_async16z(sbase + (uint32_t)((OK + (nbuf * 64 + r) * PH + q * 8) * 2),
                            qbase + (size_t)kk * QKW + CDIM + q * 8, sz);
                cp_async16(sbase + (uint32_t)((OV + (nbuf * 64 + r) * PH + q * 8) * 2),
                           vbase + (size_t)r * SEQP + (kt + 1) * 64 + q * 8);
            }
        }
        asm volatile("cp.async.commit_group;" ::: "memory");
        asm volatile("cp.async.wait_group 1;" ::: "memory");
        __syncthreads();

        const uint32_t Qu = sbase + OQ * 2;
        const uint32_t Ku = sbase + (OK + buf * 64 * PH) * 2;
        const uint32_t Vu = sbase + (OV + buf * 64 * PH) * 2;

        float sacc[8][4];
        #pragma unroll
        for (int nt = 0; nt < 8; ++nt)
            #pragma unroll
            for (int j = 0; j < 4; ++j) sacc[nt][j] = 0.f;

        #pragma unroll
        for (int k16 = 0; k16 < 4; ++k16) {
            uint32_t a0, a1, a2, a3;
            ldsm_x4(a0, a1, a2, a3, Qu + aoff + (uint32_t)(k16 * 32));
            #pragma unroll
            for (int ntp = 0; ntp < 4; ++ntp) {
                uint32_t b0, b1, b2, b3;
                ldsm_x4(b0, b1, b2, b3,
                        Ku + boff + (uint32_t)(ntp * 16 * PH * 2 + k16 * 32));
                mma_f16(sacc[2 * ntp],     a0, a1, a2, a3, b0, b1);
                mma_f16(sacc[2 * ntp + 1], a0, a1, a2, a3, b2, b3);
            }
        }

        const int kb0 = kt * 64;
        uint32_t pfrag[4][4];
        #pragma unroll
        for (int nt = 0; nt < 8; ++nt) {
            const int c0 = kb0 + nt * 8 + 2 * t;
            float p0 = (c0     < SEQ) ? __expf(sacc[nt][0] * 0.125f) : 0.f;
            float p1 = (c0 + 1 < SEQ) ? __expf(sacc[nt][1] * 0.125f) : 0.f;
            float p2 = (c0     < SEQ) ? __expf(sacc[nt][2] * 0.125f) : 0.f;
            float p3 = (c0 + 1 < SEQ) ? __expf(sacc[nt][3] * 0.125f) : 0.f;
            l0 += p0 + p1; l1 += p2 + p3;
            __half2 h01 = __floats2half2_rn(p0, p1);
            __half2 h23 = __floats2half2_rn(p2, p3);
            const int k16i = nt >> 1, hi = nt & 1;
            pfrag[k16i][2 * hi]     = *(uint32_t*)&h01;
            pfrag[k16i][2 * hi + 1] = *(uint32_t*)&h23;
        }

        #pragma unroll
        for (int k16 = 0; k16 < 4; ++k16) {
            #pragma unroll
            for (int ntp = 0; ntp < 4; ++ntp) {
                uint32_t b0, b1, b2, b3;
                ldsm_x4(b0, b1, b2, b3,
                        Vu + boff + (uint32_t)(ntp * 16 * PH * 2 + k16 * 32));
                mma_f16(oacc[2 * ntp],     pfrag[k16][0], pfrag[k16][1],
                        pfrag[k16][2], pfrag[k16][3], b0, b1);
                mma_f16(oacc[2 * ntp + 1], pfrag[k16][0], pfrag[k16][1],
                        pfrag[k16][2], pfrag[k16][3], b2, b3);
            }
        }
    }

    l0 += __shfl_xor_sync(0xffffffffu, l0, 1);
    l0 += __shfl_xor_sync(0xffffffffu, l0, 2);
    l1 += __shfl_xor_sync(0xffffffffu, l1, 1);
    l1 += __shfl_xor_sync(0xffffffffu, l1, 2);

    const float inv0 = 1.0f / l0, inv1 = 1.0f / l1;
    const int r0 = qt * 128 + wr + g;
    const int r1 = r0 + 8;
    #pragma unroll
    for (int nt = 0; nt < 8; ++nt) {
        const int col = h * DHEAD + nt * 8 + 2 * t;
        if (r0 < SEQ)
            *(__half2*)&outa[(browbase + r0) * CDIM + col] =
                __floats2half2_rn(oacc[nt][0] * inv0, oacc[nt][1] * inv0);
        if (r1 < SEQ)
            *(__half2*)&outa[(browbase + r1) * CDIM + col] =
                __floats2half2_rn(oacc[nt][2] * inv1, oacc[nt][3] * inv1);
    }
}

// ---------------- launcher ----------------
extern "C" void kernel_launch(void* const* d_in, const int* in_sizes, int n_in,
                              void* d_out, int out_size)
{
    const float* x      = (const float*)d_in[0];
    const float* ln1_g  = (const float*)d_in[1];
    const float* ln1_b  = (const float*)d_in[2];
    const float* ln2_g  = (const float*)d_in[3];
    const float* ln2_b  = (const float*)d_in[4];
    const float* qkv_w  = (const float*)d_in[5];
    const float* qkv_b  = (const float*)d_in[6];
    const float* proj_w = (const float*)d_in[7];
    const float* proj_b = (const float*)d_in[8];
    const float* fc1_w  = (const float*)d_in[9];
    const float* fc1_b  = (const float*)d_in[10];
    const float* fc2_w  = (const float*)d_in[11];
    const float* fc2_b  = (const float*)d_in[12];
    float* out = (float*)d_out;

    __half *h, *qk, *vt, *attn, *ff, *wtq, *wtp, *wt1, *wt2;
    float *x1;
    cudaGetSymbolAddress((void**)&h,    g_h);
    cudaGetSymbolAddress((void**)&qk,   g_qk);
    cudaGetSymbolAddress((void**)&vt,   g_vt);
    cudaGetSymbolAddress((void**)&attn, g_attn);
    cudaGetSymbolAddress((void**)&x1,   g_x1);
    cudaGetSymbolAddress((void**)&ff,   g_ff);
    cudaGetSymbolAddress((void**)&wtq,  g_wt_qkv);
    cudaGetSymbolAddress((void**)&wtp,  g_wt_proj);
    cudaGetSymbolAddress((void**)&wt1,  g_wt_fc1);
    cudaGetSymbolAddress((void**)&wt2,  g_wt_fc2);

    cudaFuncSetAttribute(gemm_mma<0>, cudaFuncAttributeMaxDynamicSharedMemorySize, SMEM_DYN);
    cudaFuncSetAttribute(gemm_mma<1>, cudaFuncAttributeMaxDynamicSharedMemorySize, SMEM_DYN);
    cudaFuncSetAttribute(gemm_mma<2>, cudaFuncAttributeMaxDynamicSharedMemorySize, SMEM_DYN);
    cudaFuncSetAttribute(attn_tc,     cudaFuncAttributeMaxDynamicSharedMemorySize, ATT_SMEM);

    const int M  = MROWS;
    const int gy = (M + GBM - 1) / GBM;     // 145

    prep_kernel<<<MROWS + 7296, dim3(32, 8)>>>(x, ln1_g, ln1_b, qkv_w, proj_w, fc1_w, fc2_w);

    // 2. QKV (Q,K natural; V transposed)
    gemm_mma<0><<<dim3(C3 / GBN, gy), GTHREADS, SMEM_DYN>>>(h, wtq, qkv_b, nullptr, qk, vt, M, CDIM, C3);
    // 3. attention
    attn_tc<<<dim3((SEQ + 127) / 128, NHEAD, BATCH), 256, ATT_SMEM>>>(qk, vt, attn);
    // 4. x1 = x + attn @ proj_w + proj_b
    gemm_mma<1><<<dim3(CDIM / GBN, gy), GTHREADS, SMEM_DYN>>>(attn, wtp, proj_b, x, x1, nullptr, M, CDIM, CDIM);
    // 5. LN2
    ln_kernel<<<M, 256>>>(x1, ln2_g, ln2_b, h);
    // 6. ff = gelu(h @ fc1_w + fc1_b)
    gemm_mma<2><<<dim3(DFF / GBN, gy), GTHREADS, SMEM_DYN>>>(h, wt1, fc1_b, nullptr, ff, nullptr, M, CDIM, DFF);
    // 7. out = x1 + ff @ fc2_w + fc2_b
    gemm_mma<1><<<dim3(CDIM / GBN, gy), GTHREADS, SMEM_DYN>>>(ff, wt2, fc2_b, x1, out, nullptr, M, DFF, CDIM);
}

// round 13
// speedup vs baseline: 6.0055x; 1.0603x over previous
#include <cuda_runtime.h>
#include <cuda_fp16.h>
#include <cstdint>
#include <math.h>

// ---------------- problem constants ----------------
#define BATCH 32
#define SEQ   577
#define CDIM  768
#define NHEAD 12
#define DHEAD 64
#define DFF   3072
#define MROWS (BATCH*SEQ)          // 18464
#define C3    2304
#define QKW   1536                 // row width of g_qk (Q|K)
#define SEQP  640                  // padded seq for transposed V

// ---------------- scratch (device globals; no allocation) ----------------
__device__ __align__(256) __half g_h   [(size_t)MROWS * CDIM];
__device__ __align__(256) __half g_qk  [(size_t)MROWS * QKW];
__device__ __align__(256) __half g_vt  [(size_t)BATCH * NHEAD * DHEAD * SEQP];
__device__ __align__(256) __half g_attn[(size_t)MROWS * CDIM];
__device__ __align__(256) float  g_x1  [(size_t)MROWS * CDIM];
__device__ __align__(256) __half g_ff  [(size_t)MROWS * DFF];
__device__ __align__(256) __half g_wt_qkv [(size_t)C3   * CDIM];
__device__ __align__(256) __half g_wt_proj[(size_t)CDIM * CDIM];
__device__ __align__(256) __half g_wt_fc1 [(size_t)DFF  * CDIM];
__device__ __align__(256) __half g_wt_fc2 [(size_t)CDIM * DFF];

// ---------------- helpers ----------------
static __device__ __forceinline__ uint32_t smem_u32(const void* p) {
    uint32_t a;
    asm("{ .reg .u64 t; cvta.to.shared.u64 t, %1; cvt.u32.u64 %0, t; }" : "=r"(a) : "l"(p));
    return a;
}
static __device__ __forceinline__ void cp_async16(uint32_t dst, const void* src) {
    asm volatile("cp.async.cg.shared.global [%0], [%1], 16;" :: "r"(dst), "l"(src));
}
static __device__ __forceinline__ void cp_async16z(uint32_t dst, const void* src, int sz) {
    asm volatile("cp.async.cg.shared.global [%0], [%1], 16, %2;" :: "r"(dst), "l"(src), "r"(sz));
}
static __device__ __forceinline__ void mma_f16(
    float* d, uint32_t a0, uint32_t a1, uint32_t a2, uint32_t a3,
    uint32_t b0, uint32_t b1)
{
    asm volatile(
        "mma.sync.aligned.m16n8k16.row.col.f32.f16.f16.f32 "
        "{%0,%1,%2,%3}, {%4,%5,%6,%7}, {%8,%9}, {%0,%1,%2,%3};"
        : "+f"(d[0]), "+f"(d[1]), "+f"(d[2]), "+f"(d[3])
        : "r"(a0), "r"(a1), "r"(a2), "r"(a3), "r"(b0), "r"(b1));
}
static __device__ __forceinline__ void ldsm_x4(
    uint32_t& r0, uint32_t& r1, uint32_t& r2, uint32_t& r3, uint32_t addr)
{
    asm volatile("ldmatrix.sync.aligned.m8n8.x4.shared.b16 {%0,%1,%2,%3}, [%4];"
                 : "=r"(r0), "=r"(r1), "=r"(r2), "=r"(r3) : "r"(addr));
}

// ---------------- LayerNorm body (shared by prep + standalone) ----------------
static __device__ __forceinline__ void ln_body(
    const float* __restrict__ x, const float* __restrict__ g,
    const float* __restrict__ b, __half* __restrict__ out,
    int row, int tid, float* red)
{
    const float* xr = x + (size_t)row * CDIM;
    float v0 = xr[tid], v1 = xr[tid + 256], v2 = xr[tid + 512];

    float s = v0 + v1 + v2;
    #pragma unroll
    for (int o = 16; o > 0; o >>= 1) s += __shfl_xor_sync(0xffffffffu, s, o);
    if ((tid & 31) == 0) red[tid >> 5] = s;
    __syncthreads();
    if (tid == 0) {
        float t = 0.f;
        #pragma unroll
        for (int w = 0; w < 8; ++w) t += red[w];
        red[0] = t;
    }
    __syncthreads();
    const float mean = red[0] * (1.0f / CDIM);
    __syncthreads();

    float d0 = v0 - mean, d1 = v1 - mean, d2 = v2 - mean;
    float sq = d0 * d0 + d1 * d1 + d2 * d2;
    #pragma unroll
    for (int o = 16; o > 0; o >>= 1) sq += __shfl_xor_sync(0xffffffffu, sq, o);
    if ((tid & 31) == 0) red[tid >> 5] = sq;
    __syncthreads();
    if (tid == 0) {
        float t = 0.f;
        #pragma unroll
        for (int w = 0; w < 8; ++w) t += red[w];
        red[0] = t;
    }
    __syncthreads();
    const float var = red[0] * (1.0f / CDIM);
    const float rstd = rsqrtf(var + 1e-5f);

    __half* outr = out + (size_t)row * CDIM;
    outr[tid]       = __float2half_rn(d0 * rstd * g[tid]       + b[tid]);
    outr[tid + 256] = __float2half_rn(d1 * rstd * g[tid + 256] + b[tid + 256]);
    outr[tid + 512] = __float2half_rn(d2 * rstd * g[tid + 512] + b[tid + 512]);
}

__global__ void __launch_bounds__(256) ln_kernel(
    const float* __restrict__ x, const float* __restrict__ g,
    const float* __restrict__ b, __half* __restrict__ out)
{
    __shared__ float red[8];
    ln_body(x, g, b, out, blockIdx.x, threadIdx.x, red);
}

// ---------------- merged prep: LN1 + 4 weight transposes + V-tail zero -------------
__global__ void __launch_bounds__(256) prep_kernel(
    const float* __restrict__ x, const float* __restrict__ ln1_g,
    const float* __restrict__ ln1_b,
    const float* __restrict__ qkv_w, const float* __restrict__ proj_w,
    const float* __restrict__ fc1_w, const float* __restrict__ fc2_w)
{
    __shared__ float tb[32][33];
    __shared__ float red[8];
    int bid = blockIdx.x;
    const int tid = threadIdx.y * 32 + threadIdx.x;

    if (bid < MROWS) {
        ln_body(x, ln1_g, ln1_b, g_h, bid, tid, red);
        return;
    }
    bid -= MROWS;

    if (bid >= 6912) {
        __half* vt = g_vt + (size_t)(bid - 6912) * DHEAD * SEQP;
        const uint4 z = make_uint4(0u, 0u, 0u, 0u);
        #pragma unroll
        for (int i = 0; i < 4; ++i) {
            int f = i * 256 + tid;
            int d = f >> 4, u = f & 15;
            *(uint4*)(vt + (size_t)d * SEQP + 512 + u * 8) = z;
        }
        return;
    }
    const float* W; __half* Wt; int K, N;
    if (bid < 1728)      { W = qkv_w;  Wt = g_wt_qkv;  K = CDIM; N = C3;  }
    else if (bid < 2304) { W = proj_w; Wt = g_wt_proj; K = CDIM; N = CDIM; bid -= 1728; }
    else if (bid < 4608) { W = fc1_w;  Wt = g_wt_fc1;  K = CDIM; N = DFF;  bid -= 2304; }
    else                 { W = fc2_w;  Wt = g_wt_fc2;  K = DFF;  N = CDIM; bid -= 4608; }

    const int nbx = K >> 5;
    const int k0 = (bid % nbx) * 32, n0 = (bid / nbx) * 32;
    #pragma unroll
    for (int i = threadIdx.y; i < 32; i += 8)
        tb[i][threadIdx.x] = W[(size_t)(k0 + i) * N + n0 + threadIdx.x];
    __syncthreads();
    #pragma unroll
    for (int i = threadIdx.y; i < 32; i += 8)
        Wt[(size_t)(n0 + i) * K + k0 + threadIdx.x] = __float2half_rn(tb[threadIdx.x][i]);
}

// ---------------- fp16 HMMA GEMM: 512 thr, 16 warps 32x64, K=128 stages, 2-stage ---
#define GBM 128
#define GBN 256
#define GPH 136                            // halfs per smem row (128 + 8 pad); 272B stride
#define GSTG_BYTES ((128 + 256) * GPH * 2) // 104448
#define GSMEM_DYN (2 * GSTG_BYTES)         // 208896
#define GTHREADS 512

__device__ __forceinline__ void load_stage(
    uint32_t sb, const __half* __restrict__ A, const __half* __restrict__ Wt,
    int bm, int bn, int M, int K, int kc, int tid)
{
    // A tile: 128 rows x 128 halfs
    #pragma unroll
    for (int i = 0; i < 4; ++i) {
        int f = i * GTHREADS + tid;
        int r = f >> 4, q = f & 15;
        int rr = bm + r;
        int sz = (rr < M) ? 16 : 0;
        if (rr >= M) rr = M - 1;
        cp_async16z(sb + (uint32_t)(r * (GPH * 2) + q * 16),
                    A + (size_t)rr * K + kc + q * 8, sz);
    }
    // B tile: 256 rows x 128 halfs
    const uint32_t bb = sb + 128 * (GPH * 2);
    #pragma unroll
    for (int i = 0; i < 8; ++i) {
        int f = i * GTHREADS + tid;
        int r = f >> 4, q = f & 15;
        cp_async16(bb + (uint32_t)(r * (GPH * 2) + q * 16),
                   Wt + (size_t)(bn + r) * K + kc + q * 8);
    }
    asm volatile("cp.async.commit_group;" ::: "memory");
}

template <int EPI>
__global__ void __launch_bounds__(GTHREADS, 1) gemm_mma(
    const __half* __restrict__ A, const __half* __restrict__ Wt,
    const float* __restrict__ bias, const float* __restrict__ res,
    void* __restrict__ outp, __half* __restrict__ vt,
    int M, int K, int N)
{
    extern __shared__ __align__(16) char dsm[];
    const uint32_t sbase = smem_u32(dsm);

    const int tid  = threadIdx.x;
    const int wid  = tid >> 5;
    const int lane = tid & 31;
    const int g = lane >> 2, t = lane & 3;
    const int bm = blockIdx.y * GBM;
    const int bn = blockIdx.x * GBN;
    const int wm = (wid >> 2) * 32;       // 4 warp-rows of 32
    const int wn = (wid & 3) * 64;        // 4 warp-cols of 64

    const int l15 = lane & 15;
    const int lhi = lane >> 4;
    const uint32_t aoff = (uint32_t)(((wm + l15) * GPH + lhi * 8) * 2);
    const int l7 = lane & 7;
    const int q2 = lane >> 3;
    const uint32_t boff = (uint32_t)(((wn + (q2 >> 1) * 8 + l7) * GPH + (q2 & 1) * 8) * 2);

    float acc[2][8][4];
    #pragma unroll
    for (int mt = 0; mt < 2; ++mt)
        #pragma unroll
        for (int nt = 0; nt < 8; ++nt)
            #pragma unroll
            for (int j = 0; j < 4; ++j) acc[mt][nt][j] = 0.f;

    const int KT = K >> 7;                // 128-half chunks (768->6, 3072->24)

    load_stage(sbase, A, Wt, bm, bn, M, K, 0, tid);

    for (int kt = 0; kt < KT; ++kt) {
        asm volatile("cp.async.wait_group 0;" ::: "memory");
        __syncthreads();

        if (kt + 1 < KT)
            load_stage(sbase + (uint32_t)(((kt + 1) & 1) * GSTG_BYTES),
                       A, Wt, bm, bn, M, K, (kt + 1) * 128, tid);

        const uint32_t sA_u = sbase + (uint32_t)((kt & 1) * GSTG_BYTES);
        const uint32_t sB_u = sA_u + 128 * (GPH * 2);

        #pragma unroll
        for (int k16 = 0; k16 < 8; ++k16) {
            uint32_t bf[8][2];
            #pragma unroll
            for (int ntp = 0; ntp < 4; ++ntp) {
                uint32_t r0, r1, r2, r3;
                ldsm_x4(r0, r1, r2, r3,
                        sB_u + boff + (uint32_t)(ntp * 16 * GPH * 2 + k16 * 32));
                bf[2 * ntp][0] = r0; bf[2 * ntp][1] = r1;
                bf[2 * ntp + 1][0] = r2; bf[2 * ntp + 1][1] = r3;
            }
            #pragma unroll
            for (int mt = 0; mt < 2; ++mt) {
                uint32_t a0, a1, a2, a3;
                ldsm_x4(a0, a1, a2, a3,
                        sA_u + aoff + (uint32_t)(mt * 16 * GPH * 2 + k16 * 32));
                #pragma unroll
                for (int nt = 0; nt < 8; ++nt)
                    mma_f16(acc[mt][nt], a0, a1, a2, a3, bf[nt][0], bf[nt][1]);
            }
        }
    }

    // ---- epilogue ----
    #pragma unroll
    for (int nt = 0; nt < 8; ++nt) {
        const int c = bn + wn + nt * 8 + 2 * t;
        const float2 bia = *(const float2*)&bias[c];
        #pragma unroll
        for (int mt = 0; mt < 2; ++mt) {
            const int r0 = bm + wm + mt * 16 + g;
            const int r1 = r0 + 8;
            float v0 = acc[mt][nt][0] + bia.x;
            float v1 = acc[mt][nt][1] + bia.y;
            float v2 = acc[mt][nt][2] + bia.x;
            float v3 = acc[mt][nt][3] + bia.y;

            if (EPI == 0) {
                if (c < QKW) {
                    __half* qk = (__half*)outp;
                    if (r0 < M) *(__half2*)&qk[(size_t)r0 * QKW + c] = __floats2half2_rn(v0, v1);
                    if (r1 < M) *(__half2*)&qk[(size_t)r1 * QKW + c] = __floats2half2_rn(v2, v3);
                } else {
                    const int cc = c - QKW;
                    const int hh = cc >> 6, dd = cc & 63;
                    if (r0 < M) {
                        int bb = r0 / SEQ, n = r0 - bb * SEQ;
                        __half* p = vt + ((size_t)(bb * NHEAD + hh) * DHEAD + dd) * SEQP + n;
                        p[0]    = __float2half_rn(v0);
                        p[SEQP] = __float2half_rn(v1);
                    }
                    if (r1 < M) {
                        int bb = r1 / SEQ, n = r1 - bb * SEQ;
                        __half* p = vt + ((size_t)(bb * NHEAD + hh) * DHEAD + dd) * SEQP + n;
                        p[0]    = __float2half_rn(v2);
                        p[SEQP] = __float2half_rn(v3);
                    }
                }
            } else if (EPI == 1) {
                float* out = (float*)outp;
                if (r0 < M) {
                    float2 rv = *(const float2*)&res[(size_t)r0 * N + c];
                    *(float2*)&out[(size_t)r0 * N + c] = make_float2(v0 + rv.x, v1 + rv.y);
                }
                if (r1 < M) {
                    float2 rv = *(const float2*)&res[(size_t)r1 * N + c];
                    *(float2*)&out[(size_t)r1 * N + c] = make_float2(v2 + rv.x, v3 + rv.y);
                }
            } else {
                __half* out = (__half*)outp;
                v0 = 0.5f * v0 * (1.0f + erff(v0 * 0.70710678118654752f));
                v1 = 0.5f * v1 * (1.0f + erff(v1 * 0.70710678118654752f));
                v2 = 0.5f * v2 * (1.0f + erff(v2 * 0.70710678118654752f));
                v3 = 0.5f * v3 * (1.0f + erff(v3 * 0.70710678118654752f));
                if (r0 < M) *(__half2*)&out[(size_t)r0 * N + c] = __floats2half2_rn(v0, v1);
                if (r1 < M) *(__half2*)&out[(size_t)r1 * N + c] = __floats2half2_rn(v2, v3);
            }
        }
    }
}

// ---------------- fp16 flash attention: no-max softmax, register P -----------------
#define PH 72
#define OQ 0
#define OK (128 * PH)
#define OV (OK + 2 * 64 * PH)
#define ATT_SMEM ((OV + 2 * 64 * PH) * 2)
#define NKT 10

__global__ void __launch_bounds__(256) attn_tc(
    const __half* __restrict__ qk, const __half* __restrict__ vt,
    __half* __restrict__ outa)
{
    extern __shared__ __align__(16) char sm[];
    const uint32_t sbase = smem_u32(sm);

    const int qt = blockIdx.x;
    const int h  = blockIdx.y;
    const int b  = blockIdx.z;
    const int tid  = threadIdx.x;
    const int wid  = tid >> 5;
    const int lane = tid & 31;
    const int g = lane >> 2, t = lane & 3;
    const int wr = wid * 16;
    const size_t browbase = (size_t)b * SEQ;
    const __half* qbase = qk + browbase * QKW + h * DHEAD;
    const __half* vbase = vt + (size_t)(b * NHEAD + h) * DHEAD * SEQP;

    const int l15 = lane & 15;
    const int lhi = lane >> 4;
    const uint32_t aoff = (uint32_t)(((wr + l15) * PH + lhi * 8) * 2);
    const int l7 = lane & 7;
    const int q2 = lane >> 3;
    const uint32_t boff = (uint32_t)((((q2 >> 1) * 8 + l7) * PH + (q2 & 1) * 8) * 2);

    #pragma unroll
    for (int i = 0; i < 4; ++i) {
        int f = i * 256 + tid;
        int r = f >> 3, q = f & 7;
        int n = qt * 128 + r;
        int sz = (n < SEQ) ? 16 : 0;
        if (n >= SEQ) n = SEQ - 1;
        cp_async16z(sbase + (uint32_t)((OQ + r * PH + q * 8) * 2),
                    qbase + (size_t)n * QKW + q * 8, sz);
    }
    #pragma unroll
    for (int i = 0; i < 2; ++i) {
        int f = i * 256 + tid;
        int r = f >> 3, q = f & 7;
        cp_async16(sbase + (uint32_t)((OK + r * PH + q * 8) * 2),
                   qbase + (size_t)r * QKW + CDIM + q * 8);
        cp_async16(sbase + (uint32_t)((OV + r * PH + q * 8) * 2),
                   vbase + (size_t)r * SEQP + q * 8);
    }
    asm volatile("cp.async.commit_group;" ::: "memory");

    float oacc[8][4];
    #pragma unroll
    for (int nt = 0; nt < 8; ++nt)
        #pragma unroll
        for (int j = 0; j < 4; ++j) oacc[nt][j] = 0.f;
    float l0 = 0.f, l1 = 0.f;

    for (int kt = 0; kt < NKT; ++kt) {
        const int buf = kt & 1;
        if (kt > 0) __syncthreads();
        if (kt + 1 < NKT) {
            const int nbuf = (kt + 1) & 1;
            #pragma unroll
            for (int i = 0; i < 2; ++i) {
                int f = i * 256 + tid;
                int r = f >> 3, q = f & 7;
                int kk = (kt + 1) * 64 + r;
                int sz = (kk < SEQ) ? 16 : 0;
                if (kk >= SEQ) kk = SEQ - 1;
                cp_async16z(sbase + (uint32_t)((OK + (nbuf * 64 + r) * PH + q * 8) * 2),
                            qbase + (size_t)kk * QKW + CDIM + q * 8, sz);
                cp_async16(sbase + (uint32_t)((OV + (nbuf * 64 + r) * PH + q * 8) * 2),
                           vbase + (size_t)r * SEQP + (kt + 1) * 64 + q * 8);
            }
        }
        asm volatile("cp.async.commit_group;" ::: "memory");
        asm volatile("cp.async.wait_group 1;" ::: "memory");
        __syncthreads();

        const uint32_t Qu = sbase + OQ * 2;
        const uint32_t Ku = sbase + (OK + buf * 64 * PH) * 2;
        const uint32_t Vu = sbase + (OV + buf * 64 * PH) * 2;

        float sacc[8][4];
        #pragma unroll
        for (int nt = 0; nt < 8; ++nt)
            #pragma unroll
            for (int j = 0; j < 4; ++j) sacc[nt][j] = 0.f;

        #pragma unroll
        for (int k16 = 0; k16 < 4; ++k16) {
            uint32_t a0, a1, a2, a3;
            ldsm_x4(a0, a1, a2, a3, Qu + aoff + (uint32_t)(k16 * 32));
            #pragma unroll
            for (int ntp = 0; ntp < 4; ++ntp) {
                uint32_t b0, b1, b2, b3;
                ldsm_x4(b0, b1, b2, b3,
                        Ku + boff + (uint32_t)(ntp * 16 * PH * 2 + k16 * 32));
                mma_f16(sacc[2 * ntp],     a0, a1, a2, a3, b0, b1);
                mma_f16(sacc[2 * ntp + 1], a0, a1, a2, a3, b2, b3);
            }
        }

        const int kb0 = kt * 64;
        uint32_t pfrag[4][4];
        #pragma unroll
        for (int nt = 0; nt < 8; ++nt) {
            const int c0 = kb0 + nt * 8 + 2 * t;
            float p0 = (c0     < SEQ) ? __expf(sacc[nt][0] * 0.125f) : 0.f;
            float p1 = (c0 + 1 < SEQ) ? __expf(sacc[nt][1] * 0.125f) : 0.f;
            float p2 = (c0     < SEQ) ? __expf(sacc[nt][2] * 0.125f) : 0.f;
            float p3 = (c0 + 1 < SEQ) ? __expf(sacc[nt][3] * 0.125f) : 0.f;
            l0 += p0 + p1; l1 += p2 + p3;
            __half2 h01 = __floats2half2_rn(p0, p1);
            __half2 h23 = __floats2half2_rn(p2, p3);
            const int k16i = nt >> 1, hi = nt & 1;
            pfrag[k16i][2 * hi]     = *(uint32_t*)&h01;
            pfrag[k16i][2 * hi + 1] = *(uint32_t*)&h23;
        }

        #pragma unroll
        for (int k16 = 0; k16 < 4; ++k16) {
            #pragma unroll
            for (int ntp = 0; ntp < 4; ++ntp) {
                uint32_t b0, b1, b2, b3;
                ldsm_x4(b0, b1, b2, b3,
                        Vu + boff + (uint32_t)(ntp * 16 * PH * 2 + k16 * 32));
                mma_f16(oacc[2 * ntp],     pfrag[k16][0], pfrag[k16][1],
                        pfrag[k16][2], pfrag[k16][3], b0, b1);
                mma_f16(oacc[2 * ntp + 1], pfrag[k16][0], pfrag[k16][1],
                        pfrag[k16][2], pfrag[k16][3], b2, b3);
            }
        }
    }

    l0 += __shfl_xor_sync(0xffffffffu, l0, 1);
    l0 += __shfl_xor_sync(0xffffffffu, l0, 2);
    l1 += __shfl_xor_sync(0xffffffffu, l1, 1);
    l1 += __shfl_xor_sync(0xffffffffu, l1, 2);

    const float inv0 = 1.0f / l0, inv1 = 1.0f / l1;
    const int r0 = qt * 128 + wr + g;
    const int r1 = r0 + 8;
    #pragma unroll
    for (int nt = 0; nt < 8; ++nt) {
        const int col = h * DHEAD + nt * 8 + 2 * t;
        if (r0 < SEQ)
            *(__half2*)&outa[(browbase + r0) * CDIM + col] =
                __floats2half2_rn(oacc[nt][0] * inv0, oacc[nt][1] * inv0);
        if (r1 < SEQ)
            *(__half2*)&outa[(browbase + r1) * CDIM + col] =
                __floats2half2_rn(oacc[nt][2] * inv1, oacc[nt][3] * inv1);
    }
}

// ---------------- launcher ----------------
extern "C" void kernel_launch(void* const* d_in, const int* in_sizes, int n_in,
                              void* d_out, int out_size)
{
    const float* x      = (const float*)d_in[0];
    const float* ln1_g  = (const float*)d_in[1];
    const float* ln1_b  = (const float*)d_in[2];
    const float* ln2_g  = (const float*)d_in[3];
    const float* ln2_b  = (const float*)d_in[4];
    const float* qkv_w  = (const float*)d_in[5];
    const float* qkv_b  = (const float*)d_in[6];
    const float* proj_w = (const float*)d_in[7];
    const float* proj_b = (const float*)d_in[8];
    const float* fc1_w  = (const float*)d_in[9];
    const float* fc1_b  = (const float*)d_in[10];
    const float* fc2_w  = (const float*)d_in[11];
    const float* fc2_b  = (const float*)d_in[12];
    float* out = (float*)d_out;

    __half *h, *qk, *vt, *attn, *ff, *wtq, *wtp, *wt1, *wt2;
    float *x1;
    cudaGetSymbolAddress((void**)&h,    g_h);
    cudaGetSymbolAddress((void**)&qk,   g_qk);
    cudaGetSymbolAddress((void**)&vt,   g_vt);
    cudaGetSymbolAddress((void**)&attn, g_attn);
    cudaGetSymbolAddress((void**)&x1,   g_x1);
    cudaGetSymbolAddress((void**)&ff,   g_ff);
    cudaGetSymbolAddress((void**)&wtq,  g_wt_qkv);
    cudaGetSymbolAddress((void**)&wtp,  g_wt_proj);
    cudaGetSymbolAddress((void**)&wt1,  g_wt_fc1);
    cudaGetSymbolAddress((void**)&wt2,  g_wt_fc2);

    cudaFuncSetAttribute(gemm_mma<0>, cudaFuncAttributeMaxDynamicSharedMemorySize, GSMEM_DYN);
    cudaFuncSetAttribute(gemm_mma<1>, cudaFuncAttributeMaxDynamicSharedMemorySize, GSMEM_DYN);
    cudaFuncSetAttribute(gemm_mma<2>, cudaFuncAttributeMaxDynamicSharedMemorySize, GSMEM_DYN);
    cudaFuncSetAttribute(attn_tc,     cudaFuncAttributeMaxDynamicSharedMemorySize, ATT_SMEM);

    const int M  = MROWS;
    const int gy = (M + GBM - 1) / GBM;     // 145

    prep_kernel<<<MROWS + 7296, dim3(32, 8)>>>(x, ln1_g, ln1_b, qkv_w, proj_w, fc1_w, fc2_w);

    // 2. QKV (Q,K natural; V transposed)
    gemm_mma<0><<<dim3(C3 / GBN, gy), GTHREADS, GSMEM_DYN>>>(h, wtq, qkv_b, nullptr, qk, vt, M, CDIM, C3);
    // 3. attention
    attn_tc<<<dim3((SEQ + 127) / 128, NHEAD, BATCH), 256, ATT_SMEM>>>(qk, vt, attn);
    // 4. x1 = x + attn @ proj_w + proj_b
    gemm_mma<1><<<dim3(CDIM / GBN, gy), GTHREADS, GSMEM_DYN>>>(attn, wtp, proj_b, x, x1, nullptr, M, CDIM, CDIM);
    // 5. LN2
    ln_kernel<<<M, 256>>>(x1, ln2_g, ln2_b, h);
    // 6. ff = gelu(h @ fc1_w + fc1_b)
    gemm_mma<2><<<dim3(DFF / GBN, gy), GTHREADS, GSMEM_DYN>>>(h, wt1, fc1_b, nullptr, ff, nullptr, M, CDIM, DFF);
    // 7. out = x1 + ff @ fc2_w + fc2_b
    gemm_mma<1><<<dim3(CDIM / GBN, gy), GTHREADS, GSMEM_DYN>>>(ff, wt2, fc2_b, x1, out, nullptr, M, DFF, CDIM);
}

// round 14
// speedup vs baseline: 6.0970x; 1.0152x over previous
#include <cuda_runtime.h>
#include <cuda_fp16.h>
#include <cstdint>
#include <math.h>

// ---------------- problem constants ----------------
#define BATCH 32
#define SEQ   577
#define CDIM  768
#define NHEAD 12
#define DHEAD 64
#define DFF   3072
#define MROWS (BATCH*SEQ)          // 18464
#define C3    2304
#define QKW   1536                 // row width of g_qk (Q|K)
#define SEQP  640                  // padded seq for transposed V

// ---------------- scratch (device globals; no allocation) ----------------
__device__ __align__(256) __half g_h   [(size_t)MROWS * CDIM];
__device__ __align__(256) __half g_qk  [(size_t)MROWS * QKW];
__device__ __align__(256) __half g_vt  [(size_t)BATCH * NHEAD * DHEAD * SEQP];
__device__ __align__(256) __half g_attn[(size_t)MROWS * CDIM];
__device__ __align__(256) __half g_x1h [(size_t)MROWS * CDIM];
__device__ __align__(256) __half g_ff  [(size_t)MROWS * DFF];
__device__ __align__(256) __half g_wt_qkv [(size_t)C3   * CDIM];
__device__ __align__(256) __half g_wt_proj[(size_t)CDIM * CDIM];
__device__ __align__(256) __half g_wt_fc1 [(size_t)DFF  * CDIM];
__device__ __align__(256) __half g_wt_fc2 [(size_t)CDIM * DFF];

// ---------------- helpers ----------------
static __device__ __forceinline__ uint32_t smem_u32(const void* p) {
    uint32_t a;
    asm("{ .reg .u64 t; cvta.to.shared.u64 t, %1; cvt.u32.u64 %0, t; }" : "=r"(a) : "l"(p));
    return a;
}
static __device__ __forceinline__ void cp_async16(uint32_t dst, const void* src) {
    asm volatile("cp.async.cg.shared.global [%0], [%1], 16;" :: "r"(dst), "l"(src));
}
static __device__ __forceinline__ void cp_async16z(uint32_t dst, const void* src, int sz) {
    asm volatile("cp.async.cg.shared.global [%0], [%1], 16, %2;" :: "r"(dst), "l"(src), "r"(sz));
}
static __device__ __forceinline__ void mma_f16(
    float* d, uint32_t a0, uint32_t a1, uint32_t a2, uint32_t a3,
    uint32_t b0, uint32_t b1)
{
    asm volatile(
        "mma.sync.aligned.m16n8k16.row.col.f32.f16.f16.f32 "
        "{%0,%1,%2,%3}, {%4,%5,%6,%7}, {%8,%9}, {%0,%1,%2,%3};"
        : "+f"(d[0]), "+f"(d[1]), "+f"(d[2]), "+f"(d[3])
        : "r"(a0), "r"(a1), "r"(a2), "r"(a3), "r"(b0), "r"(b1));
}
static __device__ __forceinline__ void ldsm_x4(
    uint32_t& r0, uint32_t& r1, uint32_t& r2, uint32_t& r3, uint32_t addr)
{
    asm volatile("ldmatrix.sync.aligned.m8n8.x4.shared.b16 {%0,%1,%2,%3}, [%4];"
                 : "=r"(r0), "=r"(r1), "=r"(r2), "=r"(r3) : "r"(addr));
}
static __device__ __forceinline__ float ldf(const float* p)  { return *p; }
static __device__ __forceinline__ float ldf(const __half* p) { return __half2float(*p); }

// ---------------- LayerNorm body (templated input dtype) ----------------
template <typename T>
static __device__ __forceinline__ void ln_body(
    const T* __restrict__ x, const float* __restrict__ g,
    const float* __restrict__ b, __half* __restrict__ out,
    int row, int tid, float* red)
{
    const T* xr = x + (size_t)row * CDIM;
    float v0 = ldf(xr + tid), v1 = ldf(xr + tid + 256), v2 = ldf(xr + tid + 512);

    float s = v0 + v1 + v2;
    #pragma unroll
    for (int o = 16; o > 0; o >>= 1) s += __shfl_xor_sync(0xffffffffu, s, o);
    if ((tid & 31) == 0) red[tid >> 5] = s;
    __syncthreads();
    if (tid == 0) {
        float t = 0.f;
        #pragma unroll
        for (int w = 0; w < 8; ++w) t += red[w];
        red[0] = t;
    }
    __syncthreads();
    const float mean = red[0] * (1.0f / CDIM);
    __syncthreads();

    float d0 = v0 - mean, d1 = v1 - mean, d2 = v2 - mean;
    float sq = d0 * d0 + d1 * d1 + d2 * d2;
    #pragma unroll
    for (int o = 16; o > 0; o >>= 1) sq += __shfl_xor_sync(0xffffffffu, sq, o);
    if ((tid & 31) == 0) red[tid >> 5] = sq;
    __syncthreads();
    if (tid == 0) {
        float t = 0.f;
        #pragma unroll
        for (int w = 0; w < 8; ++w) t += red[w];
        red[0] = t;
    }
    __syncthreads();
    const float var = red[0] * (1.0f / CDIM);
    const float rstd = rsqrtf(var + 1e-5f);

    __half* outr = out + (size_t)row * CDIM;
    outr[tid]       = __float2half_rn(d0 * rstd * g[tid]       + b[tid]);
    outr[tid + 256] = __float2half_rn(d1 * rstd * g[tid + 256] + b[tid + 256]);
    outr[tid + 512] = __float2half_rn(d2 * rstd * g[tid + 512] + b[tid + 512]);
}

__global__ void __launch_bounds__(256) ln_kernel_h(
    const __half* __restrict__ x, const float* __restrict__ g,
    const float* __restrict__ b, __half* __restrict__ out)
{
    __shared__ float red[8];
    ln_body(x, g, b, out, blockIdx.x, threadIdx.x, red);
}

// ---------------- merged prep: LN1 + 4 weight transposes + V-tail zero -------------
__global__ void __launch_bounds__(256) prep_kernel(
    const float* __restrict__ x, const float* __restrict__ ln1_g,
    const float* __restrict__ ln1_b,
    const float* __restrict__ qkv_w, const float* __restrict__ proj_w,
    const float* __restrict__ fc1_w, const float* __restrict__ fc2_w)
{
    __shared__ float tb[32][33];
    __shared__ float red[8];
    int bid = blockIdx.x;
    const int tid = threadIdx.y * 32 + threadIdx.x;

    if (bid < MROWS) {
        ln_body(x, ln1_g, ln1_b, g_h, bid, tid, red);
        return;
    }
    bid -= MROWS;

    if (bid >= 6912) {
        __half* vt = g_vt + (size_t)(bid - 6912) * DHEAD * SEQP;
        const uint4 z = make_uint4(0u, 0u, 0u, 0u);
        #pragma unroll
        for (int i = 0; i < 4; ++i) {
            int f = i * 256 + tid;
            int d = f >> 4, u = f & 15;
            *(uint4*)(vt + (size_t)d * SEQP + 512 + u * 8) = z;
        }
        return;
    }
    const float* W; __half* Wt; int K, N;
    if (bid < 1728)      { W = qkv_w;  Wt = g_wt_qkv;  K = CDIM; N = C3;  }
    else if (bid < 2304) { W = proj_w; Wt = g_wt_proj; K = CDIM; N = CDIM; bid -= 1728; }
    else if (bid < 4608) { W = fc1_w;  Wt = g_wt_fc1;  K = CDIM; N = DFF;  bid -= 2304; }
    else                 { W = fc2_w;  Wt = g_wt_fc2;  K = DFF;  N = CDIM; bid -= 4608; }

    const int nbx = K >> 5;
    const int k0 = (bid % nbx) * 32, n0 = (bid / nbx) * 32;
    #pragma unroll
    for (int i = threadIdx.y; i < 32; i += 8)
        tb[i][threadIdx.x] = W[(size_t)(k0 + i) * N + n0 + threadIdx.x];
    __syncthreads();
    #pragma unroll
    for (int i = threadIdx.y; i < 32; i += 8)
        Wt[(size_t)(n0 + i) * K + k0 + threadIdx.x] = __float2half_rn(tb[threadIdx.x][i]);
}

// ---------------- fp16 HMMA GEMM: 512 thr, 16 warps 32x64, K=128 stages, 2-stage ---
// EPI 0: qkv (Q,K -> g_qk; V -> g_vt transposed)
// EPI 1: bias + f32 residual -> half out  (proj -> x1h)
// EPI 2: bias + exact GELU -> half out    (fc1)
// EPI 3: bias + half residual -> f32 out  (fc2 -> final)
#define GBM 128
#define GBN 256
#define GPH 136                            // halfs per smem row (128 + 8 pad); 272B stride
#define GSTG_BYTES ((128 + 256) * GPH * 2) // 104448
#define GSMEM_DYN (2 * GSTG_BYTES)         // 208896
#define GTHREADS 512

__device__ __forceinline__ void load_stage(
    uint32_t sb, const __half* __restrict__ A, const __half* __restrict__ Wt,
    int bm, int bn, int M, int K, int kc, int tid)
{
    #pragma unroll
    for (int i = 0; i < 4; ++i) {
        int f = i * GTHREADS + tid;
        int r = f >> 4, q = f & 15;
        int rr = bm + r;
        int sz = (rr < M) ? 16 : 0;
        if (rr >= M) rr = M - 1;
        cp_async16z(sb + (uint32_t)(r * (GPH * 2) + q * 16),
                    A + (size_t)rr * K + kc + q * 8, sz);
    }
    const uint32_t bb = sb + 128 * (GPH * 2);
    #pragma unroll
    for (int i = 0; i < 8; ++i) {
        int f = i * GTHREADS + tid;
        int r = f >> 4, q = f & 15;
        cp_async16(bb + (uint32_t)(r * (GPH * 2) + q * 16),
                   Wt + (size_t)(bn + r) * K + kc + q * 8);
    }
    asm volatile("cp.async.commit_group;" ::: "memory");
}

template <int EPI>
__global__ void __launch_bounds__(GTHREADS, 1) gemm_mma(
    const __half* __restrict__ A, const __half* __restrict__ Wt,
    const float* __restrict__ bias, const void* __restrict__ resv,
    void* __restrict__ outp, __half* __restrict__ vt,
    int M, int K, int N)
{
    extern __shared__ __align__(16) char dsm[];
    const uint32_t sbase = smem_u32(dsm);

    const int tid  = threadIdx.x;
    const int wid  = tid >> 5;
    const int lane = tid & 31;
    const int g = lane >> 2, t = lane & 3;
    const int bm = blockIdx.y * GBM;
    const int bn = blockIdx.x * GBN;
    const int wm = (wid >> 2) * 32;
    const int wn = (wid & 3) * 64;

    const int l15 = lane & 15;
    const int lhi = lane >> 4;
    const uint32_t aoff = (uint32_t)(((wm + l15) * GPH + lhi * 8) * 2);
    const int l7 = lane & 7;
    const int q2 = lane >> 3;
    const uint32_t boff = (uint32_t)(((wn + (q2 >> 1) * 8 + l7) * GPH + (q2 & 1) * 8) * 2);

    float acc[2][8][4];
    #pragma unroll
    for (int mt = 0; mt < 2; ++mt)
        #pragma unroll
        for (int nt = 0; nt < 8; ++nt)
            #pragma unroll
            for (int j = 0; j < 4; ++j) acc[mt][nt][j] = 0.f;

    const int KT = K >> 7;

    load_stage(sbase, A, Wt, bm, bn, M, K, 0, tid);

    for (int kt = 0; kt < KT; ++kt) {
        asm volatile("cp.async.wait_group 0;" ::: "memory");
        __syncthreads();

        if (kt + 1 < KT)
            load_stage(sbase + (uint32_t)(((kt + 1) & 1) * GSTG_BYTES),
                       A, Wt, bm, bn, M, K, (kt + 1) * 128, tid);

        const uint32_t sA_u = sbase + (uint32_t)((kt & 1) * GSTG_BYTES);
        const uint32_t sB_u = sA_u + 128 * (GPH * 2);

        #pragma unroll
        for (int k16 = 0; k16 < 8; ++k16) {
            uint32_t bf[8][2];
            #pragma unroll
            for (int ntp = 0; ntp < 4; ++ntp) {
                uint32_t r0, r1, r2, r3;
                ldsm_x4(r0, r1, r2, r3,
                        sB_u + boff + (uint32_t)(ntp * 16 * GPH * 2 + k16 * 32));
                bf[2 * ntp][0] = r0; bf[2 * ntp][1] = r1;
                bf[2 * ntp + 1][0] = r2; bf[2 * ntp + 1][1] = r3;
            }
            #pragma unroll
            for (int mt = 0; mt < 2; ++mt) {
                uint32_t a0, a1, a2, a3;
                ldsm_x4(a0, a1, a2, a3,
                        sA_u + aoff + (uint32_t)(mt * 16 * GPH * 2 + k16 * 32));
                #pragma unroll
                for (int nt = 0; nt < 8; ++nt)
                    mma_f16(acc[mt][nt], a0, a1, a2, a3, bf[nt][0], bf[nt][1]);
            }
        }
    }

    // ---- epilogue ----
    #pragma unroll
    for (int nt = 0; nt < 8; ++nt) {
        const int c = bn + wn + nt * 8 + 2 * t;
        const float2 bia = *(const float2*)&bias[c];
        #pragma unroll
        for (int mt = 0; mt < 2; ++mt) {
            const int r0 = bm + wm + mt * 16 + g;
            const int r1 = r0 + 8;
            float v0 = acc[mt][nt][0] + bia.x;
            float v1 = acc[mt][nt][1] + bia.y;
            float v2 = acc[mt][nt][2] + bia.x;
            float v3 = acc[mt][nt][3] + bia.y;

            if (EPI == 0) {
                if (c < QKW) {
                    __half* qk = (__half*)outp;
                    if (r0 < M) *(__half2*)&qk[(size_t)r0 * QKW + c] = __floats2half2_rn(v0, v1);
                    if (r1 < M) *(__half2*)&qk[(size_t)r1 * QKW + c] = __floats2half2_rn(v2, v3);
                } else {
                    const int cc = c - QKW;
                    const int hh = cc >> 6, dd = cc & 63;
                    if (r0 < M) {
                        int bb = r0 / SEQ, n = r0 - bb * SEQ;
                        __half* p = vt + ((size_t)(bb * NHEAD + hh) * DHEAD + dd) * SEQP + n;
                        p[0]    = __float2half_rn(v0);
                        p[SEQP] = __float2half_rn(v1);
                    }
                    if (r1 < M) {
                        int bb = r1 / SEQ, n = r1 - bb * SEQ;
                        __half* p = vt + ((size_t)(bb * NHEAD + hh) * DHEAD + dd) * SEQP + n;
                        p[0]    = __float2half_rn(v2);
                        p[SEQP] = __float2half_rn(v3);
                    }
                }
            } else if (EPI == 1) {
                const float* res = (const float*)resv;
                __half* out = (__half*)outp;
                if (r0 < M) {
                    float2 rv = *(const float2*)&res[(size_t)r0 * N + c];
                    *(__half2*)&out[(size_t)r0 * N + c] = __floats2half2_rn(v0 + rv.x, v1 + rv.y);
                }
                if (r1 < M) {
                    float2 rv = *(const float2*)&res[(size_t)r1 * N + c];
                    *(__half2*)&out[(size_t)r1 * N + c] = __floats2half2_rn(v2 + rv.x, v3 + rv.y);
                }
            } else if (EPI == 2) {
                __half* out = (__half*)outp;
                v0 = 0.5f * v0 * (1.0f + erff(v0 * 0.70710678118654752f));
                v1 = 0.5f * v1 * (1.0f + erff(v1 * 0.70710678118654752f));
                v2 = 0.5f * v2 * (1.0f + erff(v2 * 0.70710678118654752f));
                v3 = 0.5f * v3 * (1.0f + erff(v3 * 0.70710678118654752f));
                if (r0 < M) *(__half2*)&out[(size_t)r0 * N + c] = __floats2half2_rn(v0, v1);
                if (r1 < M) *(__half2*)&out[(size_t)r1 * N + c] = __floats2half2_rn(v2, v3);
            } else {
                const __half* res = (const __half*)resv;
                float* out = (float*)outp;
                if (r0 < M) {
                    __half2 rv = *(const __half2*)&res[(size_t)r0 * N + c];
                    *(float2*)&out[(size_t)r0 * N + c] =
                        make_float2(v0 + __half2float(rv.x), v1 + __half2float(rv.y));
                }
                if (r1 < M) {
                    __half2 rv = *(const __half2*)&res[(size_t)r1 * N + c];
                    *(float2*)&out[(size_t)r1 * N + c] =
                        make_float2(v2 + __half2float(rv.x), v3 + __half2float(rv.y));
                }
            }
        }
    }
}

// ---------------- fp16 flash attention: no-max softmax, register P -----------------
#define PH 72
#define OQ 0
#define OK (128 * PH)
#define OV (OK + 2 * 64 * PH)
#define ATT_SMEM ((OV + 2 * 64 * PH) * 2)
#define NKT 10

__global__ void __launch_bounds__(256) attn_tc(
    const __half* __restrict__ qk, const __half* __restrict__ vt,
    __half* __restrict__ outa)
{
    extern __shared__ __align__(16) char sm[];
    const uint32_t sbase = smem_u32(sm);

    const int qt = blockIdx.x;
    const int h  = blockIdx.y;
    const int b  = blockIdx.z;
    const int tid  = threadIdx.x;
    const int wid  = tid >> 5;
    const int lane = tid & 31;
    const int g = lane >> 2, t = lane & 3;
    const int wr = wid * 16;
    const size_t browbase = (size_t)b * SEQ;
    const __half* qbase = qk + browbase * QKW + h * DHEAD;
    const __half* vbase = vt + (size_t)(b * NHEAD + h) * DHEAD * SEQP;

    const int l15 = lane & 15;
    const int lhi = lane >> 4;
    const uint32_t aoff = (uint32_t)(((wr + l15) * PH + lhi * 8) * 2);
    const int l7 = lane & 7;
    const int q2 = lane >> 3;
    const uint32_t boff = (uint32_t)((((q2 >> 1) * 8 + l7) * PH + (q2 & 1) * 8) * 2);

    #pragma unroll
    for (int i = 0; i < 4; ++i) {
        int f = i * 256 + tid;
        int r = f >> 3, q = f & 7;
        int n = qt * 128 + r;
        int sz = (n < SEQ) ? 16 : 0;
        if (n >= SEQ) n = SEQ - 1;
        cp_async16z(sbase + (uint32_t)((OQ + r * PH + q * 8) * 2),
                    qbase + (size_t)n * QKW + q * 8, sz);
    }
    #pragma unroll
    for (int i = 0; i < 2; ++i) {
        int f = i * 256 + tid;
        int r = f >> 3, q = f & 7;
        cp_async16(sbase + (uint32_t)((OK + r * PH + q * 8) * 2),
                   qbase + (size_t)r * QKW + CDIM + q * 8);
        cp_async16(sbase + (uint32_t)((OV + r * PH + q * 8) * 2),
                   vbase + (size_t)r * SEQP + q * 8);
    }
    asm volatile("cp.async.commit_group;" ::: "memory");

    float oacc[8][4];
    #pragma unroll
    for (int nt = 0; nt < 8; ++nt)
        #pragma unroll
        for (int j = 0; j < 4; ++j) oacc[nt][j] = 0.f;
    float l0 = 0.f, l1 = 0.f;

    for (int kt = 0; kt < NKT; ++kt) {
        const int buf = kt & 1;
        if (kt > 0) __syncthreads();
        if (kt + 1 < NKT) {
            const int nbuf = (kt + 1) & 1;
            #pragma unroll
            for (int i = 0; i < 2; ++i) {
                int f = i * 256 + tid;
                int r = f >> 3, q = f & 7;
                int kk = (kt + 1) * 64 + r;
                int sz = (kk < SEQ) ? 16 : 0;
                if (kk >= SEQ) kk = SEQ - 1;
                cp_async16z(sbase + (uint32_t)((OK + (nbuf * 64 + r) * PH + q * 8) * 2),
                            qbase + (size_t)kk * QKW + CDIM + q * 8, sz);
                cp_async16(sbase + (uint32_t)((OV + (nbuf * 64 + r) * PH + q * 8) * 2),
                           vbase + (size_t)r * SEQP + (kt + 1) * 64 + q * 8);
            }
        }
        asm volatile("cp.async.commit_group;" ::: "memory");
        asm volatile("cp.async.wait_group 1;" ::: "memory");
        __syncthreads();

        const uint32_t Qu = sbase + OQ * 2;
        const uint32_t Ku = sbase + (OK + buf * 64 * PH) * 2;
        const uint32_t Vu = sbase + (OV + buf * 64 * PH) * 2;

        float sacc[8][4];
        #pragma unroll
        for (int nt = 0; nt < 8; ++nt)
            #pragma unroll
            for (int j = 0; j < 4; ++j) sacc[nt][j] = 0.f;

        #pragma unroll
        for (int k16 = 0; k16 < 4; ++k16) {
            uint32_t a0, a1, a2, a3;
            ldsm_x4(a0, a1, a2, a3, Qu + aoff + (uint32_t)(k16 * 32));
            #pragma unroll
            for (int ntp = 0; ntp < 4; ++ntp) {
                uint32_t b0, b1, b2, b3;
                ldsm_x4(b0, b1, b2, b3,
                        Ku + boff + (uint32_t)(ntp * 16 * PH * 2 + k16 * 32));
                mma_f16(sacc[2 * ntp],     a0, a1, a2, a3, b0, b1);
                mma_f16(sacc[2 * ntp + 1], a0, a1, a2, a3, b2, b3);
            }
        }

        const int kb0 = kt * 64;
        uint32_t pfrag[4][4];
        #pragma unroll
        for (int nt = 0; nt < 8; ++nt) {
            const int c0 = kb0 + nt * 8 + 2 * t;
            float p0 = (c0     < SEQ) ? __expf(sacc[nt][0] * 0.125f) : 0.f;
            float p1 = (c0 + 1 < SEQ) ? __expf(sacc[nt][1] * 0.125f) : 0.f;
            float p2 = (c0     < SEQ) ? __expf(sacc[nt][2] * 0.125f) : 0.f;
            float p3 = (c0 + 1 < SEQ) ? __expf(sacc[nt][3] * 0.125f) : 0.f;
            l0 += p0 + p1; l1 += p2 + p3;
            __half2 h01 = __floats2half2_rn(p0, p1);
            __half2 h23 = __floats2half2_rn(p2, p3);
            const int k16i = nt >> 1, hi = nt & 1;
            pfrag[k16i][2 * hi]     = *(uint32_t*)&h01;
            pfrag[k16i][2 * hi + 1] = *(uint32_t*)&h23;
        }

        #pragma unroll
        for (int k16 = 0; k16 < 4; ++k16) {
            #pragma unroll
            for (int ntp = 0; ntp < 4; ++ntp) {
                uint32_t b0, b1, b2, b3;
                ldsm_x4(b0, b1, b2, b3,
                        Vu + boff + (uint32_t)(ntp * 16 * PH * 2 + k16 * 32));
                mma_f16(oacc[2 * ntp],     pfrag[k16][0], pfrag[k16][1],
                        pfrag[k16][2], pfrag[k16][3], b0, b1);
                mma_f16(oacc[2 * ntp + 1], pfrag[k16][0], pfrag[k16][1],
                        pfrag[k16][2], pfrag[k16][3], b2, b3);
            }
        }
    }

    l0 += __shfl_xor_sync(0xffffffffu, l0, 1);
    l0 += __shfl_xor_sync(0xffffffffu, l0, 2);
    l1 += __shfl_xor_sync(0xffffffffu, l1, 1);
    l1 += __shfl_xor_sync(0xffffffffu, l1, 2);

    const float inv0 = 1.0f / l0, inv1 = 1.0f / l1;
    const int r0 = qt * 128 + wr + g;
    const int r1 = r0 + 8;
    #pragma unroll
    for (int nt = 0; nt < 8; ++nt) {
        const int col = h * DHEAD + nt * 8 + 2 * t;
        if (r0 < SEQ)
            *(__half2*)&outa[(browbase + r0) * CDIM + col] =
                __floats2half2_rn(oacc[nt][0] * inv0, oacc[nt][1] * inv0);
        if (r1 < SEQ)
            *(__half2*)&outa[(browbase + r1) * CDIM + col] =
                __floats2half2_rn(oacc[nt][2] * inv1, oacc[nt][3] * inv1);
    }
}

// ---------------- launcher ----------------
extern "C" void kernel_launch(void* const* d_in, const int* in_sizes, int n_in,
                              void* d_out, int out_size)
{
    const float* x      = (const float*)d_in[0];
    const float* ln1_g  = (const float*)d_in[1];
    const float* ln1_b  = (const float*)d_in[2];
    const float* ln2_g  = (const float*)d_in[3];
    const float* ln2_b  = (const float*)d_in[4];
    const float* qkv_w  = (const float*)d_in[5];
    const float* qkv_b  = (const float*)d_in[6];
    const float* proj_w = (const float*)d_in[7];
    const float* proj_b = (const float*)d_in[8];
    const float* fc1_w  = (const float*)d_in[9];
    const float* fc1_b  = (const float*)d_in[10];
    const float* fc2_w  = (const float*)d_in[11];
    const float* fc2_b  = (const float*)d_in[12];
    float* out = (float*)d_out;

    __half *h, *qk, *vt, *attn, *x1h, *ff, *wtq, *wtp, *wt1, *wt2;
    cudaGetSymbolAddress((void**)&h,    g_h);
    cudaGetSymbolAddress((void**)&qk,   g_qk);
    cudaGetSymbolAddress((void**)&vt,   g_vt);
    cudaGetSymbolAddress((void**)&attn, g_attn);
    cudaGetSymbolAddress((void**)&x1h,  g_x1h);
    cudaGetSymbolAddress((void**)&ff,   g_ff);
    cudaGetSymbolAddress((void**)&wtq,  g_wt_qkv);
    cudaGetSymbolAddress((void**)&wtp,  g_wt_proj);
    cudaGetSymbolAddress((void**)&wt1,  g_wt_fc1);
    cudaGetSymbolAddress((void**)&wt2,  g_wt_fc2);

    cudaFuncSetAttribute(gemm_mma<0>, cudaFuncAttributeMaxDynamicSharedMemorySize, GSMEM_DYN);
    cudaFuncSetAttribute(gemm_mma<1>, cudaFuncAttributeMaxDynamicSharedMemorySize, GSMEM_DYN);
    cudaFuncSetAttribute(gemm_mma<2>, cudaFuncAttributeMaxDynamicSharedMemorySize, GSMEM_DYN);
    cudaFuncSetAttribute(gemm_mma<3>, cudaFuncAttributeMaxDynamicSharedMemorySize, GSMEM_DYN);
    cudaFuncSetAttribute(attn_tc,     cudaFuncAttributeMaxDynamicSharedMemorySize, ATT_SMEM);

    const int M  = MROWS;
    const int gy = (M + GBM - 1) / GBM;     // 145

    prep_kernel<<<MROWS + 7296, dim3(32, 8)>>>(x, ln1_g, ln1_b, qkv_w, proj_w, fc1_w, fc2_w);

    // 2. QKV (Q,K natural; V transposed)
    gemm_mma<0><<<dim3(C3 / GBN, gy), GTHREADS, GSMEM_DYN>>>(h, wtq, qkv_b, nullptr, qk, vt, M, CDIM, C3);
    // 3. attention
    attn_tc<<<dim3((SEQ + 127) / 128, NHEAD, BATCH), 256, ATT_SMEM>>>(qk, vt, attn);
    // 4. x1h = half(x + attn @ proj_w + proj_b)
    gemm_mma<1><<<dim3(CDIM / GBN, gy), GTHREADS, GSMEM_DYN>>>(attn, wtp, proj_b, x, x1h, nullptr, M, CDIM, CDIM);
    // 5. LN2 (half input)
    ln_kernel_h<<<M, 256>>>(x1h, ln2_g, ln2_b, h);
    // 6. ff = gelu(h @ fc1_w + fc1_b)
    gemm_mma<2><<<dim3(DFF / GBN, gy), GTHREADS, GSMEM_DYN>>>(h, wt1, fc1_b, nullptr, ff, nullptr, M, CDIM, DFF);
    // 7. out = x1h + ff @ fc2_w + fc2_b   (f32 final)
    gemm_mma<3><<<dim3(CDIM / GBN, gy), GTHREADS, GSMEM_DYN>>>(ff, wt2, fc2_b, x1h, out, nullptr, M, DFF, CDIM);
}

// round 15
// speedup vs baseline: 6.1611x; 1.0105x over previous
#include <cuda_runtime.h>
#include <cuda_fp16.h>
#include <cstdint>
#include <math.h>

// ---------------- problem constants ----------------
#define BATCH 32
#define SEQ   577
#define CDIM  768
#define NHEAD 12
#define DHEAD 64
#define DFF   3072
#define MROWS (BATCH*SEQ)          // 18464
#define C3    2304
#define QKW   1536                 // row width of g_qk (Q|K)
#define SEQP  640                  // padded seq for transposed V

// ---------------- scratch (device globals; no allocation) ----------------
__device__ __align__(256) __half g_h   [(size_t)MROWS * CDIM];
__device__ __align__(256) __half g_qk  [(size_t)MROWS * QKW];
__device__ __align__(256) __half g_vt  [(size_t)BATCH * NHEAD * DHEAD * SEQP];
__device__ __align__(256) __half g_attn[(size_t)MROWS * CDIM];
__device__ __align__(256) __half g_x1h [(size_t)MROWS * CDIM];
__device__ __align__(256) __half g_ff  [(size_t)MROWS * DFF];
__device__ __align__(256) __half g_wt_qkv [(size_t)C3   * CDIM];
__device__ __align__(256) __half g_wt_proj[(size_t)CDIM * CDIM];
__device__ __align__(256) __half g_wt_fc1 [(size_t)DFF  * CDIM];
__device__ __align__(256) __half g_wt_fc2 [(size_t)CDIM * DFF];

// ---------------- helpers ----------------
static __device__ __forceinline__ uint32_t smem_u32(const void* p) {
    uint32_t a;
    asm("{ .reg .u64 t; cvta.to.shared.u64 t, %1; cvt.u32.u64 %0, t; }" : "=r"(a) : "l"(p));
    return a;
}
static __device__ __forceinline__ void cp_async16(uint32_t dst, const void* src) {
    asm volatile("cp.async.cg.shared.global [%0], [%1], 16;" :: "r"(dst), "l"(src));
}
static __device__ __forceinline__ void cp_async16z(uint32_t dst, const void* src, int sz) {
    asm volatile("cp.async.cg.shared.global [%0], [%1], 16, %2;" :: "r"(dst), "l"(src), "r"(sz));
}
static __device__ __forceinline__ void mma_f16(
    float* d, uint32_t a0, uint32_t a1, uint32_t a2, uint32_t a3,
    uint32_t b0, uint32_t b1)
{
    asm volatile(
        "mma.sync.aligned.m16n8k16.row.col.f32.f16.f16.f32 "
        "{%0,%1,%2,%3}, {%4,%5,%6,%7}, {%8,%9}, {%0,%1,%2,%3};"
        : "+f"(d[0]), "+f"(d[1]), "+f"(d[2]), "+f"(d[3])
        : "r"(a0), "r"(a1), "r"(a2), "r"(a3), "r"(b0), "r"(b1));
}
static __device__ __forceinline__ void ldsm_x4(
    uint32_t& r0, uint32_t& r1, uint32_t& r2, uint32_t& r3, uint32_t addr)
{
    asm volatile("ldmatrix.sync.aligned.m8n8.x4.shared.b16 {%0,%1,%2,%3}, [%4];"
                 : "=r"(r0), "=r"(r1), "=r"(r2), "=r"(r3) : "r"(addr));
}
static __device__ __forceinline__ float ldf(const float* p)  { return *p; }
static __device__ __forceinline__ float ldf(const __half* p) { return __half2float(*p); }

// ---------------- LayerNorm body (templated input dtype) ----------------
template <typename T>
static __device__ __forceinline__ void ln_body(
    const T* __restrict__ x, const float* __restrict__ g,
    const float* __restrict__ b, __half* __restrict__ out,
    int row, int tid, float* red)
{
    const T* xr = x + (size_t)row * CDIM;
    float v0 = ldf(xr + tid), v1 = ldf(xr + tid + 256), v2 = ldf(xr + tid + 512);

    float s = v0 + v1 + v2;
    #pragma unroll
    for (int o = 16; o > 0; o >>= 1) s += __shfl_xor_sync(0xffffffffu, s, o);
    if ((tid & 31) == 0) red[tid >> 5] = s;
    __syncthreads();
    if (tid == 0) {
        float t = 0.f;
        #pragma unroll
        for (int w = 0; w < 8; ++w) t += red[w];
        red[0] = t;
    }
    __syncthreads();
    const float mean = red[0] * (1.0f / CDIM);
    __syncthreads();

    float d0 = v0 - mean, d1 = v1 - mean, d2 = v2 - mean;
    float sq = d0 * d0 + d1 * d1 + d2 * d2;
    #pragma unroll
    for (int o = 16; o > 0; o >>= 1) sq += __shfl_xor_sync(0xffffffffu, sq, o);
    if ((tid & 31) == 0) red[tid >> 5] = sq;
    __syncthreads();
    if (tid == 0) {
        float t = 0.f;
        #pragma unroll
        for (int w = 0; w < 8; ++w) t += red[w];
        red[0] = t;
    }
    __syncthreads();
    const float var = red[0] * (1.0f / CDIM);
    const float rstd = rsqrtf(var + 1e-5f);

    __half* outr = out + (size_t)row * CDIM;
    outr[tid]       = __float2half_rn(d0 * rstd * g[tid]       + b[tid]);
    outr[tid + 256] = __float2half_rn(d1 * rstd * g[tid + 256] + b[tid + 256]);
    outr[tid + 512] = __float2half_rn(d2 * rstd * g[tid + 512] + b[tid + 512]);
}

__global__ void __launch_bounds__(256) ln_kernel_h(
    const __half* __restrict__ x, const float* __restrict__ g,
    const float* __restrict__ b, __half* __restrict__ out)
{
    __shared__ float red[8];
    ln_body(x, g, b, out, blockIdx.x, threadIdx.x, red);
}

// ---------------- merged prep: LN1 + 4 weight transposes + V-tail zero -------------
__global__ void __launch_bounds__(256) prep_kernel(
    const float* __restrict__ x, const float* __restrict__ ln1_g,
    const float* __restrict__ ln1_b,
    const float* __restrict__ qkv_w, const float* __restrict__ proj_w,
    const float* __restrict__ fc1_w, const float* __restrict__ fc2_w)
{
    __shared__ float tb[32][33];
    __shared__ float red[8];
    int bid = blockIdx.x;
    const int tid = threadIdx.y * 32 + threadIdx.x;

    if (bid < MROWS) {
        ln_body(x, ln1_g, ln1_b, g_h, bid, tid, red);
        return;
    }
    bid -= MROWS;

    if (bid >= 6912) {
        __half* vt = g_vt + (size_t)(bid - 6912) * DHEAD * SEQP;
        const uint4 z = make_uint4(0u, 0u, 0u, 0u);
        #pragma unroll
        for (int i = 0; i < 4; ++i) {
            int f = i * 256 + tid;
            int d = f >> 4, u = f & 15;
            *(uint4*)(vt + (size_t)d * SEQP + 512 + u * 8) = z;
        }
        return;
    }
    const float* W; __half* Wt; int K, N;
    if (bid < 1728)      { W = qkv_w;  Wt = g_wt_qkv;  K = CDIM; N = C3;  }
    else if (bid < 2304) { W = proj_w; Wt = g_wt_proj; K = CDIM; N = CDIM; bid -= 1728; }
    else if (bid < 4608) { W = fc1_w;  Wt = g_wt_fc1;  K = CDIM; N = DFF;  bid -= 2304; }
    else                 { W = fc2_w;  Wt = g_wt_fc2;  K = DFF;  N = CDIM; bid -= 4608; }

    const int nbx = K >> 5;
    const int k0 = (bid % nbx) * 32, n0 = (bid / nbx) * 32;
    #pragma unroll
    for (int i = threadIdx.y; i < 32; i += 8)
        tb[i][threadIdx.x] = W[(size_t)(k0 + i) * N + n0 + threadIdx.x];
    __syncthreads();
    #pragma unroll
    for (int i = threadIdx.y; i < 32; i += 8)
        Wt[(size_t)(n0 + i) * K + k0 + threadIdx.x] = __float2half_rn(tb[threadIdx.x][i]);
}

// ---------------- fp16 HMMA GEMM: 128x128 tile, 256 thr, 2 CTAs/SM -----------------
// EPI 0: qkv | 1: +f32 res -> half | 2: GELU -> half | 3: +half res -> f32
#define GBM 128
#define GBN 128
#define PH 72                              // halfs per smem row (64 + 8 pad)
#define GSTG_BYTES ((128 + 128) * PH * 2)  // 36864
#define NSTAGE 3
#define GSMEM_DYN (NSTAGE * GSTG_BYTES)    // 110592 -> 2 CTAs/SM
#define GTHREADS 256

__device__ __forceinline__ void load_stage(
    uint32_t sb, const __half* __restrict__ A, const __half* __restrict__ Wt,
    int bm, int bn, int M, int K, int kc, int tid)
{
    // A tile: 128 rows x 64 halfs
    #pragma unroll
    for (int i = 0; i < 4; ++i) {
        int f = i * GTHREADS + tid;
        int r = f >> 3, q = f & 7;
        int rr = bm + r;
        int sz = (rr < M) ? 16 : 0;
        if (rr >= M) rr = M - 1;
        cp_async16z(sb + (uint32_t)(r * (PH * 2) + q * 16),
                    A + (size_t)rr * K + kc + q * 8, sz);
    }
    // B tile: 128 rows x 64 halfs
    const uint32_t bb = sb + 128 * (PH * 2);
    #pragma unroll
    for (int i = 0; i < 4; ++i) {
        int f = i * GTHREADS + tid;
        int r = f >> 3, q = f & 7;
        cp_async16(bb + (uint32_t)(r * (PH * 2) + q * 16),
                   Wt + (size_t)(bn + r) * K + kc + q * 8);
    }
    asm volatile("cp.async.commit_group;" ::: "memory");
}

template <int EPI>
__global__ void __launch_bounds__(GTHREADS, 2) gemm_mma(
    const __half* __restrict__ A, const __half* __restrict__ Wt,
    const float* __restrict__ bias, const void* __restrict__ resv,
    void* __restrict__ outp, __half* __restrict__ vt,
    int M, int K, int N)
{
    extern __shared__ __align__(16) char dsm[];
    const uint32_t sbase = smem_u32(dsm);

    const int tid  = threadIdx.x;
    const int wid  = tid >> 5;
    const int lane = tid & 31;
    const int g = lane >> 2, t = lane & 3;
    const int bm = blockIdx.y * GBM;
    const int bn = blockIdx.x * GBN;
    const int wm = (wid >> 1) * 32;        // 4 warp-rows of 32
    const int wn = (wid & 1) * 64;         // 2 warp-cols of 64

    const int l15 = lane & 15;
    const int lhi = lane >> 4;
    const uint32_t aoff = (uint32_t)(((wm + l15) * PH + lhi * 8) * 2);
    const int l7 = lane & 7;
    const int q2 = lane >> 3;
    const uint32_t boff = (uint32_t)(((wn + (q2 >> 1) * 8 + l7) * PH + (q2 & 1) * 8) * 2);

    float acc[2][8][4];
    #pragma unroll
    for (int mt = 0; mt < 2; ++mt)
        #pragma unroll
        for (int nt = 0; nt < 8; ++nt)
            #pragma unroll
            for (int j = 0; j < 4; ++j) acc[mt][nt][j] = 0.f;

    const int KT = K >> 6;                 // 64-half chunks

    load_stage(sbase, A, Wt, bm, bn, M, K, 0, tid);
    load_stage(sbase + GSTG_BYTES, A, Wt, bm, bn, M, K, 64, tid);

    for (int kt = 0; kt < KT; ++kt) {
        asm volatile("cp.async.wait_group 1;" ::: "memory");
        __syncthreads();

        if (kt + 2 < KT)
            load_stage(sbase + (uint32_t)(((kt + 2) % NSTAGE) * GSTG_BYTES),
                       A, Wt, bm, bn, M, K, (kt + 2) * 64, tid);
        else
            asm volatile("cp.async.commit_group;" ::: "memory");

        const uint32_t sA_u = sbase + (uint32_t)((kt % NSTAGE) * GSTG_BYTES);
        const uint32_t sB_u = sA_u + 128 * (PH * 2);

        #pragma unroll
        for (int k16 = 0; k16 < 4; ++k16) {
            uint32_t bf[8][2];
            #pragma unroll
            for (int ntp = 0; ntp < 4; ++ntp) {
                uint32_t r0, r1, r2, r3;
                ldsm_x4(r0, r1, r2, r3,
                        sB_u + boff + (uint32_t)(ntp * 16 * PH * 2 + k16 * 32));
                bf[2 * ntp][0] = r0; bf[2 * ntp][1] = r1;
                bf[2 * ntp + 1][0] = r2; bf[2 * ntp + 1][1] = r3;
            }
            #pragma unroll
            for (int mt = 0; mt < 2; ++mt) {
                uint32_t a0, a1, a2, a3;
                ldsm_x4(a0, a1, a2, a3,
                        sA_u + aoff + (uint32_t)(mt * 16 * PH * 2 + k16 * 32));
                #pragma unroll
                for (int nt = 0; nt < 8; ++nt)
                    mma_f16(acc[mt][nt], a0, a1, a2, a3, bf[nt][0], bf[nt][1]);
            }
        }
    }

    // ---- epilogue ----
    #pragma unroll
    for (int nt = 0; nt < 8; ++nt) {
        const int c = bn + wn + nt * 8 + 2 * t;
        const float2 bia = *(const float2*)&bias[c];
        #pragma unroll
        for (int mt = 0; mt < 2; ++mt) {
            const int r0 = bm + wm + mt * 16 + g;
            const int r1 = r0 + 8;
            float v0 = acc[mt][nt][0] + bia.x;
            float v1 = acc[mt][nt][1] + bia.y;
            float v2 = acc[mt][nt][2] + bia.x;
            float v3 = acc[mt][nt][3] + bia.y;

            if (EPI == 0) {
                if (c < QKW) {
                    __half* qk = (__half*)outp;
                    if (r0 < M) *(__half2*)&qk[(size_t)r0 * QKW + c] = __floats2half2_rn(v0, v1);
                    if (r1 < M) *(__half2*)&qk[(size_t)r1 * QKW + c] = __floats2half2_rn(v2, v3);
                } else {
                    const int cc = c - QKW;
                    const int hh = cc >> 6, dd = cc & 63;
                    if (r0 < M) {
                        int bb = r0 / SEQ, n = r0 - bb * SEQ;
                        __half* p = vt + ((size_t)(bb * NHEAD + hh) * DHEAD + dd) * SEQP + n;
                        p[0]    = __float2half_rn(v0);
                        p[SEQP] = __float2half_rn(v1);
                    }
                    if (r1 < M) {
                        int bb = r1 / SEQ, n = r1 - bb * SEQ;
                        __half* p = vt + ((size_t)(bb * NHEAD + hh) * DHEAD + dd) * SEQP + n;
                        p[0]    = __float2half_rn(v2);
                        p[SEQP] = __float2half_rn(v3);
                    }
                }
            } else if (EPI == 1) {
                const float* res = (const float*)resv;
                __half* out = (__half*)outp;
                if (r0 < M) {
                    float2 rv = *(const float2*)&res[(size_t)r0 * N + c];
                    *(__half2*)&out[(size_t)r0 * N + c] = __floats2half2_rn(v0 + rv.x, v1 + rv.y);
                }
                if (r1 < M) {
                    float2 rv = *(const float2*)&res[(size_t)r1 * N + c];
                    *(__half2*)&out[(size_t)r1 * N + c] = __floats2half2_rn(v2 + rv.x, v3 + rv.y);
                }
            } else if (EPI == 2) {
                __half* out = (__half*)outp;
                v0 = 0.5f * v0 * (1.0f + erff(v0 * 0.70710678118654752f));
                v1 = 0.5f * v1 * (1.0f + erff(v1 * 0.70710678118654752f));
                v2 = 0.5f * v2 * (1.0f + erff(v2 * 0.70710678118654752f));
                v3 = 0.5f * v3 * (1.0f + erff(v3 * 0.70710678118654752f));
                if (r0 < M) *(__half2*)&out[(size_t)r0 * N + c] = __floats2half2_rn(v0, v1);
                if (r1 < M) *(__half2*)&out[(size_t)r1 * N + c] = __floats2half2_rn(v2, v3);
            } else {
                const __half* res = (const __half*)resv;
                float* out = (float*)outp;
                if (r0 < M) {
                    __half2 rv = *(const __half2*)&res[(size_t)r0 * N + c];
                    *(float2*)&out[(size_t)r0 * N + c] =
                        make_float2(v0 + __half2float(rv.x), v1 + __half2float(rv.y));
                }
                if (r1 < M) {
                    __half2 rv = *(const __half2*)&res[(size_t)r1 * N + c];
                    *(float2*)&out[(size_t)r1 * N + c] =
                        make_float2(v2 + __half2float(rv.x), v3 + __half2float(rv.y));
                }
            }
        }
    }
}

// ---------------- fp16 flash attention: no-max softmax, register P -----------------
#define OQ 0
#define OK (128 * PH)
#define OV (OK + 2 * 64 * PH)
#define ATT_SMEM ((OV + 2 * 64 * PH) * 2)
#define NKT 10

__global__ void __launch_bounds__(256) attn_tc(
    const __half* __restrict__ qk, const __half* __restrict__ vt,
    __half* __restrict__ outa)
{
    extern __shared__ __align__(16) char sm[];
    const uint32_t sbase = smem_u32(sm);

    const int qt = blockIdx.x;
    const int h  = blockIdx.y;
    const int b  = blockIdx.z;
    const int tid  = threadIdx.x;
    const int wid  = tid >> 5;
    const int lane = tid & 31;
    const int g = lane >> 2, t = lane & 3;
    const int wr = wid * 16;
    const size_t browbase = (size_t)b * SEQ;
    const __half* qbase = qk + browbase * QKW + h * DHEAD;
    const __half* vbase = vt + (size_t)(b * NHEAD + h) * DHEAD * SEQP;

    const int l15 = lane & 15;
    const int lhi = lane >> 4;
    const uint32_t aoff = (uint32_t)(((wr + l15) * PH + lhi * 8) * 2);
    const int l7 = lane & 7;
    const int q2 = lane >> 3;
    const uint32_t boff = (uint32_t)((((q2 >> 1) * 8 + l7) * PH + (q2 & 1) * 8) * 2);

    #pragma unroll
    for (int i = 0; i < 4; ++i) {
        int f = i * 256 + tid;
        int r = f >> 3, q = f & 7;
        int n = qt * 128 + r;
        int sz = (n < SEQ) ? 16 : 0;
        if (n >= SEQ) n = SEQ - 1;
        cp_async16z(sbase + (uint32_t)((OQ + r * PH + q * 8) * 2),
                    qbase + (size_t)n * QKW + q * 8, sz);
    }
    #pragma unroll
    for (int i = 0; i < 2; ++i) {
        int f = i * 256 + tid;
        int r = f >> 3, q = f & 7;
        cp_async16(sbase + (uint32_t)((OK + r * PH + q * 8) * 2),
                   qbase + (size_t)r * QKW + CDIM + q * 8);
        cp_async16(sbase + (uint32_t)((OV + r * PH + q * 8) * 2),
                   vbase + (size_t)r * SEQP + q * 8);
    }
    asm volatile("cp.async.commit_group;" ::: "memory");

    float oacc[8][4];
    #pragma unroll
    for (int nt = 0; nt < 8; ++nt)
        #pragma unroll
        for (int j = 0; j < 4; ++j) oacc[nt][j] = 0.f;
    float l0 = 0.f, l1 = 0.f;

    for (int kt = 0; kt < NKT; ++kt) {
        const int buf = kt & 1;
        if (kt > 0) __syncthreads();
        if (kt + 1 < NKT) {
            const int nbuf = (kt + 1) & 1;
            #pragma unroll
            for (int i = 0; i < 2; ++i) {
                int f = i * 256 + tid;
                int r = f >> 3, q = f & 7;
                int kk = (kt + 1) * 64 + r;
                int sz = (kk < SEQ) ? 16 : 0;
                if (kk >= SEQ) kk = SEQ - 1;
                cp_async16z(sbase + (uint32_t)((OK + (nbuf * 64 + r) * PH + q * 8) * 2),
                            qbase + (size_t)kk * QKW + CDIM + q * 8, sz);
                cp_async16(sbase + (uint32_t)((OV + (nbuf * 64 + r) * PH + q * 8) * 2),
                           vbase + (size_t)r * SEQP + (kt + 1) * 64 + q * 8);
            }
        }
        asm volatile("cp.async.commit_group;" ::: "memory");
        asm volatile("cp.async.wait_group 1;" ::: "memory");
        __syncthreads();

        const uint32_t Qu = sbase + OQ * 2;
        const uint32_t Ku = sbase + (OK + buf * 64 * PH) * 2;
        const uint32_t Vu = sbase + (OV + buf * 64 * PH) * 2;

        float sacc[8][4];
        #pragma unroll
        for (int nt = 0; nt < 8; ++nt)
            #pragma unroll
            for (int j = 0; j < 4; ++j) sacc[nt][j] = 0.f;

        #pragma unroll
        for (int k16 = 0; k16 < 4; ++k16) {
            uint32_t a0, a1, a2, a3;
            ldsm_x4(a0, a1, a2, a3, Qu + aoff + (uint32_t)(k16 * 32));
            #pragma unroll
            for (int ntp = 0; ntp < 4; ++ntp) {
                uint32_t b0, b1, b2, b3;
                ldsm_x4(b0, b1, b2, b3,
                        Ku + boff + (uint32_t)(ntp * 16 * PH * 2 + k16 * 32));
                mma_f16(sacc[2 * ntp],     a0, a1, a2, a3, b0, b1);
                mma_f16(sacc[2 * ntp + 1], a0, a1, a2, a3, b2, b3);
            }
        }

        const int kb0 = kt * 64;
        uint32_t pfrag[4][4];
        #pragma unroll
        for (int nt = 0; nt < 8; ++nt) {
            const int c0 = kb0 + nt * 8 + 2 * t;
            float p0 = (c0     < SEQ) ? __expf(sacc[nt][0] * 0.125f) : 0.f;
            float p1 = (c0 + 1 < SEQ) ? __expf(sacc[nt][1] * 0.125f) : 0.f;
            float p2 = (c0     < SEQ) ? __expf(sacc[nt][2] * 0.125f) : 0.f;
            float p3 = (c0 + 1 < SEQ) ? __expf(sacc[nt][3] * 0.125f) : 0.f;
            l0 += p0 + p1; l1 += p2 + p3;
            __half2 h01 = __floats2half2_rn(p0, p1);
            __half2 h23 = __floats2half2_rn(p2, p3);
            const int k16i = nt >> 1, hi = nt & 1;
            pfrag[k16i][2 * hi]     = *(uint32_t*)&h01;
            pfrag[k16i][2 * hi + 1] = *(uint32_t*)&h23;
        }

        #pragma unroll
        for (int k16 = 0; k16 < 4; ++k16) {
            #pragma unroll
            for (int ntp = 0; ntp < 4; ++ntp) {
                uint32_t b0, b1, b2, b3;
                ldsm_x4(b0, b1, b2, b3,
                        Vu + boff + (uint32_t)(ntp * 16 * PH * 2 + k16 * 32));
                mma_f16(oacc[2 * ntp],     pfrag[k16][0], pfrag[k16][1],
                        pfrag[k16][2], pfrag[k16][3], b0, b1);
                mma_f16(oacc[2 * ntp + 1], pfrag[k16][0], pfrag[k16][1],
                        pfrag[k16][2], pfrag[k16][3], b2, b3);
            }
        }
    }

    l0 += __shfl_xor_sync(0xffffffffu, l0, 1);
    l0 += __shfl_xor_sync(0xffffffffu, l0, 2);
    l1 += __shfl_xor_sync(0xffffffffu, l1, 1);
    l1 += __shfl_xor_sync(0xffffffffu, l1, 2);

    const float inv0 = 1.0f / l0, inv1 = 1.0f / l1;
    const int r0 = qt * 128 + wr + g;
    const int r1 = r0 + 8;
    #pragma unroll
    for (int nt = 0; nt < 8; ++nt) {
        const int col = h * DHEAD + nt * 8 + 2 * t;
        if (r0 < SEQ)
            *(__half2*)&outa[(browbase + r0) * CDIM + col] =
                __floats2half2_rn(oacc[nt][0] * inv0, oacc[nt][1] * inv0);
        if (r1 < SEQ)
            *(__half2*)&outa[(browbase + r1) * CDIM + col] =
                __floats2half2_rn(oacc[nt][2] * inv1, oacc[nt][3] * inv1);
    }
}

// ---------------- launcher ----------------
extern "C" void kernel_launch(void* const* d_in, const int* in_sizes, int n_in,
                              void* d_out, int out_size)
{
    const float* x      = (const float*)d_in[0];
    const float* ln1_g  = (const float*)d_in[1];
    const float* ln1_b  = (const float*)d_in[2];
    const float* ln2_g  = (const float*)d_in[3];
    const float* ln2_b  = (const float*)d_in[4];
    const float* qkv_w  = (const float*)d_in[5];
    const float* qkv_b  = (const float*)d_in[6];
    const float* proj_w = (const float*)d_in[7];
    const float* proj_b = (const float*)d_in[8];
    const float* fc1_w  = (const float*)d_in[9];
    const float* fc1_b  = (const float*)d_in[10];
    const float* fc2_w  = (const float*)d_in[11];
    const float* fc2_b  = (const float*)d_in[12];
    float* out = (float*)d_out;

    __half *h, *qk, *vt, *attn, *x1h, *ff, *wtq, *wtp, *wt1, *wt2;
    cudaGetSymbolAddress((void**)&h,    g_h);
    cudaGetSymbolAddress((void**)&qk,   g_qk);
    cudaGetSymbolAddress((void**)&vt,   g_vt);
    cudaGetSymbolAddress((void**)&attn, g_attn);
    cudaGetSymbolAddress((void**)&x1h,  g_x1h);
    cudaGetSymbolAddress((void**)&ff,   g_ff);
    cudaGetSymbolAddress((void**)&wtq,  g_wt_qkv);
    cudaGetSymbolAddress((void**)&wtp,  g_wt_proj);
    cudaGetSymbolAddress((void**)&wt1,  g_wt_fc1);
    cudaGetSymbolAddress((void**)&wt2,  g_wt_fc2);

    cudaFuncSetAttribute(gemm_mma<0>, cudaFuncAttributeMaxDynamicSharedMemorySize, GSMEM_DYN);
    cudaFuncSetAttribute(gemm_mma<1>, cudaFuncAttributeMaxDynamicSharedMemorySize, GSMEM_DYN);
    cudaFuncSetAttribute(gemm_mma<2>, cudaFuncAttributeMaxDynamicSharedMemorySize, GSMEM_DYN);
    cudaFuncSetAttribute(gemm_mma<3>, cudaFuncAttributeMaxDynamicSharedMemorySize, GSMEM_DYN);
    cudaFuncSetAttribute(attn_tc,     cudaFuncAttributeMaxDynamicSharedMemorySize, ATT_SMEM);

    const int M  = MROWS;
    const int gy = (M + GBM - 1) / GBM;     // 145

    prep_kernel<<<MROWS + 7296, dim3(32, 8)>>>(x, ln1_g, ln1_b, qkv_w, proj_w, fc1_w, fc2_w);

    // 2. QKV (Q,K natural; V transposed)
    gemm_mma<0><<<dim3(C3 / GBN, gy), GTHREADS, GSMEM_DYN>>>(h, wtq, qkv_b, nullptr, qk, vt, M, CDIM, C3);
    // 3. attention
    attn_tc<<<dim3((SEQ + 127) / 128, NHEAD, BATCH), 256, ATT_SMEM>>>(qk, vt, attn);
    // 4. x1h = half(x + attn @ proj_w + proj_b)
    gemm_mma<1><<<dim3(CDIM / GBN, gy), GTHREADS, GSMEM_DYN>>>(attn, wtp, proj_b, x, x1h, nullptr, M, CDIM, CDIM);
    // 5. LN2 (half input)
    ln_kernel_h<<<M, 256>>>(x1h, ln2_g, ln2_b, h);
    // 6. ff = gelu(h @ fc1_w + fc1_b)
    gemm_mma<2><<<dim3(DFF / GBN, gy), GTHREADS, GSMEM_DYN>>>(h, wt1, fc1_b, nullptr, ff, nullptr, M, CDIM, DFF);
    // 7. out = x1h + ff @ fc2_w + fc2_b   (f32 final)
    gemm_mma<3><<<dim3(CDIM / GBN, gy), GTHREADS, GSMEM_DYN>>>(ff, wt2, fc2_b, x1h, out, nullptr, M, DFF, CDIM);
}

// round 16
// speedup vs baseline: 6.1901x; 1.0047x over previous
#include <cuda_runtime.h>
#include <cuda_fp16.h>
#include <cstdint>
#include <math.h>

// ---------------- problem constants ----------------
#define BATCH 32
#define SEQ   577
#define CDIM  768
#define NHEAD 12
#define DHEAD 64
#define DFF   3072
#define MROWS (BATCH*SEQ)          // 18464
#define C3    2304

// ---------------- scratch (device globals; no allocation) ----------------
__device__ __align__(256) __half g_h   [(size_t)MROWS * CDIM];
__device__ __align__(256) __half g_qkv [(size_t)MROWS * C3];
__device__ __align__(256) __half g_attn[(size_t)MROWS * CDIM];
__device__ __align__(256) __half g_x1h [(size_t)MROWS * CDIM];
__device__ __align__(256) __half g_ff  [(size_t)MROWS * DFF];
__device__ __align__(256) __half g_wt_qkv [(size_t)C3   * CDIM];
__device__ __align__(256) __half g_wt_proj[(size_t)CDIM * CDIM];
__device__ __align__(256) __half g_wt_fc1 [(size_t)DFF  * CDIM];
__device__ __align__(256) __half g_wt_fc2 [(size_t)CDIM * DFF];

// ---------------- helpers ----------------
static __device__ __forceinline__ uint32_t smem_u32(const void* p) {
    uint32_t a;
    asm("{ .reg .u64 t; cvta.to.shared.u64 t, %1; cvt.u32.u64 %0, t; }" : "=r"(a) : "l"(p));
    return a;
}
static __device__ __forceinline__ void cp_async16(uint32_t dst, const void* src) {
    asm volatile("cp.async.cg.shared.global [%0], [%1], 16;" :: "r"(dst), "l"(src));
}
static __device__ __forceinline__ void cp_async16z(uint32_t dst, const void* src, int sz) {
    asm volatile("cp.async.cg.shared.global [%0], [%1], 16, %2;" :: "r"(dst), "l"(src), "r"(sz));
}
static __device__ __forceinline__ void mma_f16(
    float* d, uint32_t a0, uint32_t a1, uint32_t a2, uint32_t a3,
    uint32_t b0, uint32_t b1)
{
    asm volatile(
        "mma.sync.aligned.m16n8k16.row.col.f32.f16.f16.f32 "
        "{%0,%1,%2,%3}, {%4,%5,%6,%7}, {%8,%9}, {%0,%1,%2,%3};"
        : "+f"(d[0]), "+f"(d[1]), "+f"(d[2]), "+f"(d[3])
        : "r"(a0), "r"(a1), "r"(a2), "r"(a3), "r"(b0), "r"(b1));
}
static __device__ __forceinline__ void ldsm_x4(
    uint32_t& r0, uint32_t& r1, uint32_t& r2, uint32_t& r3, uint32_t addr)
{
    asm volatile("ldmatrix.sync.aligned.m8n8.x4.shared.b16 {%0,%1,%2,%3}, [%4];"
                 : "=r"(r0), "=r"(r1), "=r"(r2), "=r"(r3) : "r"(addr));
}
static __device__ __forceinline__ void ldsm_x4_trans(
    uint32_t& r0, uint32_t& r1, uint32_t& r2, uint32_t& r3, uint32_t addr)
{
    asm volatile("ldmatrix.sync.aligned.m8n8.x4.trans.shared.b16 {%0,%1,%2,%3}, [%4];"
                 : "=r"(r0), "=r"(r1), "=r"(r2), "=r"(r3) : "r"(addr));
}
static __device__ __forceinline__ float ldf(const float* p)  { return *p; }
static __device__ __forceinline__ float ldf(const __half* p) { return __half2float(*p); }

// ---------------- LayerNorm body (templated input dtype) ----------------
template <typename T>
static __device__ __forceinline__ void ln_body(
    const T* __restrict__ x, const float* __restrict__ g,
    const float* __restrict__ b, __half* __restrict__ out,
    int row, int tid, float* red)
{
    const T* xr = x + (size_t)row * CDIM;
    float v0 = ldf(xr + tid), v1 = ldf(xr + tid + 256), v2 = ldf(xr + tid + 512);

    float s = v0 + v1 + v2;
    #pragma unroll
    for (int o = 16; o > 0; o >>= 1) s += __shfl_xor_sync(0xffffffffu, s, o);
    if ((tid & 31) == 0) red[tid >> 5] = s;
    __syncthreads();
    if (tid == 0) {
        float t = 0.f;
        #pragma unroll
        for (int w = 0; w < 8; ++w) t += red[w];
        red[0] = t;
    }
    __syncthreads();
    const float mean = red[0] * (1.0f / CDIM);
    __syncthreads();

    float d0 = v0 - mean, d1 = v1 - mean, d2 = v2 - mean;
    float sq = d0 * d0 + d1 * d1 + d2 * d2;
    #pragma unroll
    for (int o = 16; o > 0; o >>= 1) sq += __shfl_xor_sync(0xffffffffu, sq, o);
    if ((tid & 31) == 0) red[tid >> 5] = sq;
    __syncthreads();
    if (tid == 0) {
        float t = 0.f;
        #pragma unroll
        for (int w = 0; w < 8; ++w) t += red[w];
        red[0] = t;
    }
    __syncthreads();
    const float var = red[0] * (1.0f / CDIM);
    const float rstd = rsqrtf(var + 1e-5f);

    __half* outr = out + (size_t)row * CDIM;
    outr[tid]       = __float2half_rn(d0 * rstd * g[tid]       + b[tid]);
    outr[tid + 256] = __float2half_rn(d1 * rstd * g[tid + 256] + b[tid + 256]);
    outr[tid + 512] = __float2half_rn(d2 * rstd * g[tid + 512] + b[tid + 512]);
}

__global__ void __launch_bounds__(256) ln_kernel_h(
    const __half* __restrict__ x, const float* __restrict__ g,
    const float* __restrict__ b, __half* __restrict__ out)
{
    __shared__ float red[8];
    ln_body(x, g, b, out, blockIdx.x, threadIdx.x, red);
}

// ---------------- merged prep: LN1 + 4 weight transposes ---------------------------
__global__ void __launch_bounds__(256) prep_kernel(
    const float* __restrict__ x, const float* __restrict__ ln1_g,
    const float* __restrict__ ln1_b,
    const float* __restrict__ qkv_w, const float* __restrict__ proj_w,
    const float* __restrict__ fc1_w, const float* __restrict__ fc2_w)
{
    __shared__ float tb[32][33];
    __shared__ float red[8];
    int bid = blockIdx.x;
    const int tid = threadIdx.y * 32 + threadIdx.x;

    if (bid < MROWS) {
        ln_body(x, ln1_g, ln1_b, g_h, bid, tid, red);
        return;
    }
    bid -= MROWS;

    const float* W; __half* Wt; int K, N;
    if (bid < 1728)      { W = qkv_w;  Wt = g_wt_qkv;  K = CDIM; N = C3;  }
    else if (bid < 2304) { W = proj_w; Wt = g_wt_proj; K = CDIM; N = CDIM; bid -= 1728; }
    else if (bid < 4608) { W = fc1_w;  Wt = g_wt_fc1;  K = CDIM; N = DFF;  bid -= 2304; }
    else                 { W = fc2_w;  Wt = g_wt_fc2;  K = DFF;  N = CDIM; bid -= 4608; }

    const int nbx = K >> 5;
    const int k0 = (bid % nbx) * 32, n0 = (bid / nbx) * 32;
    #pragma unroll
    for (int i = threadIdx.y; i < 32; i += 8)
        tb[i][threadIdx.x] = W[(size_t)(k0 + i) * N + n0 + threadIdx.x];
    __syncthreads();
    #pragma unroll
    for (int i = threadIdx.y; i < 32; i += 8)
        Wt[(size_t)(n0 + i) * K + k0 + threadIdx.x] = __float2half_rn(tb[threadIdx.x][i]);
}

// ---------------- fp16 HMMA GEMM: 128x128 tile, 256 thr, 2 CTAs/SM -----------------
// EPI 0: bias -> half | 1: +f32 res -> half | 2: GELU -> half | 3: +half res -> f32
#define GBM 128
#define GBN 128
#define PH 72                              // halfs per smem row (64 + 8 pad)
#define GSTG_BYTES ((128 + 128) * PH * 2)  // 36864
#define NSTAGE 3
#define GSMEM_DYN (NSTAGE * GSTG_BYTES)    // 110592 -> 2 CTAs/SM
#define GTHREADS 256

__device__ __forceinline__ void load_stage(
    uint32_t sb, const __half* __restrict__ A, const __half* __restrict__ Wt,
    int bm, int bn, int M, int K, int kc, int tid)
{
    #pragma unroll
    for (int i = 0; i < 4; ++i) {
        int f = i * GTHREADS + tid;
        int r = f >> 3, q = f & 7;
        int rr = bm + r;
        int sz = (rr < M) ? 16 : 0;
        if (rr >= M) rr = M - 1;
        cp_async16z(sb + (uint32_t)(r * (PH * 2) + q * 16),
                    A + (size_t)rr * K + kc + q * 8, sz);
    }
    const uint32_t bb = sb + 128 * (PH * 2);
    #pragma unroll
    for (int i = 0; i < 4; ++i) {
        int f = i * GTHREADS + tid;
        int r = f >> 3, q = f & 7;
        cp_async16(bb + (uint32_t)(r * (PH * 2) + q * 16),
                   Wt + (size_t)(bn + r) * K + kc + q * 8);
    }
    asm volatile("cp.async.commit_group;" ::: "memory");
}

template <int EPI>
__global__ void __launch_bounds__(GTHREADS, 2) gemm_mma(
    const __half* __restrict__ A, const __half* __restrict__ Wt,
    const float* __restrict__ bias, const void* __restrict__ resv,
    void* __restrict__ outp, int M, int K, int N)
{
    extern __shared__ __align__(16) char dsm[];
    const uint32_t sbase = smem_u32(dsm);

    const int tid  = threadIdx.x;
    const int wid  = tid >> 5;
    const int lane = tid & 31;
    const int g = lane >> 2, t = lane & 3;
    const int bm = blockIdx.y * GBM;
    const int bn = blockIdx.x * GBN;
    const int wm = (wid >> 1) * 32;
    const int wn = (wid & 1) * 64;

    const int l15 = lane & 15;
    const int lhi = lane >> 4;
    const uint32_t aoff = (uint32_t)(((wm + l15) * PH + lhi * 8) * 2);
    const int l7 = lane & 7;
    const int q2 = lane >> 3;
    const uint32_t boff = (uint32_t)(((wn + (q2 >> 1) * 8 + l7) * PH + (q2 & 1) * 8) * 2);

    float acc[2][8][4];
    #pragma unroll
    for (int mt = 0; mt < 2; ++mt)
        #pragma unroll
        for (int nt = 0; nt < 8; ++nt)
            #pragma unroll
            for (int j = 0; j < 4; ++j) acc[mt][nt][j] = 0.f;

    const int KT = K >> 6;

    load_stage(sbase, A, Wt, bm, bn, M, K, 0, tid);
    load_stage(sbase + GSTG_BYTES, A, Wt, bm, bn, M, K, 64, tid);

    for (int kt = 0; kt < KT; ++kt) {
        asm volatile("cp.async.wait_group 1;" ::: "memory");
        __syncthreads();

        if (kt + 2 < KT)
            load_stage(sbase + (uint32_t)(((kt + 2) % NSTAGE) * GSTG_BYTES),
                       A, Wt, bm, bn, M, K, (kt + 2) * 64, tid);
        else
            asm volatile("cp.async.commit_group;" ::: "memory");

        const uint32_t sA_u = sbase + (uint32_t)((kt % NSTAGE) * GSTG_BYTES);
        const uint32_t sB_u = sA_u + 128 * (PH * 2);

        #pragma unroll
        for (int k16 = 0; k16 < 4; ++k16) {
            uint32_t bf[8][2];
            #pragma unroll
            for (int ntp = 0; ntp < 4; ++ntp) {
                uint32_t r0, r1, r2, r3;
                ldsm_x4(r0, r1, r2, r3,
                        sB_u + boff + (uint32_t)(ntp * 16 * PH * 2 + k16 * 32));
                bf[2 * ntp][0] = r0; bf[2 * ntp][1] = r1;
                bf[2 * ntp + 1][0] = r2; bf[2 * ntp + 1][1] = r3;
            }
            #pragma unroll
            for (int mt = 0; mt < 2; ++mt) {
                uint32_t a0, a1, a2, a3;
                ldsm_x4(a0, a1, a2, a3,
                        sA_u + aoff + (uint32_t)(mt * 16 * PH * 2 + k16 * 32));
                #pragma unroll
                for (int nt = 0; nt < 8; ++nt)
                    mma_f16(acc[mt][nt], a0, a1, a2, a3, bf[nt][0], bf[nt][1]);
            }
        }
    }

    // ---- epilogue ----
    #pragma unroll
    for (int nt = 0; nt < 8; ++nt) {
        const int c = bn + wn + nt * 8 + 2 * t;
        const float2 bia = *(const float2*)&bias[c];
        #pragma unroll
        for (int mt = 0; mt < 2; ++mt) {
            const int r0 = bm + wm + mt * 16 + g;
            const int r1 = r0 + 8;
            float v0 = acc[mt][nt][0] + bia.x;
            float v1 = acc[mt][nt][1] + bia.y;
            float v2 = acc[mt][nt][2] + bia.x;
            float v3 = acc[mt][nt][3] + bia.y;

            if (EPI == 0) {
                __half* out = (__half*)outp;
                if (r0 < M) *(__half2*)&out[(size_t)r0 * N + c] = __floats2half2_rn(v0, v1);
                if (r1 < M) *(__half2*)&out[(size_t)r1 * N + c] = __floats2half2_rn(v2, v3);
            } else if (EPI == 1) {
                const float* res = (const float*)resv;
                __half* out = (__half*)outp;
                if (r0 < M) {
                    float2 rv = *(const float2*)&res[(size_t)r0 * N + c];
                    *(__half2*)&out[(size_t)r0 * N + c] = __floats2half2_rn(v0 + rv.x, v1 + rv.y);
                }
                if (r1 < M) {
                    float2 rv = *(const float2*)&res[(size_t)r1 * N + c];
                    *(__half2*)&out[(size_t)r1 * N + c] = __floats2half2_rn(v2 + rv.x, v3 + rv.y);
                }
            } else if (EPI == 2) {
                __half* out = (__half*)outp;
                v0 = 0.5f * v0 * (1.0f + erff(v0 * 0.70710678118654752f));
                v1 = 0.5f * v1 * (1.0f + erff(v1 * 0.70710678118654752f));
                v2 = 0.5f * v2 * (1.0f + erff(v2 * 0.70710678118654752f));
                v3 = 0.5f * v3 * (1.0f + erff(v3 * 0.70710678118654752f));
                if (r0 < M) *(__half2*)&out[(size_t)r0 * N + c] = __floats2half2_rn(v0, v1);
                if (r1 < M) *(__half2*)&out[(size_t)r1 * N + c] = __floats2half2_rn(v2, v3);
            } else {
                const __half* res = (const __half*)resv;
                float* out = (float*)outp;
                if (r0 < M) {
                    __half2 rv = *(const __half2*)&res[(size_t)r0 * N + c];
                    *(float2*)&out[(size_t)r0 * N + c] =
                        make_float2(v0 + __half2float(rv.x), v1 + __half2float(rv.y));
                }
                if (r1 < M) {
                    __half2 rv = *(const __half2*)&res[(size_t)r1 * N + c];
                    *(float2*)&out[(size_t)r1 * N + c] =
                        make_float2(v2 + __half2float(rv.x), v3 + __half2float(rv.y));
                }
            }
        }
    }
}

// ---------------- fp16 flash attention: natural V + ldmatrix.trans -----------------
// smem halfs: Qs[128][72] | Ks[2][64][72] | Vs[2][64][72]
#define OQ 0
#define OK (128 * PH)
#define OV (OK + 2 * 64 * PH)
#define ATT_SMEM ((OV + 2 * 64 * PH) * 2)
#define NKT 10

__global__ void __launch_bounds__(256) attn_tc(
    const __half* __restrict__ qkv, __half* __restrict__ outa)
{
    extern __shared__ __align__(16) char sm[];
    const uint32_t sbase = smem_u32(sm);

    const int qt = blockIdx.x;
    const int h  = blockIdx.y;
    const int b  = blockIdx.z;
    const int tid  = threadIdx.x;
    const int wid  = tid >> 5;
    const int lane = tid & 31;
    const int g = lane >> 2, t = lane & 3;
    const int wr = wid * 16;
    const size_t browbase = (size_t)b * SEQ;
    const __half* qbase = qkv + browbase * C3 + h * DHEAD;

    const int l15 = lane & 15;
    const int lhi = lane >> 4;
    const uint32_t aoff = (uint32_t)(((wr + l15) * PH + lhi * 8) * 2);
    const int l7 = lane & 7;
    const int q2 = lane >> 3;
    const uint32_t boff = (uint32_t)((((q2 >> 1) * 8 + l7) * PH + (q2 & 1) * 8) * 2);
    // trans-ldmatrix V addressing: lane -> V row (n), d-group by lane>>4
    const uint32_t voff = (uint32_t)((l15 * PH + lhi * 8) * 2);

    // ---- Q tile (128 x 64 halfs) ----
    #pragma unroll
    for (int i = 0; i < 4; ++i) {
        int f = i * 256 + tid;
        int r = f >> 3, q = f & 7;
        int n = qt * 128 + r;
        int sz = (n < SEQ) ? 16 : 0;
        if (n >= SEQ) n = SEQ - 1;
        cp_async16z(sbase + (uint32_t)((OQ + r * PH + q * 8) * 2),
                    qbase + (size_t)n * C3 + q * 8, sz);
    }
    // ---- K/V tile 0 into buf 0 (both natural, coalesced) ----
    #pragma unroll
    for (int i = 0; i < 2; ++i) {
        int f = i * 256 + tid;
        int r = f >> 3, q = f & 7;
        const __half* kb = qbase + (size_t)r * C3 + q * 8;
        cp_async16(sbase + (uint32_t)((OK + r * PH + q * 8) * 2), kb + CDIM);
        cp_async16(sbase + (uint32_t)((OV + r * PH + q * 8) * 2), kb + 2 * CDIM);
    }
    asm volatile("cp.async.commit_group;" ::: "memory");

    float oacc[8][4];
    #pragma unroll
    for (int nt = 0; nt < 8; ++nt)
        #pragma unroll
        for (int j = 0; j < 4; ++j) oacc[nt][j] = 0.f;
    float l0 = 0.f, l1 = 0.f;

    for (int kt = 0; kt < NKT; ++kt) {
        const int buf = kt & 1;
        if (kt > 0) __syncthreads();
        if (kt + 1 < NKT) {
            const int nbuf = (kt + 1) & 1;
            #pragma unroll
            for (int i = 0; i < 2; ++i) {
                int f = i * 256 + tid;
                int r = f >> 3, q = f & 7;
                int kk = (kt + 1) * 64 + r;
                int sz = (kk < SEQ) ? 16 : 0;
                if (kk >= SEQ) kk = SEQ - 1;
                const __half* kb = qbase + (size_t)kk * C3 + q * 8;
                cp_async16z(sbase + (uint32_t)((OK + (nbuf * 64 + r) * PH + q * 8) * 2),
                            kb + CDIM, sz);
                cp_async16z(sbase + (uint32_t)((OV + (nbuf * 64 + r) * PH + q * 8) * 2),
                            kb + 2 * CDIM, sz);
            }
        }
        asm volatile("cp.async.commit_group;" ::: "memory");
        asm volatile("cp.async.wait_group 1;" ::: "memory");
        __syncthreads();

        const uint32_t Qu = sbase + OQ * 2;
        const uint32_t Ku = sbase + (OK + buf * 64 * PH) * 2;
        const uint32_t Vu = sbase + (OV + buf * 64 * PH) * 2;

        // ---- S = Q @ K^T ----
        float sacc[8][4];
        #pragma unroll
        for (int nt = 0; nt < 8; ++nt)
            #pragma unroll
            for (int j = 0; j < 4; ++j) sacc[nt][j] = 0.f;

        #pragma unroll
        for (int k16 = 0; k16 < 4; ++k16) {
            uint32_t a0, a1, a2, a3;
            ldsm_x4(a0, a1, a2, a3, Qu + aoff + (uint32_t)(k16 * 32));
            #pragma unroll
            for (int ntp = 0; ntp < 4; ++ntp) {
                uint32_t b0, b1, b2, b3;
                ldsm_x4(b0, b1, b2, b3,
                        Ku + boff + (uint32_t)(ntp * 16 * PH * 2 + k16 * 32));
                mma_f16(sacc[2 * ntp],     a0, a1, a2, a3, b0, b1);
                mma_f16(sacc[2 * ntp + 1], a0, a1, a2, a3, b2, b3);
            }
        }

        // ---- no-max softmax: P = exp(S/8), mask -> 0; pack into A-fragments ----
        const int kb0 = kt * 64;
        uint32_t pfrag[4][4];
        #pragma unroll
        for (int nt = 0; nt < 8; ++nt) {
            const int c0 = kb0 + nt * 8 + 2 * t;
            float p0 = (c0     < SEQ) ? __expf(sacc[nt][0] * 0.125f) : 0.f;
            float p1 = (c0 + 1 < SEQ) ? __expf(sacc[nt][1] * 0.125f) : 0.f;
            float p2 = (c0     < SEQ) ? __expf(sacc[nt][2] * 0.125f) : 0.f;
            float p3 = (c0 + 1 < SEQ) ? __expf(sacc[nt][3] * 0.125f) : 0.f;
            l0 += p0 + p1; l1 += p2 + p3;
            __half2 h01 = __floats2half2_rn(p0, p1);
            __half2 h23 = __floats2half2_rn(p2, p3);
            const int k16i = nt >> 1, hi = nt & 1;
            pfrag[k16i][2 * hi]     = *(uint32_t*)&h01;
            pfrag[k16i][2 * hi + 1] = *(uint32_t*)&h23;
        }

        // ---- O += P @ V (V natural; B-fragments via ldmatrix.trans) ----
        #pragma unroll
        for (int k16 = 0; k16 < 4; ++k16) {
            #pragma unroll
            for (int ntp = 0; ntp < 4; ++ntp) {
                uint32_t b0, b1, b2, b3;
                ldsm_x4_trans(b0, b1, b2, b3,
                    Vu + voff + (uint32_t)((k16 * 16 * PH + ntp * 16) * 2));
                mma_f16(oacc[2 * ntp],     pfrag[k16][0], pfrag[k16][1],
                        pfrag[k16][2], pfrag[k16][3], b0, b1);
                mma_f16(oacc[2 * ntp + 1], pfrag[k16][0], pfrag[k16][1],
                        pfrag[k16][2], pfrag[k16][3], b2, b3);
            }
        }
    }

    l0 += __shfl_xor_sync(0xffffffffu, l0, 1);
    l0 += __shfl_xor_sync(0xffffffffu, l0, 2);
    l1 += __shfl_xor_sync(0xffffffffu, l1, 1);
    l1 += __shfl_xor_sync(0xffffffffu, l1, 2);

    const float inv0 = 1.0f / l0, inv1 = 1.0f / l1;
    const int r0 = qt * 128 + wr + g;
    const int r1 = r0 + 8;
    #pragma unroll
    for (int nt = 0; nt < 8; ++nt) {
        const int col = h * DHEAD + nt * 8 + 2 * t;
        if (r0 < SEQ)
            *(__half2*)&outa[(browbase + r0) * CDIM + col] =
                __floats2half2_rn(oacc[nt][0] * inv0, oacc[nt][1] * inv0);
        if (r1 < SEQ)
            *(__half2*)&outa[(browbase + r1) * CDIM + col] =
                __floats2half2_rn(oacc[nt][2] * inv1, oacc[nt][3] * inv1);
    }
}

// ---------------- launcher ----------------
extern "C" void kernel_launch(void* const* d_in, const int* in_sizes, int n_in,
                              void* d_out, int out_size)
{
    const float* x      = (const float*)d_in[0];
    const float* ln1_g  = (const float*)d_in[1];
    const float* ln1_b  = (const float*)d_in[2];
    const float* ln2_g  = (const float*)d_in[3];
    const float* ln2_b  = (const float*)d_in[4];
    const float* qkv_w  = (const float*)d_in[5];
    const float* qkv_b  = (const float*)d_in[6];
    const float* proj_w = (const float*)d_in[7];
    const float* proj_b = (const float*)d_in[8];
    const float* fc1_w  = (const float*)d_in[9];
    const float* fc1_b  = (const float*)d_in[10];
    const float* fc2_w  = (const float*)d_in[11];
    const float* fc2_b  = (const float*)d_in[12];
    float* out = (float*)d_out;

    __half *h, *qkv, *attn, *x1h, *ff, *wtq, *wtp, *wt1, *wt2;
    cudaGetSymbolAddress((void**)&h,    g_h);
    cudaGetSymbolAddress((void**)&qkv,  g_qkv);
    cudaGetSymbolAddress((void**)&attn, g_attn);
    cudaGetSymbolAddress((void**)&x1h,  g_x1h);
    cudaGetSymbolAddress((void**)&ff,   g_ff);
    cudaGetSymbolAddress((void**)&wtq,  g_wt_qkv);
    cudaGetSymbolAddress((void**)&wtp,  g_wt_proj);
    cudaGetSymbolAddress((void**)&wt1,  g_wt_fc1);
    cudaGetSymbolAddress((void**)&wt2,  g_wt_fc2);

    cudaFuncSetAttribute(gemm_mma<0>, cudaFuncAttributeMaxDynamicSharedMemorySize, GSMEM_DYN);
    cudaFuncSetAttribute(gemm_mma<1>, cudaFuncAttributeMaxDynamicSharedMemorySize, GSMEM_DYN);
    cudaFuncSetAttribute(gemm_mma<2>, cudaFuncAttributeMaxDynamicSharedMemorySize, GSMEM_DYN);
    cudaFuncSetAttribute(gemm_mma<3>, cudaFuncAttributeMaxDynamicSharedMemorySize, GSMEM_DYN);
    cudaFuncSetAttribute(attn_tc,     cudaFuncAttributeMaxDynamicSharedMemorySize, ATT_SMEM);

    const int M  = MROWS;
    const int gy = (M + GBM - 1) / GBM;     // 145

    // merged LN1 + weight transposes (one launch)
    prep_kernel<<<MROWS + 6912, dim3(32, 8)>>>(x, ln1_g, ln1_b, qkv_w, proj_w, fc1_w, fc2_w);

    // 2. QKV = h @ qkv_w + qkv_b (Q,K,V all natural layout)
    gemm_mma<0><<<dim3(C3 / GBN, gy), GTHREADS, GSMEM_DYN>>>(h, wtq, qkv_b, nullptr, qkv, M, CDIM, C3);
    // 3. attention
    attn_tc<<<dim3((SEQ + 127) / 128, NHEAD, BATCH), 256, ATT_SMEM>>>(qkv, attn);
    // 4. x1h = half(x + attn @ proj_w + proj_b)
    gemm_mma<1><<<dim3(CDIM / GBN, gy), GTHREADS, GSMEM_DYN>>>(attn, wtp, proj_b, x, x1h, M, CDIM, CDIM);
    // 5. LN2 (half input)
    ln_kernel_h<<<M, 256>>>(x1h, ln2_g, ln2_b, h);
    // 6. ff = gelu(h @ fc1_w + fc1_b)
    gemm_mma<2><<<dim3(DFF / GBN, gy), GTHREADS, GSMEM_DYN>>>(h, wt1, fc1_b, nullptr, ff, M, CDIM, DFF);
    // 7. out = x1h + ff @ fc2_w + fc2_b   (f32 final)
    gemm_mma<3><<<dim3(CDIM / GBN, gy), GTHREADS, GSMEM_DYN>>>(ff, wt2, fc2_b, x1h, out, M, DFF, CDIM);
}

// round 17
// speedup vs baseline: 6.2518x; 1.0100x over previous
#include <cuda_runtime.h>
#include <cuda_fp16.h>
#include <cstdint>
#include <math.h>

// ---------------- problem constants ----------------
#define BATCH 32
#define SEQ   577
#define CDIM  768
#define NHEAD 12
#define DHEAD 64
#define DFF   3072
#define MROWS (BATCH*SEQ)          // 18464
#define C3    2304

// ---------------- scratch (device globals; no allocation) ----------------
__device__ __align__(256) __half g_h   [(size_t)MROWS * CDIM];
__device__ __align__(256) __half g_xh  [(size_t)MROWS * CDIM];
__device__ __align__(256) __half g_qkv [(size_t)MROWS * C3];
__device__ __align__(256) __half g_attn[(size_t)MROWS * CDIM];
__device__ __align__(256) __half g_x1h [(size_t)MROWS * CDIM];
__device__ __align__(256) __half g_ff  [(size_t)MROWS * DFF];
__device__ __align__(256) __half g_wt_qkv [(size_t)C3   * CDIM];
__device__ __align__(256) __half g_wt_proj[(size_t)CDIM * CDIM];
__device__ __align__(256) __half g_wt_fc1 [(size_t)DFF  * CDIM];
__device__ __align__(256) __half g_wt_fc2 [(size_t)CDIM * DFF];

// ---------------- helpers ----------------
static __device__ __forceinline__ uint32_t smem_u32(const void* p) {
    uint32_t a;
    asm("{ .reg .u64 t; cvta.to.shared.u64 t, %1; cvt.u32.u64 %0, t; }" : "=r"(a) : "l"(p));
    return a;
}
static __device__ __forceinline__ void cp_async16(uint32_t dst, const void* src) {
    asm volatile("cp.async.cg.shared.global [%0], [%1], 16;" :: "r"(dst), "l"(src));
}
static __device__ __forceinline__ void cp_async16z(uint32_t dst, const void* src, int sz) {
    asm volatile("cp.async.cg.shared.global [%0], [%1], 16, %2;" :: "r"(dst), "l"(src), "r"(sz));
}
static __device__ __forceinline__ void mma_f16(
    float* d, uint32_t a0, uint32_t a1, uint32_t a2, uint32_t a3,
    uint32_t b0, uint32_t b1)
{
    asm volatile(
        "mma.sync.aligned.m16n8k16.row.col.f32.f16.f16.f32 "
        "{%0,%1,%2,%3}, {%4,%5,%6,%7}, {%8,%9}, {%0,%1,%2,%3};"
        : "+f"(d[0]), "+f"(d[1]), "+f"(d[2]), "+f"(d[3])
        : "r"(a0), "r"(a1), "r"(a2), "r"(a3), "r"(b0), "r"(b1));
}
static __device__ __forceinline__ void ldsm_x4(
    uint32_t& r0, uint32_t& r1, uint32_t& r2, uint32_t& r3, uint32_t addr)
{
    asm volatile("ldmatrix.sync.aligned.m8n8.x4.shared.b16 {%0,%1,%2,%3}, [%4];"
                 : "=r"(r0), "=r"(r1), "=r"(r2), "=r"(r3) : "r"(addr));
}
static __device__ __forceinline__ void ldsm_x4_trans(
    uint32_t& r0, uint32_t& r1, uint32_t& r2, uint32_t& r3, uint32_t addr)
{
    asm volatile("ldmatrix.sync.aligned.m8n8.x4.trans.shared.b16 {%0,%1,%2,%3}, [%4];"
                 : "=r"(r0), "=r"(r1), "=r"(r2), "=r"(r3) : "r"(addr));
}
static __device__ __forceinline__ float ldf(const float* p)  { return *p; }
static __device__ __forceinline__ float ldf(const __half* p) { return __half2float(*p); }

// ---------------- LayerNorm body (templated; optional half-copy of input) ----------
template <typename T, bool SAVEX>
static __device__ __forceinline__ void ln_body(
    const T* __restrict__ x, const float* __restrict__ g,
    const float* __restrict__ b, __half* __restrict__ out,
    __half* __restrict__ xh, int row, int tid, float* red)
{
    const T* xr = x + (size_t)row * CDIM;
    float v0 = ldf(xr + tid), v1 = ldf(xr + tid + 256), v2 = ldf(xr + tid + 512);

    if (SAVEX) {
        __half* xo = xh + (size_t)row * CDIM;
        xo[tid]       = __float2half_rn(v0);
        xo[tid + 256] = __float2half_rn(v1);
        xo[tid + 512] = __float2half_rn(v2);
    }

    float s = v0 + v1 + v2;
    #pragma unroll
    for (int o = 16; o > 0; o >>= 1) s += __shfl_xor_sync(0xffffffffu, s, o);
    if ((tid & 31) == 0) red[tid >> 5] = s;
    __syncthreads();
    if (tid == 0) {
        float t = 0.f;
        #pragma unroll
        for (int w = 0; w < 8; ++w) t += red[w];
        red[0] = t;
    }
    __syncthreads();
    const float mean = red[0] * (1.0f / CDIM);
    __syncthreads();

    float d0 = v0 - mean, d1 = v1 - mean, d2 = v2 - mean;
    float sq = d0 * d0 + d1 * d1 + d2 * d2;
    #pragma unroll
    for (int o = 16; o > 0; o >>= 1) sq += __shfl_xor_sync(0xffffffffu, sq, o);
    if ((tid & 31) == 0) red[tid >> 5] = sq;
    __syncthreads();
    if (tid == 0) {
        float t = 0.f;
        #pragma unroll
        for (int w = 0; w < 8; ++w) t += red[w];
        red[0] = t;
    }
    __syncthreads();
    const float var = red[0] * (1.0f / CDIM);
    const float rstd = rsqrtf(var + 1e-5f);

    __half* outr = out + (size_t)row * CDIM;
    outr[tid]       = __float2half_rn(d0 * rstd * g[tid]       + b[tid]);
    outr[tid + 256] = __float2half_rn(d1 * rstd * g[tid + 256] + b[tid + 256]);
    outr[tid + 512] = __float2half_rn(d2 * rstd * g[tid + 512] + b[tid + 512]);
}

__global__ void __launch_bounds__(256) ln_kernel_h(
    const __half* __restrict__ x, const float* __restrict__ g,
    const float* __restrict__ b, __half* __restrict__ out)
{
    __shared__ float red[8];
    ln_body<__half, false>(x, g, b, out, nullptr, blockIdx.x, threadIdx.x, red);
}

// ---------------- merged prep: LN1 (+xh copy) + 4 weight transposes ----------------
__global__ void __launch_bounds__(256) prep_kernel(
    const float* __restrict__ x, const float* __restrict__ ln1_g,
    const float* __restrict__ ln1_b,
    const float* __restrict__ qkv_w, const float* __restrict__ proj_w,
    const float* __restrict__ fc1_w, const float* __restrict__ fc2_w)
{
    __shared__ float tb[32][33];
    __shared__ float red[8];
    int bid = blockIdx.x;
    const int tid = threadIdx.y * 32 + threadIdx.x;

    if (bid < MROWS) {
        ln_body<float, true>(x, ln1_g, ln1_b, g_h, g_xh, bid, tid, red);
        return;
    }
    bid -= MROWS;

    const float* W; __half* Wt; int K, N;
    if (bid < 1728)      { W = qkv_w;  Wt = g_wt_qkv;  K = CDIM; N = C3;  }
    else if (bid < 2304) { W = proj_w; Wt = g_wt_proj; K = CDIM; N = CDIM; bid -= 1728; }
    else if (bid < 4608) { W = fc1_w;  Wt = g_wt_fc1;  K = CDIM; N = DFF;  bid -= 2304; }
    else                 { W = fc2_w;  Wt = g_wt_fc2;  K = DFF;  N = CDIM; bid -= 4608; }

    const int nbx = K >> 5;
    const int k0 = (bid % nbx) * 32, n0 = (bid / nbx) * 32;
    #pragma unroll
    for (int i = threadIdx.y; i < 32; i += 8)
        tb[i][threadIdx.x] = W[(size_t)(k0 + i) * N + n0 + threadIdx.x];
    __syncthreads();
    #pragma unroll
    for (int i = threadIdx.y; i < 32; i += 8)
        Wt[(size_t)(n0 + i) * K + k0 + threadIdx.x] = __float2half_rn(tb[threadIdx.x][i]);
}

// ---------------- fp16 HMMA GEMM: 128x128 tile, 256 thr, 2 CTAs/SM -----------------
// EPI 0: bias -> half | 1: +half res -> half | 2: GELU -> half | 3: +half res -> f32
#define GBM 128
#define GBN 128
#define PH 72
#define GSTG_BYTES ((128 + 128) * PH * 2)  // 36864
#define NSTAGE 3
#define GSMEM_DYN (NSTAGE * GSTG_BYTES)    // 110592 -> 2 CTAs/SM
#define GTHREADS 256

__device__ __forceinline__ void load_stage(
    uint32_t sb, const __half* __restrict__ A, const __half* __restrict__ Wt,
    int bm, int bn, int M, int K, int kc, int tid)
{
    #pragma unroll
    for (int i = 0; i < 4; ++i) {
        int f = i * GTHREADS + tid;
        int r = f >> 3, q = f & 7;
        int rr = bm + r;
        int sz = (rr < M) ? 16 : 0;
        if (rr >= M) rr = M - 1;
        cp_async16z(sb + (uint32_t)(r * (PH * 2) + q * 16),
                    A + (size_t)rr * K + kc + q * 8, sz);
    }
    const uint32_t bb = sb + 128 * (PH * 2);
    #pragma unroll
    for (int i = 0; i < 4; ++i) {
        int f = i * GTHREADS + tid;
        int r = f >> 3, q = f & 7;
        cp_async16(bb + (uint32_t)(r * (PH * 2) + q * 16),
                   Wt + (size_t)(bn + r) * K + kc + q * 8);
    }
    asm volatile("cp.async.commit_group;" ::: "memory");
}

template <int EPI>
__global__ void __launch_bounds__(GTHREADS, 2) gemm_mma(
    const __half* __restrict__ A, const __half* __restrict__ Wt,
    const float* __restrict__ bias, const __half* __restrict__ res,
    void* __restrict__ outp, int M, int K, int N)
{
    extern __shared__ __align__(16) char dsm[];
    const uint32_t sbase = smem_u32(dsm);

    const int tid  = threadIdx.x;
    const int wid  = tid >> 5;
    const int lane = tid & 31;
    const int g = lane >> 2, t = lane & 3;
    const int bm = blockIdx.y * GBM;
    const int bn = blockIdx.x * GBN;
    const int wm = (wid >> 1) * 32;
    const int wn = (wid & 1) * 64;

    const int l15 = lane & 15;
    const int lhi = lane >> 4;
    const uint32_t aoff = (uint32_t)(((wm + l15) * PH + lhi * 8) * 2);
    const int l7 = lane & 7;
    const int q2 = lane >> 3;
    const uint32_t boff = (uint32_t)(((wn + (q2 >> 1) * 8 + l7) * PH + (q2 & 1) * 8) * 2);

    float acc[2][8][4];
    #pragma unroll
    for (int mt = 0; mt < 2; ++mt)
        #pragma unroll
        for (int nt = 0; nt < 8; ++nt)
            #pragma unroll
            for (int j = 0; j < 4; ++j) acc[mt][nt][j] = 0.f;

    const int KT = K >> 6;

    load_stage(sbase, A, Wt, bm, bn, M, K, 0, tid);
    load_stage(sbase + GSTG_BYTES, A, Wt, bm, bn, M, K, 64, tid);

    for (int kt = 0; kt < KT; ++kt) {
        asm volatile("cp.async.wait_group 1;" ::: "memory");
        __syncthreads();

        if (kt + 2 < KT)
            load_stage(sbase + (uint32_t)(((kt + 2) % NSTAGE) * GSTG_BYTES),
                       A, Wt, bm, bn, M, K, (kt + 2) * 64, tid);
        else
            asm volatile("cp.async.commit_group;" ::: "memory");

        const uint32_t sA_u = sbase + (uint32_t)((kt % NSTAGE) * GSTG_BYTES);
        const uint32_t sB_u = sA_u + 128 * (PH * 2);

        #pragma unroll
        for (int k16 = 0; k16 < 4; ++k16) {
            uint32_t bf[8][2];
            #pragma unroll
            for (int ntp = 0; ntp < 4; ++ntp) {
                uint32_t r0, r1, r2, r3;
                ldsm_x4(r0, r1, r2, r3,
                        sB_u + boff + (uint32_t)(ntp * 16 * PH * 2 + k16 * 32));
                bf[2 * ntp][0] = r0; bf[2 * ntp][1] = r1;
                bf[2 * ntp + 1][0] = r2; bf[2 * ntp + 1][1] = r3;
            }
            #pragma unroll
            for (int mt = 0; mt < 2; ++mt) {
                uint32_t a0, a1, a2, a3;
                ldsm_x4(a0, a1, a2, a3,
                        sA_u + aoff + (uint32_t)(mt * 16 * PH * 2 + k16 * 32));
                #pragma unroll
                for (int nt = 0; nt < 8; ++nt)
                    mma_f16(acc[mt][nt], a0, a1, a2, a3, bf[nt][0], bf[nt][1]);
            }
        }
    }

    // ---- epilogue ----
    #pragma unroll
    for (int nt = 0; nt < 8; ++nt) {
        const int c = bn + wn + nt * 8 + 2 * t;
        const float2 bia = *(const float2*)&bias[c];
        #pragma unroll
        for (int mt = 0; mt < 2; ++mt) {
            const int r0 = bm + wm + mt * 16 + g;
            const int r1 = r0 + 8;
            float v0 = acc[mt][nt][0] + bia.x;
            float v1 = acc[mt][nt][1] + bia.y;
            float v2 = acc[mt][nt][2] + bia.x;
            float v3 = acc[mt][nt][3] + bia.y;

            if (EPI == 0) {
                __half* out = (__half*)outp;
                if (r0 < M) *(__half2*)&out[(size_t)r0 * N + c] = __floats2half2_rn(v0, v1);
                if (r1 < M) *(__half2*)&out[(size_t)r1 * N + c] = __floats2half2_rn(v2, v3);
            } else if (EPI == 1) {
                __half* out = (__half*)outp;
                if (r0 < M) {
                    __half2 rv = *(const __half2*)&res[(size_t)r0 * N + c];
                    *(__half2*)&out[(size_t)r0 * N + c] =
                        __floats2half2_rn(v0 + __half2float(rv.x), v1 + __half2float(rv.y));
                }
                if (r1 < M) {
                    __half2 rv = *(const __half2*)&res[(size_t)r1 * N + c];
                    *(__half2*)&out[(size_t)r1 * N + c] =
                        __floats2half2_rn(v2 + __half2float(rv.x), v3 + __half2float(rv.y));
                }
            } else if (EPI == 2) {
                __half* out = (__half*)outp;
                v0 = 0.5f * v0 * (1.0f + erff(v0 * 0.70710678118654752f));
                v1 = 0.5f * v1 * (1.0f + erff(v1 * 0.70710678118654752f));
                v2 = 0.5f * v2 * (1.0f + erff(v2 * 0.70710678118654752f));
                v3 = 0.5f * v3 * (1.0f + erff(v3 * 0.70710678118654752f));
                if (r0 < M) *(__half2*)&out[(size_t)r0 * N + c] = __floats2half2_rn(v0, v1);
                if (r1 < M) *(__half2*)&out[(size_t)r1 * N + c] = __floats2half2_rn(v2, v3);
            } else {
                float* out = (float*)outp;
                if (r0 < M) {
                    __half2 rv = *(const __half2*)&res[(size_t)r0 * N + c];
                    *(float2*)&out[(size_t)r0 * N + c] =
                        make_float2(v0 + __half2float(rv.x), v1 + __half2float(rv.y));
                }
                if (r1 < M) {
                    __half2 rv = *(const __half2*)&res[(size_t)r1 * N + c];
                    *(float2*)&out[(size_t)r1 * N + c] =
                        make_float2(v2 + __half2float(rv.x), v3 + __half2float(rv.y));
                }
            }
        }
    }
}

// ---------------- fp16 flash attention: natural V + ldmatrix.trans, 2 CTAs/SM ------
#define OQ 0
#define OK (128 * PH)
#define OV (OK + 2 * 64 * PH)
#define ATT_SMEM ((OV + 2 * 64 * PH) * 2)
#define NKT 10

__global__ void __launch_bounds__(256, 2) attn_tc(
    const __half* __restrict__ qkv, __half* __restrict__ outa)
{
    extern __shared__ __align__(16) char sm[];
    const uint32_t sbase = smem_u32(sm);

    const int qt = blockIdx.x;
    const int h  = blockIdx.y;
    const int b  = blockIdx.z;
    const int tid  = threadIdx.x;
    const int wid  = tid >> 5;
    const int lane = tid & 31;
    const int g = lane >> 2, t = lane & 3;
    const int wr = wid * 16;
    const size_t browbase = (size_t)b * SEQ;
    const __half* qbase = qkv + browbase * C3 + h * DHEAD;

    const int l15 = lane & 15;
    const int lhi = lane >> 4;
    const uint32_t aoff = (uint32_t)(((wr + l15) * PH + lhi * 8) * 2);
    const int l7 = lane & 7;
    const int q2 = lane >> 3;
    const uint32_t boff = (uint32_t)((((q2 >> 1) * 8 + l7) * PH + (q2 & 1) * 8) * 2);
    const uint32_t voff = (uint32_t)((l15 * PH + lhi * 8) * 2);

    #pragma unroll
    for (int i = 0; i < 4; ++i) {
        int f = i * 256 + tid;
        int r = f >> 3, q = f & 7;
        int n = qt * 128 + r;
        int sz = (n < SEQ) ? 16 : 0;
        if (n >= SEQ) n = SEQ - 1;
        cp_async16z(sbase + (uint32_t)((OQ + r * PH + q * 8) * 2),
                    qbase + (size_t)n * C3 + q * 8, sz);
    }
    #pragma unroll
    for (int i = 0; i < 2; ++i) {
        int f = i * 256 + tid;
        int r = f >> 3, q = f & 7;
        const __half* kb = qbase + (size_t)r * C3 + q * 8;
        cp_async16(sbase + (uint32_t)((OK + r * PH + q * 8) * 2), kb + CDIM);
        cp_async16(sbase + (uint32_t)((OV + r * PH + q * 8) * 2), kb + 2 * CDIM);
    }
    asm volatile("cp.async.commit_group;" ::: "memory");

    float oacc[8][4];
    #pragma unroll
    for (int nt = 0; nt < 8; ++nt)
        #pragma unroll
        for (int j = 0; j < 4; ++j) oacc[nt][j] = 0.f;
    float l0 = 0.f, l1 = 0.f;

    for (int kt = 0; kt < NKT; ++kt) {
        const int buf = kt & 1;
        if (kt > 0) __syncthreads();
        if (kt + 1 < NKT) {
            const int nbuf = (kt + 1) & 1;
            #pragma unroll
            for (int i = 0; i < 2; ++i) {
                int f = i * 256 + tid;
                int r = f >> 3, q = f & 7;
                int kk = (kt + 1) * 64 + r;
                int sz = (kk < SEQ) ? 16 : 0;
                if (kk >= SEQ) kk = SEQ - 1;
                const __half* kb = qbase + (size_t)kk * C3 + q * 8;
                cp_async16z(sbase + (uint32_t)((OK + (nbuf * 64 + r) * PH + q * 8) * 2),
                            kb + CDIM, sz);
                cp_async16z(sbase + (uint32_t)((OV + (nbuf * 64 + r) * PH + q * 8) * 2),
                            kb + 2 * CDIM, sz);
            }
        }
        asm volatile("cp.async.commit_group;" ::: "memory");
        asm volatile("cp.async.wait_group 1;" ::: "memory");
        __syncthreads();

        const uint32_t Qu = sbase + OQ * 2;
        const uint32_t Ku = sbase + (OK + buf * 64 * PH) * 2;
        const uint32_t Vu = sbase + (OV + buf * 64 * PH) * 2;

        float sacc[8][4];
        #pragma unroll
        for (int nt = 0; nt < 8; ++nt)
            #pragma unroll
            for (int j = 0; j < 4; ++j) sacc[nt][j] = 0.f;

        #pragma unroll
        for (int k16 = 0; k16 < 4; ++k16) {
            uint32_t a0, a1, a2, a3;
            ldsm_x4(a0, a1, a2, a3, Qu + aoff + (uint32_t)(k16 * 32));
            #pragma unroll
            for (int ntp = 0; ntp < 4; ++ntp) {
                uint32_t b0, b1, b2, b3;
                ldsm_x4(b0, b1, b2, b3,
                        Ku + boff + (uint32_t)(ntp * 16 * PH * 2 + k16 * 32));
                mma_f16(sacc[2 * ntp],     a0, a1, a2, a3, b0, b1);
                mma_f16(sacc[2 * ntp + 1], a0, a1, a2, a3, b2, b3);
            }
        }

        const int kb0 = kt * 64;
        uint32_t pfrag[4][4];
        #pragma unroll
        for (int nt = 0; nt < 8; ++nt) {
            const int c0 = kb0 + nt * 8 + 2 * t;
            float p0 = (c0     < SEQ) ? __expf(sacc[nt][0] * 0.125f) : 0.f;
            float p1 = (c0 + 1 < SEQ) ? __expf(sacc[nt][1] * 0.125f) : 0.f;
            float p2 = (c0     < SEQ) ? __expf(sacc[nt][2] * 0.125f) : 0.f;
            float p3 = (c0 + 1 < SEQ) ? __expf(sacc[nt][3] * 0.125f) : 0.f;
            l0 += p0 + p1; l1 += p2 + p3;
            __half2 h01 = __floats2half2_rn(p0, p1);
            __half2 h23 = __floats2half2_rn(p2, p3);
            const int k16i = nt >> 1, hi = nt & 1;
            pfrag[k16i][2 * hi]     = *(uint32_t*)&h01;
            pfrag[k16i][2 * hi + 1] = *(uint32_t*)&h23;
        }

        #pragma unroll
        for (int k16 = 0; k16 < 4; ++k16) {
            #pragma unroll
            for (int ntp = 0; ntp < 4; ++ntp) {
                uint32_t b0, b1, b2, b3;
                ldsm_x4_trans(b0, b1, b2, b3,
                    Vu + voff + (uint32_t)((k16 * 16 * PH + ntp * 16) * 2));
                mma_f16(oacc[2 * ntp],     pfrag[k16][0], pfrag[k16][1],
                        pfrag[k16][2], pfrag[k16][3], b0, b1);
                mma_f16(oacc[2 * ntp + 1], pfrag[k16][0], pfrag[k16][1],
                        pfrag[k16][2], pfrag[k16][3], b2, b3);
            }
        }
    }

    l0 += __shfl_xor_sync(0xffffffffu, l0, 1);
    l0 += __shfl_xor_sync(0xffffffffu, l0, 2);
    l1 += __shfl_xor_sync(0xffffffffu, l1, 1);
    l1 += __shfl_xor_sync(0xffffffffu, l1, 2);

    const float inv0 = 1.0f / l0, inv1 = 1.0f / l1;
    const int r0 = qt * 128 + wr + g;
    const int r1 = r0 + 8;
    #pragma unroll
    for (int nt = 0; nt < 8; ++nt) {
        const int col = h * DHEAD + nt * 8 + 2 * t;
        if (r0 < SEQ)
            *(__half2*)&outa[(browbase + r0) * CDIM + col] =
                __floats2half2_rn(oacc[nt][0] * inv0, oacc[nt][1] * inv0);
        if (r1 < SEQ)
            *(__half2*)&outa[(browbase + r1) * CDIM + col] =
                __floats2half2_rn(oacc[nt][2] * inv1, oacc[nt][3] * inv1);
    }
}

// ---------------- launcher ----------------
extern "C" void kernel_launch(void* const* d_in, const int* in_sizes, int n_in,
                              void* d_out, int out_size)
{
    const float* x      = (const float*)d_in[0];
    const float* ln1_g  = (const float*)d_in[1];
    const float* ln1_b  = (const float*)d_in[2];
    const float* ln2_g  = (const float*)d_in[3];
    const float* ln2_b  = (const float*)d_in[4];
    const float* qkv_w  = (const float*)d_in[5];
    const float* qkv_b  = (const float*)d_in[6];
    const float* proj_w = (const float*)d_in[7];
    const float* proj_b = (const float*)d_in[8];
    const float* fc1_w  = (const float*)d_in[9];
    const float* fc1_b  = (const float*)d_in[10];
    const float* fc2_w  = (const float*)d_in[11];
    const float* fc2_b  = (const float*)d_in[12];
    float* out = (float*)d_out;

    __half *h, *xh, *qkv, *attn, *x1h, *ff, *wtq, *wtp, *wt1, *wt2;
    cudaGetSymbolAddress((void**)&h,    g_h);
    cudaGetSymbolAddress((void**)&xh,   g_xh);
    cudaGetSymbolAddress((void**)&qkv,  g_qkv);
    cudaGetSymbolAddress((void**)&attn, g_attn);
    cudaGetSymbolAddress((void**)&x1h,  g_x1h);
    cudaGetSymbolAddress((void**)&ff,   g_ff);
    cudaGetSymbolAddress((void**)&wtq,  g_wt_qkv);
    cudaGetSymbolAddress((void**)&wtp,  g_wt_proj);
    cudaGetSymbolAddress((void**)&wt1,  g_wt_fc1);
    cudaGetSymbolAddress((void**)&wt2,  g_wt_fc2);

    cudaFuncSetAttribute(gemm_mma<0>, cudaFuncAttributeMaxDynamicSharedMemorySize, GSMEM_DYN);
    cudaFuncSetAttribute(gemm_mma<1>, cudaFuncAttributeMaxDynamicSharedMemorySize, GSMEM_DYN);
    cudaFuncSetAttribute(gemm_mma<2>, cudaFuncAttributeMaxDynamicSharedMemorySize, GSMEM_DYN);
    cudaFuncSetAttribute(gemm_mma<3>, cudaFuncAttributeMaxDynamicSharedMemorySize, GSMEM_DYN);
    cudaFuncSetAttribute(attn_tc,     cudaFuncAttributeMaxDynamicSharedMemorySize, ATT_SMEM);

    const int M  = MROWS;
    const int gy = (M + GBM - 1) / GBM;     // 145

    prep_kernel<<<MROWS + 6912, dim3(32, 8)>>>(x, ln1_g, ln1_b, qkv_w, proj_w, fc1_w, fc2_w);

    // 2. QKV = h @ qkv_w + qkv_b (Q,K,V natural layout)
    gemm_mma<0><<<dim3(C3 / GBN, gy), GTHREADS, GSMEM_DYN>>>(h, wtq, qkv_b, nullptr, qkv, M, CDIM, C3);
    // 3. attention (2 CTAs/SM)
    attn_tc<<<dim3((SEQ + 127) / 128, NHEAD, BATCH), 256, ATT_SMEM>>>(qkv, attn);
    // 4. x1h = half(xh + attn @ proj_w + proj_b)
    gemm_mma<1><<<dim3(CDIM / GBN, gy), GTHREADS, GSMEM_DYN>>>(attn, wtp, proj_b, xh, x1h, M, CDIM, CDIM);
    // 5. LN2 (half input)
    ln_kernel_h<<<M, 256>>>(x1h, ln2_g, ln2_b, h);
    // 6. ff = gelu(h @ fc1_w + fc1_b)
    gemm_mma<2><<<dim3(DFF / GBN, gy), GTHREADS, GSMEM_DYN>>>(h, wt1, fc1_b, nullptr, ff, M, CDIM, DFF);
    // 7. out = x1h + ff @ fc2_w + fc2_b   (f32 final)
    gemm_mma<3><<<dim3(CDIM / GBN, gy), GTHREADS, GSMEM_DYN>>>(ff, wt2, fc2_b, x1h, out, M, DFF, CDIM);
}